// round 2
// baseline (speedup 1.0000x reference)
#include <cuda_runtime.h>
#include <math.h>

#define B_   2
#define C_   128
#define N_   4096
#define K_   16
#define DIM_ 256
#define PH_  64
#define AH_  1024

// ---------------- scratch (static device globals; no cudaMalloc allowed) ----
__device__ float g_x    [(size_t)B_ * 2 * C_ * N_];        // concat(key,query)
__device__ float g_t    [(size_t)B_ * C_ * N_];            // relu(w1@x)
__device__ float g_value[(size_t)B_ * C_ * N_];            // MLP_Res out / identity
__device__ float g_kf   [(size_t)B_ * DIM_ * N_];
__device__ float g_qf   [(size_t)B_ * DIM_ * N_];
__device__ float g_vf   [(size_t)B_ * DIM_ * N_];
__device__ int   g_idx  [(size_t)B_ * N_ * K_];
__device__ float g_t1   [(size_t)B_ * PH_ * N_ * K_];      // pos conv1 out
__device__ float g_pe   [(size_t)B_ * DIM_ * N_ * K_];     // pos_emb
__device__ float g_s    [(size_t)B_ * DIM_ * N_ * K_];     // qk_rel+pos_emb, then attn out
__device__ float g_h    [(size_t)B_ * AH_ * N_ * K_];      // attn hidden (537 MB)
__device__ float g_scale[AH_];
__device__ float g_shift[AH_];
__device__ float g_agg  [(size_t)B_ * DIM_ * N_];

// ---------------- concat(key,query) -> g_x ---------------------------------
__global__ void concat_kernel(const float* __restrict__ key,
                              const float* __restrict__ query,
                              float* __restrict__ x) {
    size_t i = (size_t)blockIdx.x * blockDim.x + threadIdx.x;  // B*2C*N = 4M
    if (i >= (size_t)B_ * 2 * C_ * N_) return;
    int n = (int)(i % N_);
    int c = (int)((i / N_) % (2 * C_));
    int b = (int)(i / ((size_t)N_ * 2 * C_));
    float v;
    if (c < C_) v = key  [((size_t)b * C_ + c) * N_ + n];
    else        v = query[((size_t)b * C_ + (c - C_)) * N_ + n];
    x[i] = v;
}

// ---------------- KNN: top-16 smallest d2, stable tie-break ----------------
__global__ void knn_kernel(const float* __restrict__ pos, int* __restrict__ idx) {
    const int b = blockIdx.y;
    const int n = blockIdx.x * blockDim.x + threadIdx.x;
    const float* p = pos + (size_t)b * 3 * N_;
    const float qx = p[n], qy = p[N_ + n], qz = p[2 * N_ + n];
    const float qs = qx * qx + qy * qy + qz * qz;

    float bd[K_];
    int   bi[K_];
#pragma unroll
    for (int j = 0; j < K_; j++) { bd[j] = 3.4e38f; bi[j] = 0; }

    __shared__ float sx[512], sy[512], sz[512], ss[512];
    for (int t0 = 0; t0 < N_; t0 += 512) {
        __syncthreads();
        for (int i = threadIdx.x; i < 512; i += blockDim.x) {
            float x = p[t0 + i], y = p[N_ + t0 + i], z = p[2 * N_ + t0 + i];
            sx[i] = x; sy[i] = y; sz[i] = z; ss[i] = x * x + y * y + z * z;
        }
        __syncthreads();
        for (int i = 0; i < 512; i++) {
            float d = qs + ss[i] - 2.0f * (qx * sx[i] + qy * sy[i] + qz * sz[i]);
            if (d < bd[K_ - 1]) {
                int j = K_ - 1;
                while (j > 0 && d < bd[j - 1]) {
                    bd[j] = bd[j - 1]; bi[j] = bi[j - 1]; j--;
                }
                bd[j] = d; bi[j] = t0 + i;
            }
        }
    }
    int* op = idx + ((size_t)b * N_ + n) * K_;
#pragma unroll
    for (int j = 0; j < K_; j++) op[j] = bi[j];
}

// ---------------- generic fp32 SGEMM --------------------------------------
// out[b][o][m] = sum_i W[o][i] * X[b][i][m] + bias[o]  (+flags)
// FLAGS: 1=relu, 2=accumulate into out, 4=add residual res (same layout as out)
// Requires: O % 128 == 0, M % 128 == 0, I % 8 == 0 (all shapes here satisfy).
template <int FLAGS>
__global__ void sgemm_kernel(const float* __restrict__ W,
                             const float* __restrict__ Xg,
                             const float* __restrict__ bias,
                             float* __restrict__ outg,
                             const float* __restrict__ resg,
                             int O, int I, int M) {
    const int b = blockIdx.z;
    const float* X = Xg + (size_t)b * I * M;
    float* out = outg + (size_t)b * O * M;
    const float* res = (FLAGS & 4) ? (resg + (size_t)b * O * M) : nullptr;

    __shared__ float Ws[8][132];
    __shared__ float Xs[8][128];

    const int tid = threadIdx.x;            // 256 threads
    const int tx = tid & 15, ty = tid >> 4;
    const int o0 = blockIdx.y * 128, m0 = blockIdx.x * 128;

    const int wr = tid >> 1;                // 0..127
    const int wc = (tid & 1) * 4;           // 0 or 4
    const int xr = tid >> 5;                // 0..7
    const int xc = (tid & 31) * 4;          // 0..124

    float acc[8][8];
#pragma unroll
    for (int i = 0; i < 8; i++)
#pragma unroll
        for (int j = 0; j < 8; j++) acc[i][j] = 0.0f;

    for (int kt = 0; kt < I; kt += 8) {
        float4 wv = *(const float4*)&W[(size_t)(o0 + wr) * I + kt + wc];
        float4 xv = *(const float4*)&X[(size_t)(kt + xr) * M + m0 + xc];
        __syncthreads();
        Ws[wc + 0][wr] = wv.x;
        Ws[wc + 1][wr] = wv.y;
        Ws[wc + 2][wr] = wv.z;
        Ws[wc + 3][wr] = wv.w;
        *(float4*)&Xs[xr][xc] = xv;
        __syncthreads();
#pragma unroll
        for (int k = 0; k < 8; k++) {
            float a[8], bb[8];
            *(float4*)&a[0]  = *(const float4*)&Ws[k][ty * 8];
            *(float4*)&a[4]  = *(const float4*)&Ws[k][ty * 8 + 4];
            *(float4*)&bb[0] = *(const float4*)&Xs[k][tx * 8];
            *(float4*)&bb[4] = *(const float4*)&Xs[k][tx * 8 + 4];
#pragma unroll
            for (int i = 0; i < 8; i++)
#pragma unroll
                for (int j = 0; j < 8; j++) acc[i][j] += a[i] * bb[j];
        }
    }

#pragma unroll
    for (int i = 0; i < 8; i++) {
        const int o = o0 + ty * 8 + i;
        const float bv = bias[o];
        float* orow = out + (size_t)o * M + m0 + tx * 8;
        const float* rrow = (FLAGS & 4) ? (res + (size_t)o * M + m0 + tx * 8) : nullptr;
#pragma unroll
        for (int jj = 0; jj < 8; jj += 4) {
            float4 v;
            v.x = acc[i][jj + 0] + bv;
            v.y = acc[i][jj + 1] + bv;
            v.z = acc[i][jj + 2] + bv;
            v.w = acc[i][jj + 3] + bv;
            if (FLAGS & 1) {
                v.x = fmaxf(v.x, 0.0f); v.y = fmaxf(v.y, 0.0f);
                v.z = fmaxf(v.z, 0.0f); v.w = fmaxf(v.w, 0.0f);
            }
            if (FLAGS & 2) {
                float4 old = *(float4*)&orow[jj];
                v.x += old.x; v.y += old.y; v.z += old.z; v.w += old.w;
            }
            if (FLAGS & 4) {
                float4 r = *(const float4*)&rrow[jj];
                v.x += r.x; v.y += r.y; v.z += r.z; v.w += r.w;
            }
            *(float4*)&orow[jj] = v;
        }
    }
}

// ---------------- pos_rel + pos conv1 --------------------------------------
// t1[b][c][n][k] = sum_d w[c][d]*(pos[b][d][n]-pos[b][d][idx]) + bias[c]
__global__ void posrel_conv1_kernel(const float* __restrict__ pos,
                                    const int* __restrict__ idx,
                                    const float* __restrict__ w,
                                    const float* __restrict__ bias,
                                    float* __restrict__ t1) {
    size_t i = (size_t)blockIdx.x * blockDim.x + threadIdx.x;  // B*PH*N*K
    if (i >= (size_t)B_ * PH_ * N_ * K_) return;
    int k = (int)(i % K_);
    int n = (int)((i / K_) % N_);
    int c = (int)((i / ((size_t)K_ * N_)) % PH_);
    int b = (int)(i / ((size_t)K_ * N_ * PH_));
    int m = idx[((size_t)b * N_ + n) * K_ + k];
    const float* p = pos + (size_t)b * 3 * N_;
    float rx = p[n] - p[m];
    float ry = p[N_ + n] - p[N_ + m];
    float rz = p[2 * N_ + n] - p[2 * N_ + m];
    t1[i] = w[c * 3] * rx + w[c * 3 + 1] * ry + w[c * 3 + 2] * rz + bias[c];
}

// ---------------- BN stats (training-mode, biased var) --------------------
__global__ void bn_stats_kernel(const float* __restrict__ x,
                                const float* __restrict__ g,
                                const float* __restrict__ beta,
                                float* __restrict__ scale,
                                float* __restrict__ shift, int C) {
    const int c = blockIdx.x;
    const size_t per = (size_t)N_ * K_;  // 65536
    double s = 0.0, sq = 0.0;
    for (int b = 0; b < B_; b++) {
        const float* p = x + ((size_t)b * C + c) * per;
        for (size_t i = threadIdx.x; i < per; i += blockDim.x) {
            double v = (double)p[i];
            s += v; sq += v * v;
        }
    }
    __shared__ double sh[256], sh2[256];
    sh[threadIdx.x] = s; sh2[threadIdx.x] = sq;
    __syncthreads();
    for (int st = 128; st > 0; st >>= 1) {
        if ((int)threadIdx.x < st) {
            sh[threadIdx.x]  += sh[threadIdx.x + st];
            sh2[threadIdx.x] += sh2[threadIdx.x + st];
        }
        __syncthreads();
    }
    if (threadIdx.x == 0) {
        double cnt  = (double)B_ * (double)per;
        double mean = sh[0] / cnt;
        double var  = sh2[0] / cnt - mean * mean;
        float  sc   = g[c] * (float)(1.0 / sqrt(var + 1e-5));
        scale[c] = sc;
        shift[c] = beta[c] - (float)mean * sc;
    }
}

// ---------------- BN affine + relu (in place) ------------------------------
__global__ void bn_relu_kernel(float* __restrict__ x,
                               const float* __restrict__ scale,
                               const float* __restrict__ shift,
                               int C, size_t total) {
    size_t i = (size_t)blockIdx.x * blockDim.x + threadIdx.x;
    if (i >= total) return;
    int c = (int)((i / ((size_t)N_ * K_)) % C);
    float v = x[i] * scale[c] + shift[c];
    x[i] = v > 0.0f ? v : 0.0f;
}

// ---------------- s = qf - gather(kf) + pos_emb ---------------------------
__global__ void build_s_kernel(const float* __restrict__ qf,
                               const float* __restrict__ kf,
                               const int* __restrict__ idx,
                               const float* __restrict__ pe,
                               float* __restrict__ s) {
    size_t i = (size_t)blockIdx.x * blockDim.x + threadIdx.x;  // B*DIM*N*K
    if (i >= (size_t)B_ * DIM_ * N_ * K_) return;
    int k = (int)(i % K_);
    int n = (int)((i / K_) % N_);
    int c = (int)((i / ((size_t)K_ * N_)) % DIM_);
    int b = (int)(i / ((size_t)K_ * N_ * DIM_));
    int m = idx[((size_t)b * N_ + n) * K_ + k];
    s[i] = qf[((size_t)b * DIM_ + c) * N_ + n]
         - kf[((size_t)b * DIM_ + c) * N_ + m]
         + pe[i];
}

// ---------------- softmax over K + aggregation -----------------------------
// agg[b][c][n] = sum_k softmax(attn[b][c][n][:])_k * (vf[b][c][n] + pe[b][c][n][k])
__global__ void softmax_agg_kernel(const float* __restrict__ attn,
                                   const float* __restrict__ vf,
                                   const float* __restrict__ pe,
                                   float* __restrict__ agg) {
    size_t i = (size_t)blockIdx.x * blockDim.x + threadIdx.x;  // B*DIM*N
    if (i >= (size_t)B_ * DIM_ * N_) return;
    const float* a = attn + i * K_;
    const float* pp = pe + i * K_;
    float mx = -3.4e38f;
#pragma unroll
    for (int k = 0; k < K_; k++) mx = fmaxf(mx, a[k]);
    float e[K_];
    float sum = 0.0f;
#pragma unroll
    for (int k = 0; k < K_; k++) { e[k] = expf(a[k] - mx); sum += e[k]; }
    float vb = vf[i];
    float acc = 0.0f;
#pragma unroll
    for (int k = 0; k < K_; k++) acc += e[k] * (vb + pp[k]);
    agg[i] = acc / sum;
}

// ---------------- launch ---------------------------------------------------
extern "C" void kernel_launch(void* const* d_in, const int* in_sizes, int n_in,
                              void* d_out, int out_size) {
    const float* pos     = (const float*)d_in[0];
    const float* key     = (const float*)d_in[1];
    const float* query   = (const float*)d_in[2];
    const float* mlpv_w1 = (const float*)d_in[3];
    const float* mlpv_b1 = (const float*)d_in[4];
    const float* mlpv_w2 = (const float*)d_in[5];
    const float* mlpv_b2 = (const float*)d_in[6];
    const float* mlpv_ws = (const float*)d_in[7];
    const float* mlpv_bs = (const float*)d_in[8];
    const float* wk      = (const float*)d_in[9];
    const float* bk      = (const float*)d_in[10];
    const float* wq      = (const float*)d_in[11];
    const float* bq      = (const float*)d_in[12];
    const float* wv      = (const float*)d_in[13];
    const float* bv      = (const float*)d_in[14];
    const float* pos_w1  = (const float*)d_in[15];
    const float* pos_b1  = (const float*)d_in[16];
    const float* pos_g1  = (const float*)d_in[17];
    const float* pos_be1 = (const float*)d_in[18];
    const float* pos_w2  = (const float*)d_in[19];
    const float* pos_b2  = (const float*)d_in[20];
    const float* att_w1  = (const float*)d_in[21];
    const float* att_b1  = (const float*)d_in[22];
    const float* att_g1  = (const float*)d_in[23];
    const float* att_be1 = (const float*)d_in[24];
    const float* att_w2  = (const float*)d_in[25];
    const float* att_b2  = (const float*)d_in[26];
    const float* we      = (const float*)d_in[27];
    const float* be      = (const float*)d_in[28];
    float* out = (float*)d_out;

    void *vx, *vt, *vvalue, *vkf, *vqf, *vvf, *vidx, *vt1, *vpe, *vs, *vh,
         *vscale, *vshift, *vagg;
    cudaGetSymbolAddress(&vx, g_x);
    cudaGetSymbolAddress(&vt, g_t);
    cudaGetSymbolAddress(&vvalue, g_value);
    cudaGetSymbolAddress(&vkf, g_kf);
    cudaGetSymbolAddress(&vqf, g_qf);
    cudaGetSymbolAddress(&vvf, g_vf);
    cudaGetSymbolAddress(&vidx, g_idx);
    cudaGetSymbolAddress(&vt1, g_t1);
    cudaGetSymbolAddress(&vpe, g_pe);
    cudaGetSymbolAddress(&vs, g_s);
    cudaGetSymbolAddress(&vh, g_h);
    cudaGetSymbolAddress(&vscale, g_scale);
    cudaGetSymbolAddress(&vshift, g_shift);
    cudaGetSymbolAddress(&vagg, g_agg);
    float* x_  = (float*)vx;    float* t_  = (float*)vt;
    float* val = (float*)vvalue;
    float* kf_ = (float*)vkf;   float* qf_ = (float*)vqf;  float* vf_ = (float*)vvf;
    int*   idx = (int*)vidx;
    float* t1_ = (float*)vt1;   float* pe_ = (float*)vpe;  float* s_  = (float*)vs;
    float* h_  = (float*)vh;
    float* sc_ = (float*)vscale; float* sh_ = (float*)vshift;
    float* agg = (float*)vagg;

    // 1. concat
    {
        size_t tot = (size_t)B_ * 2 * C_ * N_;
        concat_kernel<<<(unsigned)((tot + 255) / 256), 256>>>(key, query, x_);
    }
    // 2. knn
    knn_kernel<<<dim3(N_ / 256, B_), 256>>>(pos, idx);
    // 3. value = mlpv_w2 @ relu(mlpv_w1 @ x + b1) + b2 + (mlpv_ws @ x + bs)
    sgemm_kernel<1><<<dim3(N_ / 128, C_ / 128, B_), 256>>>(
        mlpv_w1, x_, mlpv_b1, t_, nullptr, C_, 2 * C_, N_);
    sgemm_kernel<0><<<dim3(N_ / 128, C_ / 128, B_), 256>>>(
        mlpv_w2, t_, mlpv_b2, val, nullptr, C_, C_, N_);
    sgemm_kernel<2><<<dim3(N_ / 128, C_ / 128, B_), 256>>>(
        mlpv_ws, x_, mlpv_bs, val, nullptr, C_, 2 * C_, N_);
    // 4. k_f, q_f, v_f
    sgemm_kernel<0><<<dim3(N_ / 128, DIM_ / 128, B_), 256>>>(
        wk, key, bk, kf_, nullptr, DIM_, C_, N_);
    sgemm_kernel<0><<<dim3(N_ / 128, DIM_ / 128, B_), 256>>>(
        wq, query, bq, qf_, nullptr, DIM_, C_, N_);
    sgemm_kernel<0><<<dim3(N_ / 128, DIM_ / 128, B_), 256>>>(
        wv, val, bv, vf_, nullptr, DIM_, C_, N_);
    // 5. pos mlp: conv1 -> bn -> relu -> conv2
    {
        size_t tot = (size_t)B_ * PH_ * N_ * K_;
        posrel_conv1_kernel<<<(unsigned)((tot + 255) / 256), 256>>>(
            pos, idx, pos_w1, pos_b1, t1_);
        bn_stats_kernel<<<PH_, 256>>>(t1_, pos_g1, pos_be1, sc_, sh_, PH_);
        bn_relu_kernel<<<(unsigned)((tot + 255) / 256), 256>>>(t1_, sc_, sh_, PH_, tot);
        sgemm_kernel<0><<<dim3((N_ * K_) / 128, DIM_ / 128, B_), 256>>>(
            pos_w2, t1_, pos_b2, pe_, nullptr, DIM_, PH_, N_ * K_);
    }
    // 6. s = qk_rel + pos_emb
    {
        size_t tot = (size_t)B_ * DIM_ * N_ * K_;
        build_s_kernel<<<(unsigned)((tot + 255) / 256), 256>>>(qf_, kf_, idx, pe_, s_);
    }
    // 7. attn mlp: conv1 -> bn -> relu -> conv2 (writes back into s_)
    {
        sgemm_kernel<0><<<dim3((N_ * K_) / 128, AH_ / 128, B_), 256>>>(
            att_w1, s_, att_b1, h_, nullptr, AH_, DIM_, N_ * K_);
        bn_stats_kernel<<<AH_, 256>>>(h_, att_g1, att_be1, sc_, sh_, AH_);
        size_t tot = (size_t)B_ * AH_ * N_ * K_;
        bn_relu_kernel<<<(unsigned)((tot + 255) / 256), 256>>>(h_, sc_, sh_, AH_, tot);
        sgemm_kernel<0><<<dim3((N_ * K_) / 128, DIM_ / 128, B_), 256>>>(
            att_w2, h_, att_b2, s_, nullptr, DIM_, AH_, N_ * K_);
    }
    // 8. softmax over K + aggregate
    {
        size_t tot = (size_t)B_ * DIM_ * N_;
        softmax_agg_kernel<<<(unsigned)((tot + 255) / 256), 256>>>(s_, vf_, pe_, agg);
    }
    // 9. y = we @ agg + be + identity(value)
    sgemm_kernel<4><<<dim3(N_ / 128, C_ / 128, B_), 256>>>(
        we, agg, be, out, val, C_, DIM_, N_);
}

// round 3
// speedup vs baseline: 1.5346x; 1.5346x over previous
#include <cuda_runtime.h>
#include <math.h>

#define B_   2
#define C_   128
#define N_   4096
#define K_   16
#define DIM_ 256
#define PH_  64
#define AH_  1024
#define M_   (N_ * K_)          // 65536 columns per batch in (n,k) space

// ---------------- scratch ---------------------------------------------------
__device__ float g_x    [(size_t)B_ * 2 * C_ * N_];
__device__ float g_t    [(size_t)B_ * C_ * N_];
__device__ float g_value[(size_t)B_ * C_ * N_];
__device__ float g_vf   [(size_t)B_ * DIM_ * N_];
__device__ float g_u    [(size_t)B_ * AH_ * N_];
__device__ float g_v    [(size_t)B_ * AH_ * N_];
__device__ int   g_idx  [(size_t)B_ * N_ * K_];
__device__ float g_t1   [(size_t)B_ * PH_ * M_];
__device__ float g_pe   [(size_t)B_ * DIM_ * M_];
__device__ float g_h    [(size_t)B_ * AH_ * M_];       // 537 MB
__device__ float g_agg  [(size_t)B_ * DIM_ * N_];
__device__ float g_part [(size_t)B_ * (M_/128) * AH_ * 2];   // GEMM1 BN partials
__device__ float g_partp[(size_t)PH_ * 512 * 2];             // pos BN partials
__device__ float g_Wuq  [AH_ * C_];
__device__ float g_Wvk  [AH_ * C_];
__device__ float g_A1t  [PH_ * AH_];     // (att_w1@pos_w2)^T  [64][1024]
__device__ float g_w2t  [AH_ * DIM_];    // att_w2^T [1024][256]
__device__ float g_posw2t[PH_ * DIM_];   // pos_w2^T [64][256]
__device__ float g_bias1[AH_];
__device__ float g_scp  [PH_];
__device__ float g_shp  [PH_];
__device__ float g_sca  [AH_];
__device__ float g_sha  [AH_];
__device__ float g_zero [AH_];           // stays zero (zero-initialized)

// ---------------- concat ----------------------------------------------------
__global__ void concat_kernel(const float* __restrict__ key,
                              const float* __restrict__ query,
                              float* __restrict__ x) {
    size_t i = (size_t)blockIdx.x * blockDim.x + threadIdx.x;
    if (i >= (size_t)B_ * 2 * C_ * N_) return;
    int n = (int)(i % N_);
    int c = (int)((i / N_) % (2 * C_));
    int b = (int)(i / ((size_t)N_ * 2 * C_));
    float v;
    if (c < C_) v = key  [((size_t)b * C_ + c) * N_ + n];
    else        v = query[((size_t)b * C_ + (c - C_)) * N_ + n];
    x[i] = v;
}

// ---------------- KNN -------------------------------------------------------
__global__ void knn_kernel(const float* __restrict__ pos, int* __restrict__ idx) {
    const int b = blockIdx.y;
    const int n = blockIdx.x * blockDim.x + threadIdx.x;
    const float* p = pos + (size_t)b * 3 * N_;
    const float qx = p[n], qy = p[N_ + n], qz = p[2 * N_ + n];
    const float qs = qx * qx + qy * qy + qz * qz;
    float bd[K_]; int bi[K_];
#pragma unroll
    for (int j = 0; j < K_; j++) { bd[j] = 3.4e38f; bi[j] = 0; }
    __shared__ float sx[512], sy[512], sz[512], ss[512];
    for (int t0 = 0; t0 < N_; t0 += 512) {
        __syncthreads();
        for (int i = threadIdx.x; i < 512; i += blockDim.x) {
            float x = p[t0 + i], y = p[N_ + t0 + i], z = p[2 * N_ + t0 + i];
            sx[i] = x; sy[i] = y; sz[i] = z; ss[i] = x * x + y * y + z * z;
        }
        __syncthreads();
        for (int i = 0; i < 512; i++) {
            float d = qs + ss[i] - 2.0f * (qx * sx[i] + qy * sy[i] + qz * sz[i]);
            if (d < bd[K_ - 1]) {
                int j = K_ - 1;
                while (j > 0 && d < bd[j - 1]) { bd[j] = bd[j - 1]; bi[j] = bi[j - 1]; j--; }
                bd[j] = d; bi[j] = t0 + i;
            }
        }
    }
    int* op = idx + ((size_t)b * N_ + n) * K_;
#pragma unroll
    for (int j = 0; j < K_; j++) op[j] = bi[j];
}

// ---------------- precompute small products ---------------------------------
__global__ void smallmm_kernel(const float* __restrict__ A, const float* __restrict__ Bm,
                               float* __restrict__ Cc, int O, int Id, int J, int tr) {
    int t = blockIdx.x * 256 + threadIdx.x;
    if (t >= O * J) return;
    int o = t / J, j = t % J;
    float s = 0.0f;
    for (int d = 0; d < Id; d++) s += A[o * Id + d] * Bm[d * J + j];
    if (tr) Cc[j * O + o] = s; else Cc[o * J + j] = s;
}
__global__ void transpose_kernel(const float* __restrict__ Mm, float* __restrict__ T,
                                 int R, int Cc) {
    int t = blockIdx.x * 256 + threadIdx.x;
    if (t >= R * Cc) return;
    int r = t / Cc, c = t % Cc;
    T[c * R + r] = Mm[r * Cc + c];
}
__global__ void bias1_kernel(const float* __restrict__ w1, const float* __restrict__ bq,
                             const float* __restrict__ bk, const float* __restrict__ pb2,
                             const float* __restrict__ ab1, float* __restrict__ out) {
    int o = blockIdx.x * 256 + threadIdx.x;
    if (o >= AH_) return;
    float s = ab1[o];
    for (int d = 0; d < DIM_; d++) s += w1[o * DIM_ + d] * (bq[d] - bk[d] + pb2[d]);
    out[o] = s;
}

// ---------------- generic fp32 SGEMM (small GEMMs) --------------------------
// FLAGS: 1=relu, 2=accumulate, 4=residual add
template <int FLAGS>
__global__ void sgemm_kernel(const float* __restrict__ W, const float* __restrict__ Xg,
                             const float* __restrict__ bias, float* __restrict__ outg,
                             const float* __restrict__ resg, int O, int I, int M) {
    const int b = blockIdx.z;
    const float* X = Xg + (size_t)b * I * M;
    float* out = outg + (size_t)b * O * M;
    const float* res = (FLAGS & 4) ? (resg + (size_t)b * O * M) : nullptr;
    __shared__ float Ws[8][132];
    __shared__ float Xs[8][128];
    const int tid = threadIdx.x;
    const int tx = tid & 15, ty = tid >> 4;
    const int o0 = blockIdx.y * 128, m0 = blockIdx.x * 128;
    const int wr = tid >> 1, wc = (tid & 1) * 4;
    const int xr = tid >> 5, xc = (tid & 31) * 4;
    float acc[8][8];
#pragma unroll
    for (int i = 0; i < 8; i++)
#pragma unroll
        for (int j = 0; j < 8; j++) acc[i][j] = 0.0f;
    for (int kt = 0; kt < I; kt += 8) {
        float4 wv = *(const float4*)&W[(size_t)(o0 + wr) * I + kt + wc];
        float4 xv = *(const float4*)&X[(size_t)(kt + xr) * M + m0 + xc];
        __syncthreads();
        Ws[wc + 0][wr] = wv.x; Ws[wc + 1][wr] = wv.y;
        Ws[wc + 2][wr] = wv.z; Ws[wc + 3][wr] = wv.w;
        *(float4*)&Xs[xr][xc] = xv;
        __syncthreads();
#pragma unroll
        for (int k = 0; k < 8; k++) {
            float a[8], bb[8];
            *(float4*)&a[0]  = *(const float4*)&Ws[k][ty * 8];
            *(float4*)&a[4]  = *(const float4*)&Ws[k][ty * 8 + 4];
            *(float4*)&bb[0] = *(const float4*)&Xs[k][tx * 8];
            *(float4*)&bb[4] = *(const float4*)&Xs[k][tx * 8 + 4];
#pragma unroll
            for (int i = 0; i < 8; i++)
#pragma unroll
                for (int j = 0; j < 8; j++) acc[i][j] += a[i] * bb[j];
        }
    }
#pragma unroll
    for (int i = 0; i < 8; i++) {
        const int o = o0 + ty * 8 + i;
        const float bv = bias[o];
        float* orow = out + (size_t)o * M + m0 + tx * 8;
        const float* rrow = (FLAGS & 4) ? (res + (size_t)o * M + m0 + tx * 8) : nullptr;
#pragma unroll
        for (int jj = 0; jj < 8; jj += 4) {
            float4 v;
            v.x = acc[i][jj + 0] + bv; v.y = acc[i][jj + 1] + bv;
            v.z = acc[i][jj + 2] + bv; v.w = acc[i][jj + 3] + bv;
            if (FLAGS & 1) { v.x = fmaxf(v.x, 0.f); v.y = fmaxf(v.y, 0.f);
                             v.z = fmaxf(v.z, 0.f); v.w = fmaxf(v.w, 0.f); }
            if (FLAGS & 2) { float4 old = *(float4*)&orow[jj];
                             v.x += old.x; v.y += old.y; v.z += old.z; v.w += old.w; }
            if (FLAGS & 4) { float4 r = *(const float4*)&rrow[jj];
                             v.x += r.x; v.y += r.y; v.z += r.z; v.w += r.w; }
            *(float4*)&orow[jj] = v;
        }
    }
}

// ---------------- pos_rel conv1 + BN partial stats ---------------------------
__global__ void posrel_kernel(const float* __restrict__ pos, const int* __restrict__ idx,
                              const float* __restrict__ w, const float* __restrict__ bias,
                              float* __restrict__ t1, float* __restrict__ part) {
    size_t i = (size_t)blockIdx.x * 256 + threadIdx.x;   // exact: B*PH*M / 256 blocks
    int k = (int)(i & 15);
    int n = (int)((i >> 4) & (N_ - 1));
    int c = (int)((i >> 16) & (PH_ - 1));
    int b = (int)(i >> 22);
    int m = idx[(((size_t)b * N_ + n) << 4) + k];
    const float* p = pos + (size_t)b * 3 * N_;
    float rx = p[n] - p[m];
    float ry = p[N_ + n] - p[N_ + m];
    float rz = p[2 * N_ + n] - p[2 * N_ + m];
    float val = w[c * 3] * rx + w[c * 3 + 1] * ry + w[c * 3 + 2] * rz + bias[c];
    t1[i] = val;
    __shared__ float ssum[256], ssq[256];
    ssum[threadIdx.x] = val; ssq[threadIdx.x] = val * val;
    __syncthreads();
    for (int st = 128; st > 0; st >>= 1) {
        if ((int)threadIdx.x < st) {
            ssum[threadIdx.x] += ssum[threadIdx.x + st];
            ssq[threadIdx.x]  += ssq[threadIdx.x + st];
        }
        __syncthreads();
    }
    if (threadIdx.x == 0) {
        int cb = (blockIdx.x >> 8) & (PH_ - 1);
        int bb = blockIdx.x >> 14;
        int sblk = blockIdx.x & 255;
        size_t o = ((size_t)cb * 512 + bb * 256 + sblk) * 2;
        part[o] = ssum[0]; part[o + 1] = ssq[0];
    }
}

// ---------------- BN finalize (generic over partial layout) ------------------
__global__ void finalize_stats(const float* __restrict__ part, int P, int ps, int cs,
                               const float* __restrict__ g, const float* __restrict__ be,
                               float* __restrict__ sc, float* __restrict__ sh, float cnt) {
    int c = blockIdx.x;
    double s = 0.0, q = 0.0;
    for (int p = threadIdx.x; p < P; p += blockDim.x) {
        size_t o = ((size_t)p * ps + (size_t)c * cs) * 2;
        s += (double)part[o]; q += (double)part[o + 1];
    }
    __shared__ double S[256], Q[256];
    S[threadIdx.x] = s; Q[threadIdx.x] = q;
    __syncthreads();
    for (int st = 128; st > 0; st >>= 1) {
        if ((int)threadIdx.x < st) {
            S[threadIdx.x] += S[threadIdx.x + st];
            Q[threadIdx.x] += Q[threadIdx.x + st];
        }
        __syncthreads();
    }
    if (threadIdx.x == 0) {
        double mean = S[0] / (double)cnt;
        double var  = Q[0] / (double)cnt - mean * mean;
        float scv = g[c] * (float)(1.0 / sqrt(var + 1e-5));
        sc[c] = scv;
        sh[c] = be[c] - (float)mean * scv;
    }
}

// ---------------- fused mid: h = A1t@t1relu + u - gather(v) + bias1 ----------
//                  pe = posw2t@t1relu + pos_b2         (+ BN partial stats of h)
__global__ __launch_bounds__(256) void fused_mid_kernel(
    const float* __restrict__ t1, const float* __restrict__ psc,
    const float* __restrict__ psh, const float* __restrict__ A1t,
    const float* __restrict__ posw2t, const float* __restrict__ bias1,
    const float* __restrict__ pos_b2, const float* __restrict__ u,
    const float* __restrict__ v, const int* __restrict__ idx,
    float* __restrict__ h, float* __restrict__ pe, float* __restrict__ part) {
    extern __shared__ float sm[];
    float (*Xs)[128] = (float(*)[128])sm;
    float (*Ws)[128] = (float(*)[128])(sm + 64 * 128);
    float* redS = (float*)(sm + 64 * 128);           // alias Ws (reused post-FMA)
    float* redQ = redS + 128 * 17;
    __shared__ int sidx[128];
    const int tid = threadIdx.x;
    const int tx = tid & 15, ty = tid >> 4;
    const int b = blockIdx.y;
    const int m0 = blockIdx.x * 128;
    const int lr = tid >> 5, lc = (tid & 31) * 4;

    // load X panel (64 x 128) with pos-BN relu applied
#pragma unroll
    for (int it = 0; it < 8; it++) {
        int r = it * 8 + lr;
        float4 vv = *(const float4*)&t1[((size_t)(b * PH_ + r)) * M_ + m0 + lc];
        float s_ = psc[r], h_ = psh[r];
        float4 o;
        o.x = fmaxf(vv.x * s_ + h_, 0.f); o.y = fmaxf(vv.y * s_ + h_, 0.f);
        o.z = fmaxf(vv.z * s_ + h_, 0.f); o.w = fmaxf(vv.w * s_ + h_, 0.f);
        *(float4*)&Xs[r][lc] = o;
    }
    if (tid < 128) sidx[tid] = idx[(((size_t)b * N_ + (m0 >> 4)) << 4) + tid];

    const int nloc = tx >> 1;
    const int khalf = (tx & 1) * 8;
    const int n = (m0 >> 4) + nloc;

    for (int ot = 0; ot < 10; ot++) {
        const float* Wt; int wstr;
        if (ot < 8) { Wt = A1t + ot * 128; wstr = AH_; }
        else        { Wt = posw2t + (ot - 8) * 128; wstr = DIM_; }
        __syncthreads();   // red readers done (and first-iter X/sidx ready)
#pragma unroll
        for (int it = 0; it < 8; it++) {
            int r = it * 8 + lr;
            *(float4*)&Ws[r][lc] = *(const float4*)&Wt[(size_t)r * wstr + lc];
        }
        __syncthreads();
        float acc[8][8];
#pragma unroll
        for (int i = 0; i < 8; i++)
#pragma unroll
            for (int j = 0; j < 8; j++) acc[i][j] = 0.0f;
#pragma unroll 4
        for (int k = 0; k < 64; k++) {
            float a[8], bb[8];
            *(float4*)&a[0]  = *(const float4*)&Ws[k][ty * 8];
            *(float4*)&a[4]  = *(const float4*)&Ws[k][ty * 8 + 4];
            *(float4*)&bb[0] = *(const float4*)&Xs[k][tx * 8];
            *(float4*)&bb[4] = *(const float4*)&Xs[k][tx * 8 + 4];
#pragma unroll
            for (int i = 0; i < 8; i++)
#pragma unroll
                for (int j = 0; j < 8; j++) acc[i][j] += a[i] * bb[j];
        }
        __syncthreads();   // all FMA reads of Ws done before red overwrite
        if (ot < 8) {
#pragma unroll
            for (int i = 0; i < 8; i++) {
                int cl = ty * 8 + i;
                int c = ot * 128 + cl;
                size_t crow = (size_t)b * AH_ + c;
                float uval = u[crow * N_ + n] + bias1[c];
                const float* vrow = v + crow * N_;
                float hv[8]; float s = 0.f, q = 0.f;
#pragma unroll
                for (int j = 0; j < 8; j++) {
                    float val = acc[i][j] + uval - vrow[sidx[nloc * 16 + khalf + j]];
                    hv[j] = val; s += val; q += val * val;
                }
                float* hd = h + crow * M_ + m0 + tx * 8;
                float4 v0 = make_float4(hv[0], hv[1], hv[2], hv[3]);
                float4 v1 = make_float4(hv[4], hv[5], hv[6], hv[7]);
                *(float4*)hd = v0; *(float4*)(hd + 4) = v1;
                redS[cl * 17 + tx] = s; redQ[cl * 17 + tx] = q;
            }
            __syncthreads();
            if (tid < 128) {
                float s = 0.f, q = 0.f;
#pragma unroll
                for (int t = 0; t < 16; t++) { s += redS[tid * 17 + t]; q += redQ[tid * 17 + t]; }
                size_t p = (((size_t)b * (M_ / 128) + blockIdx.x) * AH_ + ot * 128 + tid) * 2;
                part[p] = s; part[p + 1] = q;
            }
        } else {
#pragma unroll
            for (int i = 0; i < 8; i++) {
                int c = (ot - 8) * 128 + ty * 8 + i;
                float bv = pos_b2[c];
                float* pd = pe + ((size_t)b * DIM_ + c) * M_ + m0 + tx * 8;
                float4 v0 = make_float4(acc[i][0] + bv, acc[i][1] + bv,
                                        acc[i][2] + bv, acc[i][3] + bv);
                float4 v1 = make_float4(acc[i][4] + bv, acc[i][5] + bv,
                                        acc[i][6] + bv, acc[i][7] + bv);
                *(float4*)pd = v0; *(float4*)(pd + 4) = v1;
            }
        }
    }
}

// ---------------- attn GEMM2 + softmax + aggregation ------------------------
// agg[b][c][n] = vf[b][c][n] + sum_k softmax_k(W2t^T @ relu(bn(h)))[c,n,k] * pe[c,n,k]
__global__ __launch_bounds__(512, 1) void attn2_kernel(
    const float* __restrict__ W2t,   // [1024][256]
    const float* __restrict__ hg,    // [B][1024][M]
    const float* __restrict__ scale, const float* __restrict__ shift,
    const float* __restrict__ pe, const float* __restrict__ vf,
    float* __restrict__ agg) {
    __shared__ float Xs[16][128];
    __shared__ float Ws[16][256];
    __shared__ float Ss[AH_], Sh[AH_];
    const int tid = threadIdx.x;
    const int tx = tid & 15, ty = tid >> 4;
    const int b = blockIdx.y;
    const int m0 = blockIdx.x * 128;
    const float* X = hg + (size_t)b * AH_ * M_;
    const int xr = tid >> 5, xc = (tid & 31) * 4;
    const int wr = tid >> 6, wc = (tid & 63) * 4;

    for (int i = tid; i < AH_; i += 512) { Ss[i] = scale[i]; Sh[i] = shift[i]; }

    float acc[8][8];
#pragma unroll
    for (int i = 0; i < 8; i++)
#pragma unroll
        for (int j = 0; j < 8; j++) acc[i][j] = 0.0f;

    float4 xv = *(const float4*)&X[(size_t)xr * M_ + m0 + xc];
    float4 wv0 = *(const float4*)&W2t[(size_t)wr * DIM_ + wc];
    float4 wv1 = *(const float4*)&W2t[(size_t)(wr + 8) * DIM_ + wc];

    for (int kt = 0; kt < AH_ / 16; kt++) {
        __syncthreads();
        {
            float s_ = Ss[kt * 16 + xr], h_ = Sh[kt * 16 + xr];
            float4 o;
            o.x = fmaxf(xv.x * s_ + h_, 0.f); o.y = fmaxf(xv.y * s_ + h_, 0.f);
            o.z = fmaxf(xv.z * s_ + h_, 0.f); o.w = fmaxf(xv.w * s_ + h_, 0.f);
            *(float4*)&Xs[xr][xc] = o;
            *(float4*)&Ws[wr][wc] = wv0;
            *(float4*)&Ws[wr + 8][wc] = wv1;
        }
        __syncthreads();
        if (kt + 1 < AH_ / 16) {
            xv  = *(const float4*)&X[(size_t)((kt + 1) * 16 + xr) * M_ + m0 + xc];
            wv0 = *(const float4*)&W2t[(size_t)((kt + 1) * 16 + wr) * DIM_ + wc];
            wv1 = *(const float4*)&W2t[(size_t)((kt + 1) * 16 + wr + 8) * DIM_ + wc];
        }
#pragma unroll
        for (int k = 0; k < 16; k++) {
            float a[8], bb[8];
            *(float4*)&a[0]  = *(const float4*)&Ws[k][ty * 8];
            *(float4*)&a[4]  = *(const float4*)&Ws[k][ty * 8 + 4];
            *(float4*)&bb[0] = *(const float4*)&Xs[k][tx * 8];
            *(float4*)&bb[4] = *(const float4*)&Xs[k][tx * 8 + 4];
#pragma unroll
            for (int i = 0; i < 8; i++)
#pragma unroll
                for (int j = 0; j < 8; j++) acc[i][j] += a[i] * bb[j];
        }
    }

    // epilogue: per (c, n) softmax over k (att_b2 is softmax-invariant) + agg
    const int n = (m0 >> 4) + (tx >> 1);
    const int khalf = (tx & 1) * 8;
#pragma unroll
    for (int i = 0; i < 8; i++) {
        int c = ty * 8 + i;
        float mh = acc[i][0];
#pragma unroll
        for (int j = 1; j < 8; j++) mh = fmaxf(mh, acc[i][j]);
        mh = fmaxf(mh, __shfl_xor_sync(0xffffffffu, mh, 1));
        float e[8]; float ssum = 0.f;
#pragma unroll
        for (int j = 0; j < 8; j++) { e[j] = __expf(acc[i][j] - mh); ssum += e[j]; }
        float stot = ssum + __shfl_xor_sync(0xffffffffu, ssum, 1);
        const float* per = pe + ((size_t)b * DIM_ + c) * M_ + n * 16 + khalf;
        float4 p0 = *(const float4*)per;
        float4 p1 = *(const float4*)(per + 4);
        float part = e[0] * p0.x + e[1] * p0.y + e[2] * p0.z + e[3] * p0.w
                   + e[4] * p1.x + e[5] * p1.y + e[6] * p1.z + e[7] * p1.w;
        part += __shfl_xor_sync(0xffffffffu, part, 1);
        if ((tx & 1) == 0) {
            size_t o = ((size_t)b * DIM_ + c) * N_ + n;
            agg[o] = vf[o] + part / stot;
        }
    }
}

// ---------------- launch ----------------------------------------------------
extern "C" void kernel_launch(void* const* d_in, const int* in_sizes, int n_in,
                              void* d_out, int out_size) {
    const float* pos     = (const float*)d_in[0];
    const float* key     = (const float*)d_in[1];
    const float* query   = (const float*)d_in[2];
    const float* mlpv_w1 = (const float*)d_in[3];
    const float* mlpv_b1 = (const float*)d_in[4];
    const float* mlpv_w2 = (const float*)d_in[5];
    const float* mlpv_b2 = (const float*)d_in[6];
    const float* mlpv_ws = (const float*)d_in[7];
    const float* mlpv_bs = (const float*)d_in[8];
    const float* wk      = (const float*)d_in[9];
    const float* bk      = (const float*)d_in[10];
    const float* wq      = (const float*)d_in[11];
    const float* bq      = (const float*)d_in[12];
    const float* wv      = (const float*)d_in[13];
    const float* bv      = (const float*)d_in[14];
    const float* pos_w1  = (const float*)d_in[15];
    const float* pos_b1  = (const float*)d_in[16];
    const float* pos_g1  = (const float*)d_in[17];
    const float* pos_be1 = (const float*)d_in[18];
    const float* pos_w2  = (const float*)d_in[19];
    const float* pos_b2  = (const float*)d_in[20];
    const float* att_w1  = (const float*)d_in[21];
    const float* att_b1  = (const float*)d_in[22];
    const float* att_g1  = (const float*)d_in[23];
    const float* att_be1 = (const float*)d_in[24];
    const float* att_w2  = (const float*)d_in[25];
    const float* att_b2  = (const float*)d_in[26];  (void)att_b2; // softmax-invariant
    const float* we      = (const float*)d_in[27];
    const float* be      = (const float*)d_in[28];
    float* out = (float*)d_out;

    void *p;
#define GETP(sym, var) cudaGetSymbolAddress(&p, sym); float* var = (float*)p;
    GETP(g_x, x_)       GETP(g_t, t_)       GETP(g_value, val)
    GETP(g_vf, vf_)     GETP(g_u, u_)       GETP(g_v, v_)
    GETP(g_t1, t1_)     GETP(g_pe, pe_)     GETP(g_h, h_)
    GETP(g_agg, agg)    GETP(g_part, part)  GETP(g_partp, partp)
    GETP(g_Wuq, Wuq)    GETP(g_Wvk, Wvk)    GETP(g_A1t, A1t)
    GETP(g_w2t, w2t)    GETP(g_posw2t, posw2t) GETP(g_bias1, bias1)
    GETP(g_scp, scp)    GETP(g_shp, shp)    GETP(g_sca, sca)
    GETP(g_sha, sha)    GETP(g_zero, zero)
#undef GETP
    cudaGetSymbolAddress(&p, g_idx); int* idx = (int*)p;

    // --- precompute folded weights ---
    smallmm_kernel<<<(AH_ * C_ + 255) / 256, 256>>>(att_w1, wq, Wuq, AH_, DIM_, C_, 0);
    smallmm_kernel<<<(AH_ * C_ + 255) / 256, 256>>>(att_w1, wk, Wvk, AH_, DIM_, C_, 0);
    smallmm_kernel<<<(AH_ * PH_ + 255) / 256, 256>>>(att_w1, pos_w2, A1t, AH_, DIM_, PH_, 1);
    transpose_kernel<<<(DIM_ * AH_ + 255) / 256, 256>>>(att_w2, w2t, DIM_, AH_);
    transpose_kernel<<<(DIM_ * PH_ + 255) / 256, 256>>>(pos_w2, posw2t, DIM_, PH_);
    bias1_kernel<<<(AH_ + 255) / 256, 256>>>(att_w1, bq, bk, pos_b2, att_b1, bias1);

    // --- front end ---
    concat_kernel<<<(unsigned)(((size_t)B_ * 2 * C_ * N_ + 255) / 256), 256>>>(key, query, x_);
    knn_kernel<<<dim3(N_ / 256, B_), 256>>>(pos, idx);
    sgemm_kernel<1><<<dim3(N_ / 128, C_ / 128, B_), 256>>>(mlpv_w1, x_, mlpv_b1, t_, nullptr, C_, 2 * C_, N_);
    sgemm_kernel<0><<<dim3(N_ / 128, C_ / 128, B_), 256>>>(mlpv_w2, t_, mlpv_b2, val, nullptr, C_, C_, N_);
    sgemm_kernel<2><<<dim3(N_ / 128, C_ / 128, B_), 256>>>(mlpv_ws, x_, mlpv_bs, val, nullptr, C_, 2 * C_, N_);
    sgemm_kernel<0><<<dim3(N_ / 128, DIM_ / 128, B_), 256>>>(wv, val, bv, vf_, nullptr, DIM_, C_, N_);
    sgemm_kernel<0><<<dim3(N_ / 128, AH_ / 128, B_), 256>>>(Wuq, query, zero, u_, nullptr, AH_, C_, N_);
    sgemm_kernel<0><<<dim3(N_ / 128, AH_ / 128, B_), 256>>>(Wvk, key, zero, v_, nullptr, AH_, C_, N_);

    // --- pos_rel conv1 + pos BN ---
    posrel_kernel<<<(unsigned)(((size_t)B_ * PH_ * M_) / 256), 256>>>(pos, idx, pos_w1, pos_b1, t1_, partp);
    finalize_stats<<<PH_, 256>>>(partp, 512, 1, 512, pos_g1, pos_be1, scp, shp, (float)((size_t)B_ * M_));

    // --- fused mid: h + pe (+ attn BN partials) ---
    cudaFuncSetAttribute(fused_mid_kernel, cudaFuncAttributeMaxDynamicSharedMemorySize, 65536);
    fused_mid_kernel<<<dim3(M_ / 128, B_), 256, 65536>>>(
        t1_, scp, shp, A1t, posw2t, bias1, pos_b2, u_, v_, idx, h_, pe_, part);
    finalize_stats<<<AH_, 256>>>(part, B_ * (M_ / 128), AH_, 1, att_g1, att_be1, sca, sha, (float)((size_t)B_ * M_));

    // --- big GEMM2 + softmax + aggregation ---
    attn2_kernel<<<dim3(M_ / 128, B_), 512>>>(w2t, h_, sca, sha, pe_, vf_, agg);

    // --- final projection + residual ---
    sgemm_kernel<4><<<dim3(N_ / 128, C_ / 128, B_), 256>>>(we, agg, be, out, val, C_, DIM_, N_);
}

// round 5
// speedup vs baseline: 1.7760x; 1.1573x over previous
#include <cuda_runtime.h>
#include <cuda_bf16.h>
#include <math.h>
#include <stdint.h>

#define B_   2
#define C_   128
#define N_   4096
#define K_   16
#define DIM_ 256
#define PH_  64
#define AH_  1024
#define M_   (N_ * K_)          // 65536 columns per batch in (n,k) space

// ---------------- scratch ---------------------------------------------------
__device__ float g_x    [(size_t)B_ * 2 * C_ * N_];
__device__ float g_t    [(size_t)B_ * C_ * N_];
__device__ float g_value[(size_t)B_ * C_ * N_];
__device__ float g_vf   [(size_t)B_ * DIM_ * N_];
__device__ float g_u    [(size_t)B_ * AH_ * N_];
__device__ float g_v    [(size_t)B_ * AH_ * N_];
__device__ int   g_idx  [(size_t)B_ * N_ * K_];
__device__ float g_t1   [(size_t)B_ * PH_ * M_];
__device__ float g_pe   [(size_t)B_ * DIM_ * M_];
__device__ float g_h    [(size_t)B_ * AH_ * M_];       // h_t: [B][M_][AH]
__device__ float g_agg  [(size_t)B_ * DIM_ * N_];
__device__ float g_part [(size_t)B_ * (M_/128) * AH_ * 2];
__device__ float g_partp[(size_t)PH_ * 512 * 2];
__device__ float g_Wuq  [AH_ * C_];
__device__ float g_Wvk  [AH_ * C_];
__device__ float g_A1t  [PH_ * AH_];
__device__ float g_posw2t[PH_ * DIM_];
__device__ float g_bias1[AH_];
__device__ float g_scp  [PH_];
__device__ float g_shp  [PH_];
__device__ float g_sca  [AH_];
__device__ float g_sha  [AH_];
__device__ float g_zero [AH_];
// pre-swizzled bf16 image of att_w2: 16 K-chunks x (hi 32KB + lo 32KB) = 1MB
__device__ unsigned int g_w2img[16 * 65536 / 4];

// ---------------- helpers ---------------------------------------------------
__device__ __forceinline__ uint32_t smem_u32(const void* p) {
    uint32_t a;
    asm("{ .reg .u64 t; cvta.to.shared.u64 t, %1; cvt.u32.u64 %0, t; }" : "=r"(a) : "l"(p));
    return a;
}
#define SWZ128(b) ((b) ^ (((b) >> 3) & 0x70))
__device__ __forceinline__ uint32_t pack_bf16(float a, float b) {
    __nv_bfloat16 ha = __float2bfloat16(a), hb = __float2bfloat16(b);
    return (uint32_t)__bfloat16_as_ushort(ha) |
           ((uint32_t)__bfloat16_as_ushort(hb) << 16);
}
__device__ __forceinline__ void ldm_x4(uint32_t* r, uint32_t addr) {
    asm volatile("ldmatrix.sync.aligned.m8n8.x4.shared.b16 {%0,%1,%2,%3}, [%4];"
        : "=r"(r[0]), "=r"(r[1]), "=r"(r[2]), "=r"(r[3]) : "r"(addr));
}
__device__ __forceinline__ void mma16816(float* d, const uint32_t* a, const uint32_t* b) {
    asm volatile(
        "mma.sync.aligned.m16n8k16.row.col.f32.bf16.bf16.f32 "
        "{%0,%1,%2,%3}, {%4,%5,%6,%7}, {%8,%9}, {%0,%1,%2,%3};"
        : "+f"(d[0]), "+f"(d[1]), "+f"(d[2]), "+f"(d[3])
        : "r"(a[0]), "r"(a[1]), "r"(a[2]), "r"(a[3]), "r"(b[0]), "r"(b[1]));
}

// ---------------- concat ----------------------------------------------------
__global__ void concat_kernel(const float* __restrict__ key,
                              const float* __restrict__ query,
                              float* __restrict__ x) {
    size_t i = (size_t)blockIdx.x * blockDim.x + threadIdx.x;
    if (i >= (size_t)B_ * 2 * C_ * N_) return;
    int n = (int)(i % N_);
    int c = (int)((i / N_) % (2 * C_));
    int b = (int)(i / ((size_t)N_ * 2 * C_));
    float v;
    if (c < C_) v = key  [((size_t)b * C_ + c) * N_ + n];
    else        v = query[((size_t)b * C_ + (c - C_)) * N_ + n];
    x[i] = v;
}

// ---------------- KNN -------------------------------------------------------
__global__ void knn_kernel(const float* __restrict__ pos, int* __restrict__ idx) {
    const int b = blockIdx.y;
    const int n = blockIdx.x * blockDim.x + threadIdx.x;
    const float* p = pos + (size_t)b * 3 * N_;
    const float qx = p[n], qy = p[N_ + n], qz = p[2 * N_ + n];
    const float qs = qx * qx + qy * qy + qz * qz;
    float bd[K_]; int bi[K_];
#pragma unroll
    for (int j = 0; j < K_; j++) { bd[j] = 3.4e38f; bi[j] = 0; }
    __shared__ float sx[512], sy[512], sz[512], ss[512];
    for (int t0 = 0; t0 < N_; t0 += 512) {
        __syncthreads();
        for (int i = threadIdx.x; i < 512; i += blockDim.x) {
            float x = p[t0 + i], y = p[N_ + t0 + i], z = p[2 * N_ + t0 + i];
            sx[i] = x; sy[i] = y; sz[i] = z; ss[i] = x * x + y * y + z * z;
        }
        __syncthreads();
        for (int i = 0; i < 512; i++) {
            float d = qs + ss[i] - 2.0f * (qx * sx[i] + qy * sy[i] + qz * sz[i]);
            if (d < bd[K_ - 1]) {
                int j = K_ - 1;
                while (j > 0 && d < bd[j - 1]) { bd[j] = bd[j - 1]; bi[j] = bi[j - 1]; j--; }
                bd[j] = d; bi[j] = t0 + i;
            }
        }
    }
    int* op = idx + ((size_t)b * N_ + n) * K_;
#pragma unroll
    for (int j = 0; j < K_; j++) op[j] = bi[j];
}

// ---------------- precompute small products ---------------------------------
__global__ void smallmm_kernel(const float* __restrict__ A, const float* __restrict__ Bm,
                               float* __restrict__ Cc, int O, int Id, int J, int tr) {
    int t = blockIdx.x * 256 + threadIdx.x;
    if (t >= O * J) return;
    int o = t / J, j = t % J;
    float s = 0.0f;
    for (int d = 0; d < Id; d++) s += A[o * Id + d] * Bm[d * J + j];
    if (tr) Cc[j * O + o] = s; else Cc[o * J + j] = s;
}
__global__ void transpose_kernel(const float* __restrict__ Mm, float* __restrict__ T,
                                 int R, int Cc) {
    int t = blockIdx.x * 256 + threadIdx.x;
    if (t >= R * Cc) return;
    int r = t / Cc, c = t % Cc;
    T[c * R + r] = Mm[r * Cc + c];
}
__global__ void bias1_kernel(const float* __restrict__ w1, const float* __restrict__ bq,
                             const float* __restrict__ bk, const float* __restrict__ pb2,
                             const float* __restrict__ ab1, float* __restrict__ out) {
    int o = blockIdx.x * 256 + threadIdx.x;
    if (o >= AH_) return;
    float s = ab1[o];
    for (int d = 0; d < DIM_; d++) s += w1[o * DIM_ + d] * (bq[d] - bk[d] + pb2[d]);
    out[o] = s;
}

// ---------------- att_w2 -> pre-swizzled bf16 hi/lo image --------------------
__global__ void prep_w2_kernel(const float* __restrict__ w2, unsigned int* __restrict__ img) {
    int t = blockIdx.x * 256 + threadIdx.x;   // 65536 = 256 c * 256 k4
    if (t >= 256 * 256) return;
    int c = t >> 8, k4 = t & 255;
    int k = k4 * 4;
    int q = k >> 6, kl = k & 63;
    const float* src = w2 + (size_t)c * AH_ + k;
    float f0 = src[0], f1 = src[1], f2 = src[2], f3 = src[3];
    float h0 = __bfloat162float(__float2bfloat16(f0));
    float h1 = __bfloat162float(__float2bfloat16(f1));
    float h2 = __bfloat162float(__float2bfloat16(f2));
    float h3 = __bfloat162float(__float2bfloat16(f3));
    uint32_t off = SWZ128((uint32_t)((c >> 3) * 1024 + (c & 7) * 128 + kl * 2));
    char* base = (char*)img + (size_t)q * 65536;
    *(uint2*)(base + off) = make_uint2(pack_bf16(f0, f1), pack_bf16(f2, f3));
    *(uint2*)(base + 32768 + off) =
        make_uint2(pack_bf16(f0 - h0, f1 - h1), pack_bf16(f2 - h2, f3 - h3));
}

// ---------------- generic fp32 SGEMM (small GEMMs) --------------------------
template <int FLAGS>
__global__ void sgemm_kernel(const float* __restrict__ W, const float* __restrict__ Xg,
                             const float* __restrict__ bias, float* __restrict__ outg,
                             const float* __restrict__ resg, int O, int I, int M) {
    const int b = blockIdx.z;
    const float* X = Xg + (size_t)b * I * M;
    float* out = outg + (size_t)b * O * M;
    const float* res = (FLAGS & 4) ? (resg + (size_t)b * O * M) : nullptr;
    __shared__ float Ws[8][132];
    __shared__ float Xs[8][128];
    const int tid = threadIdx.x;
    const int tx = tid & 15, ty = tid >> 4;
    const int o0 = blockIdx.y * 128, m0 = blockIdx.x * 128;
    const int wr = tid >> 1, wc = (tid & 1) * 4;
    const int xr = tid >> 5, xc = (tid & 31) * 4;
    float acc[8][8];
#pragma unroll
    for (int i = 0; i < 8; i++)
#pragma unroll
        for (int j = 0; j < 8; j++) acc[i][j] = 0.0f;
    for (int kt = 0; kt < I; kt += 8) {
        float4 wv = *(const float4*)&W[(size_t)(o0 + wr) * I + kt + wc];
        float4 xv = *(const float4*)&X[(size_t)(kt + xr) * M + m0 + xc];
        __syncthreads();
        Ws[wc + 0][wr] = wv.x; Ws[wc + 1][wr] = wv.y;
        Ws[wc + 2][wr] = wv.z; Ws[wc + 3][wr] = wv.w;
        *(float4*)&Xs[xr][xc] = xv;
        __syncthreads();
#pragma unroll
        for (int k = 0; k < 8; k++) {
            float a[8], bb[8];
            *(float4*)&a[0]  = *(const float4*)&Ws[k][ty * 8];
            *(float4*)&a[4]  = *(const float4*)&Ws[k][ty * 8 + 4];
            *(float4*)&bb[0] = *(const float4*)&Xs[k][tx * 8];
            *(float4*)&bb[4] = *(const float4*)&Xs[k][tx * 8 + 4];
#pragma unroll
            for (int i = 0; i < 8; i++)
#pragma unroll
                for (int j = 0; j < 8; j++) acc[i][j] += a[i] * bb[j];
        }
    }
#pragma unroll
    for (int i = 0; i < 8; i++) {
        const int o = o0 + ty * 8 + i;
        const float bv = bias[o];
        float* orow = out + (size_t)o * M + m0 + tx * 8;
        const float* rrow = (FLAGS & 4) ? (res + (size_t)o * M + m0 + tx * 8) : nullptr;
#pragma unroll
        for (int jj = 0; jj < 8; jj += 4) {
            float4 v;
            v.x = acc[i][jj + 0] + bv; v.y = acc[i][jj + 1] + bv;
            v.z = acc[i][jj + 2] + bv; v.w = acc[i][jj + 3] + bv;
            if (FLAGS & 1) { v.x = fmaxf(v.x, 0.f); v.y = fmaxf(v.y, 0.f);
                             v.z = fmaxf(v.z, 0.f); v.w = fmaxf(v.w, 0.f); }
            if (FLAGS & 2) { float4 old = *(float4*)&orow[jj];
                             v.x += old.x; v.y += old.y; v.z += old.z; v.w += old.w; }
            if (FLAGS & 4) { float4 r = *(const float4*)&rrow[jj];
                             v.x += r.x; v.y += r.y; v.z += r.z; v.w += r.w; }
            *(float4*)&orow[jj] = v;
        }
    }
}

// ---------------- pos_rel conv1 + BN partial stats ---------------------------
__global__ void posrel_kernel(const float* __restrict__ pos, const int* __restrict__ idx,
                              const float* __restrict__ w, const float* __restrict__ bias,
                              float* __restrict__ t1, float* __restrict__ part) {
    size_t i = (size_t)blockIdx.x * 256 + threadIdx.x;
    int k = (int)(i & 15);
    int n = (int)((i >> 4) & (N_ - 1));
    int c = (int)((i >> 16) & (PH_ - 1));
    int b = (int)(i >> 22);
    int m = idx[(((size_t)b * N_ + n) << 4) + k];
    const float* p = pos + (size_t)b * 3 * N_;
    float rx = p[n] - p[m];
    float ry = p[N_ + n] - p[N_ + m];
    float rz = p[2 * N_ + n] - p[2 * N_ + m];
    float val = w[c * 3] * rx + w[c * 3 + 1] * ry + w[c * 3 + 2] * rz + bias[c];
    t1[i] = val;
    __shared__ float ssum[256], ssq[256];
    ssum[threadIdx.x] = val; ssq[threadIdx.x] = val * val;
    __syncthreads();
    for (int st = 128; st > 0; st >>= 1) {
        if ((int)threadIdx.x < st) {
            ssum[threadIdx.x] += ssum[threadIdx.x + st];
            ssq[threadIdx.x]  += ssq[threadIdx.x + st];
        }
        __syncthreads();
    }
    if (threadIdx.x == 0) {
        int cb = (blockIdx.x >> 8) & (PH_ - 1);
        int bb = blockIdx.x >> 14;
        int sblk = blockIdx.x & 255;
        size_t o = ((size_t)cb * 512 + bb * 256 + sblk) * 2;
        part[o] = ssum[0]; part[o + 1] = ssq[0];
    }
}

// ---------------- BN finalize ------------------------------------------------
__global__ void finalize_stats(const float* __restrict__ part, int P, int ps, int cs,
                               const float* __restrict__ g, const float* __restrict__ be,
                               float* __restrict__ sc, float* __restrict__ sh, float cnt) {
    int c = blockIdx.x;
    double s = 0.0, q = 0.0;
    for (int p = threadIdx.x; p < P; p += blockDim.x) {
        size_t o = ((size_t)p * ps + (size_t)c * cs) * 2;
        s += (double)part[o]; q += (double)part[o + 1];
    }
    __shared__ double S[256], Q[256];
    S[threadIdx.x] = s; Q[threadIdx.x] = q;
    __syncthreads();
    for (int st = 128; st > 0; st >>= 1) {
        if ((int)threadIdx.x < st) {
            S[threadIdx.x] += S[threadIdx.x + st];
            Q[threadIdx.x] += Q[threadIdx.x + st];
        }
        __syncthreads();
    }
    if (threadIdx.x == 0) {
        double mean = S[0] / (double)cnt;
        double var  = Q[0] / (double)cnt - mean * mean;
        float scv = g[c] * (float)(1.0 / sqrt(var + 1e-5));
        sc[c] = scv;
        sh[c] = be[c] - (float)mean * scv;
    }
}

// ---------------- fused mid: h_t (transposed) + pe + BN partials -------------
__global__ __launch_bounds__(256) void fused_mid_kernel(
    const float* __restrict__ t1, const float* __restrict__ psc,
    const float* __restrict__ psh, const float* __restrict__ A1t,
    const float* __restrict__ posw2t, const float* __restrict__ bias1,
    const float* __restrict__ pos_b2, const float* __restrict__ u,
    const float* __restrict__ v, const int* __restrict__ idx,
    float* __restrict__ ht, float* __restrict__ pe, float* __restrict__ part) {
    extern __shared__ float sm[];
    float (*Xs)[128] = (float(*)[128])sm;
    float (*Ws)[128] = (float(*)[128])(sm + 64 * 128);
    float* redS = (float*)(sm + 64 * 128);
    float* redQ = redS + 128 * 17;
    __shared__ int sidx[128];
    const int tid = threadIdx.x;
    const int tx = tid & 15, ty = tid >> 4;
    const int b = blockIdx.y;
    const int m0 = blockIdx.x * 128;
    const int lr = tid >> 5, lc = (tid & 31) * 4;

#pragma unroll
    for (int it = 0; it < 8; it++) {
        int r = it * 8 + lr;
        float4 vv = *(const float4*)&t1[((size_t)(b * PH_ + r)) * M_ + m0 + lc];
        float s_ = psc[r], h_ = psh[r];
        float4 o;
        o.x = fmaxf(vv.x * s_ + h_, 0.f); o.y = fmaxf(vv.y * s_ + h_, 0.f);
        o.z = fmaxf(vv.z * s_ + h_, 0.f); o.w = fmaxf(vv.w * s_ + h_, 0.f);
        *(float4*)&Xs[r][lc] = o;
    }
    if (tid < 128) sidx[tid] = idx[(((size_t)b * N_ + (m0 >> 4)) << 4) + tid];

    const int nloc = tx >> 1;
    const int khalf = (tx & 1) * 8;
    const int n = (m0 >> 4) + nloc;

    for (int ot = 0; ot < 10; ot++) {
        const float* Wt; int wstr;
        if (ot < 8) { Wt = A1t + ot * 128; wstr = AH_; }
        else        { Wt = posw2t + (ot - 8) * 128; wstr = DIM_; }
        __syncthreads();
#pragma unroll
        for (int it = 0; it < 8; it++) {
            int r = it * 8 + lr;
            *(float4*)&Ws[r][lc] = *(const float4*)&Wt[(size_t)r * wstr + lc];
        }
        __syncthreads();
        float acc[8][8];
#pragma unroll
        for (int i = 0; i < 8; i++)
#pragma unroll
            for (int j = 0; j < 8; j++) acc[i][j] = 0.0f;
#pragma unroll 4
        for (int k = 0; k < 64; k++) {
            float a[8], bb[8];
            *(float4*)&a[0]  = *(const float4*)&Ws[k][ty * 8];
            *(float4*)&a[4]  = *(const float4*)&Ws[k][ty * 8 + 4];
            *(float4*)&bb[0] = *(const float4*)&Xs[k][tx * 8];
            *(float4*)&bb[4] = *(const float4*)&Xs[k][tx * 8 + 4];
#pragma unroll
            for (int i = 0; i < 8; i++)
#pragma unroll
                for (int j = 0; j < 8; j++) acc[i][j] += a[i] * bb[j];
        }
        __syncthreads();
        if (ot < 8) {
            float uval[8];
#pragma unroll
            for (int i = 0; i < 8; i++) {
                int c = ot * 128 + ty * 8 + i;
                uval[i] = u[((size_t)b * AH_ + c) * N_ + n] + bias1[c];
            }
            const float* vbase = v + ((size_t)b * AH_ + ot * 128 + ty * 8) * N_;
            float sI[8], qI[8];
#pragma unroll
            for (int i = 0; i < 8; i++) { sI[i] = 0.f; qI[i] = 0.f; }
#pragma unroll
            for (int j = 0; j < 8; j++) {
                int sj = sidx[nloc * 16 + khalf + j];
                float w[8];
#pragma unroll
                for (int i = 0; i < 8; i++) {
                    float val = acc[i][j] + uval[i] - vbase[(size_t)i * N_ + sj];
                    w[i] = val; sI[i] += val; qI[i] += val * val;
                }
                float* hd = ht + ((size_t)(b * M_ + m0 + tx * 8 + j)) * AH_ + ot * 128 + ty * 8;
                *(float4*)hd       = make_float4(w[0], w[1], w[2], w[3]);
                *(float4*)(hd + 4) = make_float4(w[4], w[5], w[6], w[7]);
            }
#pragma unroll
            for (int i = 0; i < 8; i++) {
                int cl = ty * 8 + i;
                redS[cl * 17 + tx] = sI[i]; redQ[cl * 17 + tx] = qI[i];
            }
            __syncthreads();
            if (tid < 128) {
                float s = 0.f, q = 0.f;
#pragma unroll
                for (int t = 0; t < 16; t++) { s += redS[tid * 17 + t]; q += redQ[tid * 17 + t]; }
                size_t p = (((size_t)b * (M_ / 128) + blockIdx.x) * AH_ + ot * 128 + tid) * 2;
                part[p] = s; part[p + 1] = q;
            }
        } else {
#pragma unroll
            for (int i = 0; i < 8; i++) {
                int c = (ot - 8) * 128 + ty * 8 + i;
                float bv = pos_b2[c];
                float* pd = pe + ((size_t)b * DIM_ + c) * M_ + m0 + tx * 8;
                *(float4*)pd       = make_float4(acc[i][0] + bv, acc[i][1] + bv,
                                                 acc[i][2] + bv, acc[i][3] + bv);
                *(float4*)(pd + 4) = make_float4(acc[i][4] + bv, acc[i][5] + bv,
                                                 acc[i][6] + bv, acc[i][7] + bv);
            }
        }
    }
}

// ---------------- attn GEMM2 (HMMA split-bf16) + softmax + aggregation -------
// D[m=128][c=256] = sum_k bnrelu(h_t[m][k]) * att_w2[c][k]  (K=1024, chunks of 64)
// smem stage: A_hi 16K | A_lo 16K | B_hi 32K | B_lo 32K = 96K, double buffered.
#define STG_STRIDE 98304
__device__ __forceinline__ void attn2_fill(char* smc, int stage, int cq,
                                           const float* hbase, const uint4* w2img,
                                           const float* Ssm, const float* Shm, int tid) {
    char* stg = smc + stage * STG_STRIDE;
#pragma unroll
    for (int it = 0; it < 8; it++) {
        int task = it * 256 + tid;
        int m = task >> 4, kq = task & 15;
        int kc = cq * 64 + kq * 4;
        float4 hv = *(const float4*)(hbase + (size_t)m * AH_ + kc);
        float4 sv = *(const float4*)&Ssm[kc];
        float4 tv = *(const float4*)&Shm[kc];
        float x0 = fmaxf(hv.x * sv.x + tv.x, 0.f);
        float x1 = fmaxf(hv.y * sv.y + tv.y, 0.f);
        float x2 = fmaxf(hv.z * sv.z + tv.z, 0.f);
        float x3 = fmaxf(hv.w * sv.w + tv.w, 0.f);
        float r0 = __bfloat162float(__float2bfloat16(x0));
        float r1 = __bfloat162float(__float2bfloat16(x1));
        float r2 = __bfloat162float(__float2bfloat16(x2));
        float r3 = __bfloat162float(__float2bfloat16(x3));
        uint32_t off = (uint32_t)((m >> 3) * 1024 + (m & 7) * 128 +
                                  ((kq * 8) ^ (((uint32_t)(m & 7)) << 4)));
        *(uint2*)(stg + off) = make_uint2(pack_bf16(x0, x1), pack_bf16(x2, x3));
        *(uint2*)(stg + 16384 + off) =
            make_uint2(pack_bf16(x0 - r0, x1 - r1), pack_bf16(x2 - r2, x3 - r3));
    }
    const uint4* src = w2img + (size_t)cq * 4096;
    uint4* dh = (uint4*)(stg + 32768);
    uint4* dl = (uint4*)(stg + 65536);
#pragma unroll
    for (int it = 0; it < 8; it++) {
        int i = it * 256 + tid;
        dh[i] = src[i];
        dl[i] = src[2048 + i];
    }
}

__global__ __launch_bounds__(256, 1) void attn2_hmma_kernel(
    const uint4* __restrict__ w2img, const float* __restrict__ ht,
    const float* __restrict__ scale, const float* __restrict__ shift,
    const float* __restrict__ pe, const float* __restrict__ vf,
    float* __restrict__ agg) {
    extern __shared__ char smc[];
    __shared__ float Ssm[AH_], Shm[AH_];
    const int tid = threadIdx.x, lane = tid & 31, wid = tid >> 5;
    const int b = blockIdx.y, m0 = blockIdx.x * 128;
    const int warp_m = wid >> 2, warp_c = wid & 3;   // 2 x 4 warp grid, 64x64 tiles

    for (int i = tid; i < AH_; i += 256) { Ssm[i] = scale[i]; Shm[i] = shift[i]; }
    __syncthreads();

    const float* hbase = ht + ((size_t)(b * M_ + m0)) * AH_;

    float acc[4][8][4];
#pragma unroll
    for (int mt = 0; mt < 4; mt++)
#pragma unroll
        for (int nt = 0; nt < 8; nt++)
#pragma unroll
            for (int j = 0; j < 4; j++) acc[mt][nt][j] = 0.0f;

    // ldmatrix per-lane geometry
    const int g = lane >> 3, lr = lane & 7;
    const int amr  = warp_m * 64 + (g & 1) * 8 + lr;   // + mt*16
    const int bcr  = warp_c * 64 + (g >> 1) * 8 + lr;  // + np*16
    const int akb0 = (g >> 1) * 16;
    const int bkb0 = (g & 1) * 16;

    for (int cq = 0; cq < 16; cq++) {
        const int s = cq & 1;
        if (cq == 0) { attn2_fill(smc, 0, 0, hbase, w2img, Ssm, Shm, tid); __syncthreads(); }
        if (cq + 1 < 16) attn2_fill(smc, s ^ 1, cq + 1, hbase, w2img, Ssm, Shm, tid);

        const uint32_t sA = smem_u32(smc) + s * STG_STRIDE;
        const uint32_t sB = sA + 32768;
#pragma unroll
        for (int ks = 0; ks < 4; ks++) {
            uint32_t Ahi[4][4], Alo[4][4], Bhi[4][4], Blo[4][4];
#pragma unroll
            for (int mt = 0; mt < 4; mt++) {
                int m = amr + mt * 16;
                uint32_t ro = (uint32_t)((m >> 3) * 1024 + (m & 7) * 128);
                uint32_t kb = (uint32_t)((ks * 32 + akb0) ^ ((m & 7) << 4));
                ldm_x4(Ahi[mt], sA + ro + kb);
                ldm_x4(Alo[mt], sA + 16384 + ro + kb);
            }
#pragma unroll
            for (int np = 0; np < 4; np++) {
                int c = bcr + np * 16;
                uint32_t ro = (uint32_t)((c >> 3) * 1024 + (c & 7) * 128);
                uint32_t kb = (uint32_t)((ks * 32 + bkb0) ^ ((c & 7) << 4));
                ldm_x4(Bhi[np], sB + ro + kb);
                ldm_x4(Blo[np], sB + 32768 + ro + kb);
            }
#pragma unroll
            for (int mt = 0; mt < 4; mt++)
#pragma unroll
                for (int np = 0; np < 4; np++) {
                    mma16816(acc[mt][np * 2],     Ahi[mt], &Bhi[np][0]);
                    mma16816(acc[mt][np * 2],     Alo[mt], &Bhi[np][0]);
                    mma16816(acc[mt][np * 2],     Ahi[mt], &Blo[np][0]);
                    mma16816(acc[mt][np * 2 + 1], Ahi[mt], &Bhi[np][2]);
                    mma16816(acc[mt][np * 2 + 1], Alo[mt], &Bhi[np][2]);
                    mma16816(acc[mt][np * 2 + 1], Ahi[mt], &Blo[np][2]);
                }
        }
        __syncthreads();
    }

    // ---- epilogue: stage pe tile (c=256 rows x m=128 cols, stride 132) ----
    float* pes = (float*)smc;
    for (int i = tid; i < 256 * 32; i += 256) {
        int row = i >> 5, q = i & 31;
        float4 v = *(const float4*)(pe + ((size_t)(b * DIM_ + row)) * M_ + m0 + q * 4);
        *(float4*)&pes[row * 132 + q * 4] = v;
    }
    __syncthreads();

#pragma unroll
    for (int mt = 0; mt < 4; mt++) {
        const int mbase = warp_m * 64 + mt * 16;
        const int n = (m0 + mbase) >> 4;
        const int r = lane >> 2;
#pragma unroll
        for (int nt = 0; nt < 8; nt++) {
#pragma unroll
            for (int j = 0; j < 2; j++) {
                int c = warp_c * 64 + nt * 8 + (lane & 3) * 2 + j;
                float v0 = acc[mt][nt][j], v1 = acc[mt][nt][2 + j];
                float mx = fmaxf(v0, v1);
                mx = fmaxf(mx, __shfl_xor_sync(0xffffffffu, mx, 4));
                mx = fmaxf(mx, __shfl_xor_sync(0xffffffffu, mx, 8));
                mx = fmaxf(mx, __shfl_xor_sync(0xffffffffu, mx, 16));
                float e0 = __expf(v0 - mx), e1 = __expf(v1 - mx);
                float se = e0 + e1;
                se += __shfl_xor_sync(0xffffffffu, se, 4);
                se += __shfl_xor_sync(0xffffffffu, se, 8);
                se += __shfl_xor_sync(0xffffffffu, se, 16);
                float p0 = pes[c * 132 + mbase + r];
                float p1 = pes[c * 132 + mbase + r + 8];
                float t = e0 * p0 + e1 * p1;
                t += __shfl_xor_sync(0xffffffffu, t, 4);
                t += __shfl_xor_sync(0xffffffffu, t, 8);
                t += __shfl_xor_sync(0xffffffffu, t, 16);
                if (r == 0) {
                    size_t o = ((size_t)(b * DIM_ + c)) * N_ + n;
                    agg[o] = vf[o] + t / se;
                }
            }
        }
    }
}

// ---------------- launch ----------------------------------------------------
extern "C" void kernel_launch(void* const* d_in, const int* in_sizes, int n_in,
                              void* d_out, int out_size) {
    const float* pos     = (const float*)d_in[0];
    const float* key     = (const float*)d_in[1];
    const float* query   = (const float*)d_in[2];
    const float* mlpv_w1 = (const float*)d_in[3];
    const float* mlpv_b1 = (const float*)d_in[4];
    const float* mlpv_w2 = (const float*)d_in[5];
    const float* mlpv_b2 = (const float*)d_in[6];
    const float* mlpv_ws = (const float*)d_in[7];
    const float* mlpv_bs = (const float*)d_in[8];
    const float* wk      = (const float*)d_in[9];
    const float* bk      = (const float*)d_in[10];
    const float* wq      = (const float*)d_in[11];
    const float* bq      = (const float*)d_in[12];
    const float* wv      = (const float*)d_in[13];
    const float* bv      = (const float*)d_in[14];
    const float* pos_w1  = (const float*)d_in[15];
    const float* pos_b1  = (const float*)d_in[16];
    const float* pos_g1  = (const float*)d_in[17];
    const float* pos_be1 = (const float*)d_in[18];
    const float* pos_w2  = (const float*)d_in[19];
    const float* pos_b2  = (const float*)d_in[20];
    const float* att_w1  = (const float*)d_in[21];
    const float* att_b1  = (const float*)d_in[22];
    const float* att_g1  = (const float*)d_in[23];
    const float* att_be1 = (const float*)d_in[24];
    const float* att_w2  = (const float*)d_in[25];
    const float* we      = (const float*)d_in[27];
    const float* be      = (const float*)d_in[28];
    float* out = (float*)d_out;

    void* p;
#define GETP(sym, var) cudaGetSymbolAddress(&p, sym); float* var = (float*)p;
    GETP(g_x, x_)       GETP(g_t, t_)       GETP(g_value, val)
    GETP(g_vf, vf_)     GETP(g_u, u_)       GETP(g_v, v_)
    GETP(g_t1, t1_)     GETP(g_pe, pe_)     GETP(g_h, ht_)
    GETP(g_agg, agg)    GETP(g_part, part)  GETP(g_partp, partp)
    GETP(g_Wuq, Wuq)    GETP(g_Wvk, Wvk)    GETP(g_A1t, A1t)
    GETP(g_posw2t, posw2t) GETP(g_bias1, bias1)
    GETP(g_scp, scp)    GETP(g_shp, shp)    GETP(g_sca, sca)
    GETP(g_sha, sha)    GETP(g_zero, zero)
#undef GETP
    cudaGetSymbolAddress(&p, g_idx);   int* idx = (int*)p;
    cudaGetSymbolAddress(&p, g_w2img); unsigned int* w2img = (unsigned int*)p;

    // --- precompute folded weights + w2 bf16 image ---
    smallmm_kernel<<<(AH_ * C_ + 255) / 256, 256>>>(att_w1, wq, Wuq, AH_, DIM_, C_, 0);
    smallmm_kernel<<<(AH_ * C_ + 255) / 256, 256>>>(att_w1, wk, Wvk, AH_, DIM_, C_, 0);
    smallmm_kernel<<<(AH_ * PH_ + 255) / 256, 256>>>(att_w1, pos_w2, A1t, AH_, DIM_, PH_, 1);
    transpose_kernel<<<(DIM_ * PH_ + 255) / 256, 256>>>(pos_w2, posw2t, DIM_, PH_);
    bias1_kernel<<<(AH_ + 255) / 256, 256>>>(att_w1, bq, bk, pos_b2, att_b1, bias1);
    prep_w2_kernel<<<(256 * 256) / 256, 256>>>(att_w2, w2img);

    // --- front end ---
    concat_kernel<<<(unsigned)(((size_t)B_ * 2 * C_ * N_ + 255) / 256), 256>>>(key, query, x_);
    knn_kernel<<<dim3(N_ / 256, B_), 256>>>(pos, idx);
    sgemm_kernel<1><<<dim3(N_ / 128, C_ / 128, B_), 256>>>(mlpv_w1, x_, mlpv_b1, t_, nullptr, C_, 2 * C_, N_);
    sgemm_kernel<0><<<dim3(N_ / 128, C_ / 128, B_), 256>>>(mlpv_w2, t_, mlpv_b2, val, nullptr, C_, C_, N_);
    sgemm_kernel<2><<<dim3(N_ / 128, C_ / 128, B_), 256>>>(mlpv_ws, x_, mlpv_bs, val, nullptr, C_, 2 * C_, N_);
    sgemm_kernel<0><<<dim3(N_ / 128, DIM_ / 128, B_), 256>>>(wv, val, bv, vf_, nullptr, DIM_, C_, N_);
    sgemm_kernel<0><<<dim3(N_ / 128, AH_ / 128, B_), 256>>>(Wuq, query, zero, u_, nullptr, AH_, C_, N_);
    sgemm_kernel<0><<<dim3(N_ / 128, AH_ / 128, B_), 256>>>(Wvk, key, zero, v_, nullptr, AH_, C_, N_);

    // --- pos_rel conv1 + pos BN ---
    posrel_kernel<<<(unsigned)(((size_t)B_ * PH_ * M_) / 256), 256>>>(pos, idx, pos_w1, pos_b1, t1_, partp);
    finalize_stats<<<PH_, 256>>>(partp, 512, 1, 512, pos_g1, pos_be1, scp, shp, (float)((size_t)B_ * M_));

    // --- fused mid: h_t + pe (+ attn BN partials) ---
    cudaFuncSetAttribute(fused_mid_kernel, cudaFuncAttributeMaxDynamicSharedMemorySize, 65536);
    fused_mid_kernel<<<dim3(M_ / 128, B_), 256, 65536>>>(
        t1_, scp, shp, A1t, posw2t, bias1, pos_b2, u_, v_, idx, ht_, pe_, part);
    finalize_stats<<<AH_, 256>>>(part, B_ * (M_ / 128), AH_, 1, att_g1, att_be1, sca, sha, (float)((size_t)B_ * M_));

    // --- big GEMM2 on HMMA tensor path + softmax + aggregation ---
    cudaFuncSetAttribute(attn2_hmma_kernel, cudaFuncAttributeMaxDynamicSharedMemorySize, 2 * STG_STRIDE);
    attn2_hmma_kernel<<<dim3(M_ / 128, B_), 256, 2 * STG_STRIDE>>>(
        (const uint4*)w2img, ht_, sca, sha, pe_, vf_, agg);

    // --- final projection + residual ---
    sgemm_kernel<4><<<dim3(N_ / 128, C_ / 128, B_), 256>>>(we, agg, be, out, val, C_, DIM_, N_);
}

// round 6
// speedup vs baseline: 1.7942x; 1.0103x over previous
#include <cuda_runtime.h>
#include <cuda_bf16.h>
#include <math.h>
#include <stdint.h>

#define B_   2
#define C_   128
#define N_   4096
#define K_   16
#define DIM_ 256
#define PH_  64
#define AH_  1024
#define M_   (N_ * K_)          // 65536 columns per batch in (n,k) space

// ---------------- scratch ---------------------------------------------------
__device__ float g_x    [(size_t)B_ * 2 * C_ * N_];
__device__ float g_t    [(size_t)B_ * C_ * N_];
__device__ float g_value[(size_t)B_ * C_ * N_];
__device__ float g_vf   [(size_t)B_ * DIM_ * N_];
__device__ float g_u    [(size_t)B_ * AH_ * N_];
__device__ float g_v    [(size_t)B_ * AH_ * N_];
__device__ int   g_idx  [(size_t)B_ * N_ * K_];
__device__ float g_t1   [(size_t)B_ * PH_ * M_];
__device__ float g_pe   [(size_t)B_ * DIM_ * M_];
__device__ float g_h    [(size_t)B_ * AH_ * M_];       // h: [B][AH][M]  (c-major)
__device__ float g_agg  [(size_t)B_ * DIM_ * N_];
__device__ float g_part [(size_t)B_ * (M_/128) * AH_ * 2];
__device__ float g_partp[(size_t)PH_ * 512 * 2];
__device__ float g_Wuq  [AH_ * C_];
__device__ float g_Wvk  [AH_ * C_];
__device__ float g_A1t  [PH_ * AH_];
__device__ float g_posw2t[PH_ * DIM_];
__device__ float g_bias1[AH_];
__device__ float g_scp  [PH_];
__device__ float g_shp  [PH_];
__device__ float g_sca  [AH_];
__device__ float g_sha  [AH_];
__device__ float g_zero [AH_];
// pre-swizzled bf16 image of att_w2: 16 K-chunks x (hi 32KB + lo 32KB) = 1MB
__device__ unsigned int g_w2img[16 * 65536 / 4];

// ---------------- helpers ---------------------------------------------------
__device__ __forceinline__ uint32_t smem_u32(const void* p) {
    uint32_t a;
    asm("{ .reg .u64 t; cvta.to.shared.u64 t, %1; cvt.u32.u64 %0, t; }" : "=r"(a) : "l"(p));
    return a;
}
#define SWZ128(b) ((b) ^ (((b) >> 3) & 0x70))
__device__ __forceinline__ uint32_t pack_bf16(float a, float b) {
    __nv_bfloat16 ha = __float2bfloat16(a), hb = __float2bfloat16(b);
    return (uint32_t)__bfloat16_as_ushort(ha) |
           ((uint32_t)__bfloat16_as_ushort(hb) << 16);
}
__device__ __forceinline__ void ldm_x4(uint32_t* r, uint32_t addr) {
    asm volatile("ldmatrix.sync.aligned.m8n8.x4.shared.b16 {%0,%1,%2,%3}, [%4];"
        : "=r"(r[0]), "=r"(r[1]), "=r"(r[2]), "=r"(r[3]) : "r"(addr));
}
__device__ __forceinline__ void mma16816(float* d, const uint32_t* a, const uint32_t* b) {
    asm volatile(
        "mma.sync.aligned.m16n8k16.row.col.f32.bf16.bf16.f32 "
        "{%0,%1,%2,%3}, {%4,%5,%6,%7}, {%8,%9}, {%0,%1,%2,%3};"
        : "+f"(d[0]), "+f"(d[1]), "+f"(d[2]), "+f"(d[3])
        : "r"(a[0]), "r"(a[1]), "r"(a[2]), "r"(a[3]), "r"(b[0]), "r"(b[1]));
}
__device__ __forceinline__ void cp_async16(uint32_t dst, const void* src) {
    asm volatile("cp.async.cg.shared.global [%0], [%1], 16;" :: "r"(dst), "l"(src));
}
#define CP_COMMIT() asm volatile("cp.async.commit_group;" ::: "memory")
#define CP_WAIT0()  asm volatile("cp.async.wait_group 0;" ::: "memory")

// ---------------- concat ----------------------------------------------------
__global__ void concat_kernel(const float* __restrict__ key,
                              const float* __restrict__ query,
                              float* __restrict__ x) {
    size_t i = (size_t)blockIdx.x * blockDim.x + threadIdx.x;
    if (i >= (size_t)B_ * 2 * C_ * N_) return;
    int n = (int)(i % N_);
    int c = (int)((i / N_) % (2 * C_));
    int b = (int)(i / ((size_t)N_ * 2 * C_));
    float v;
    if (c < C_) v = key  [((size_t)b * C_ + c) * N_ + n];
    else        v = query[((size_t)b * C_ + (c - C_)) * N_ + n];
    x[i] = v;
}

// ---------------- KNN -------------------------------------------------------
__global__ void knn_kernel(const float* __restrict__ pos, int* __restrict__ idx) {
    const int b = blockIdx.y;
    const int n = blockIdx.x * blockDim.x + threadIdx.x;
    const float* p = pos + (size_t)b * 3 * N_;
    const float qx = p[n], qy = p[N_ + n], qz = p[2 * N_ + n];
    const float qs = qx * qx + qy * qy + qz * qz;
    float bd[K_]; int bi[K_];
#pragma unroll
    for (int j = 0; j < K_; j++) { bd[j] = 3.4e38f; bi[j] = 0; }
    __shared__ float sx[512], sy[512], sz[512], ss[512];
    for (int t0 = 0; t0 < N_; t0 += 512) {
        __syncthreads();
        for (int i = threadIdx.x; i < 512; i += blockDim.x) {
            float x = p[t0 + i], y = p[N_ + t0 + i], z = p[2 * N_ + t0 + i];
            sx[i] = x; sy[i] = y; sz[i] = z; ss[i] = x * x + y * y + z * z;
        }
        __syncthreads();
        for (int i = 0; i < 512; i++) {
            float d = qs + ss[i] - 2.0f * (qx * sx[i] + qy * sy[i] + qz * sz[i]);
            if (d < bd[K_ - 1]) {
                int j = K_ - 1;
                while (j > 0 && d < bd[j - 1]) { bd[j] = bd[j - 1]; bi[j] = bi[j - 1]; j--; }
                bd[j] = d; bi[j] = t0 + i;
            }
        }
    }
    int* op = idx + ((size_t)b * N_ + n) * K_;
#pragma unroll
    for (int j = 0; j < K_; j++) op[j] = bi[j];
}

// ---------------- precompute small products ---------------------------------
__global__ void smallmm_kernel(const float* __restrict__ A, const float* __restrict__ Bm,
                               float* __restrict__ Cc, int O, int Id, int J, int tr) {
    int t = blockIdx.x * 256 + threadIdx.x;
    if (t >= O * J) return;
    int o = t / J, j = t % J;
    float s = 0.0f;
    for (int d = 0; d < Id; d++) s += A[o * Id + d] * Bm[d * J + j];
    if (tr) Cc[j * O + o] = s; else Cc[o * J + j] = s;
}
__global__ void transpose_kernel(const float* __restrict__ Mm, float* __restrict__ T,
                                 int R, int Cc) {
    int t = blockIdx.x * 256 + threadIdx.x;
    if (t >= R * Cc) return;
    int r = t / Cc, c = t % Cc;
    T[c * R + r] = Mm[r * Cc + c];
}
__global__ void bias1_kernel(const float* __restrict__ w1, const float* __restrict__ bq,
                             const float* __restrict__ bk, const float* __restrict__ pb2,
                             const float* __restrict__ ab1, float* __restrict__ out) {
    int o = blockIdx.x * 256 + threadIdx.x;
    if (o >= AH_) return;
    float s = ab1[o];
    for (int d = 0; d < DIM_; d++) s += w1[o * DIM_ + d] * (bq[d] - bk[d] + pb2[d]);
    out[o] = s;
}

// ---------------- att_w2 -> pre-swizzled bf16 hi/lo image --------------------
__global__ void prep_w2_kernel(const float* __restrict__ w2, unsigned int* __restrict__ img) {
    int t = blockIdx.x * 256 + threadIdx.x;   // 65536 = 256 c * 256 k4
    if (t >= 256 * 256) return;
    int c = t >> 8, k4 = t & 255;
    int k = k4 * 4;
    int q = k >> 6, kl = k & 63;
    const float* src = w2 + (size_t)c * AH_ + k;
    float f0 = src[0], f1 = src[1], f2 = src[2], f3 = src[3];
    float h0 = __bfloat162float(__float2bfloat16(f0));
    float h1 = __bfloat162float(__float2bfloat16(f1));
    float h2 = __bfloat162float(__float2bfloat16(f2));
    float h3 = __bfloat162float(__float2bfloat16(f3));
    uint32_t off = SWZ128((uint32_t)((c >> 3) * 1024 + (c & 7) * 128 + kl * 2));
    char* base = (char*)img + (size_t)q * 65536;
    *(uint2*)(base + off) = make_uint2(pack_bf16(f0, f1), pack_bf16(f2, f3));
    *(uint2*)(base + 32768 + off) =
        make_uint2(pack_bf16(f0 - h0, f1 - h1), pack_bf16(f2 - h2, f3 - h3));
}

// ---------------- generic fp32 SGEMM (small GEMMs) --------------------------
template <int FLAGS>
__global__ void sgemm_kernel(const float* __restrict__ W, const float* __restrict__ Xg,
                             const float* __restrict__ bias, float* __restrict__ outg,
                             const float* __restrict__ resg, int O, int I, int M) {
    const int b = blockIdx.z;
    const float* X = Xg + (size_t)b * I * M;
    float* out = outg + (size_t)b * O * M;
    const float* res = (FLAGS & 4) ? (resg + (size_t)b * O * M) : nullptr;
    __shared__ float Ws[8][132];
    __shared__ float Xs[8][128];
    const int tid = threadIdx.x;
    const int tx = tid & 15, ty = tid >> 4;
    const int o0 = blockIdx.y * 128, m0 = blockIdx.x * 128;
    const int wr = tid >> 1, wc = (tid & 1) * 4;
    const int xr = tid >> 5, xc = (tid & 31) * 4;
    float acc[8][8];
#pragma unroll
    for (int i = 0; i < 8; i++)
#pragma unroll
        for (int j = 0; j < 8; j++) acc[i][j] = 0.0f;
    for (int kt = 0; kt < I; kt += 8) {
        float4 wv = *(const float4*)&W[(size_t)(o0 + wr) * I + kt + wc];
        float4 xv = *(const float4*)&X[(size_t)(kt + xr) * M + m0 + xc];
        __syncthreads();
        Ws[wc + 0][wr] = wv.x; Ws[wc + 1][wr] = wv.y;
        Ws[wc + 2][wr] = wv.z; Ws[wc + 3][wr] = wv.w;
        *(float4*)&Xs[xr][xc] = xv;
        __syncthreads();
#pragma unroll
        for (int k = 0; k < 8; k++) {
            float a[8], bb[8];
            *(float4*)&a[0]  = *(const float4*)&Ws[k][ty * 8];
            *(float4*)&a[4]  = *(const float4*)&Ws[k][ty * 8 + 4];
            *(float4*)&bb[0] = *(const float4*)&Xs[k][tx * 8];
            *(float4*)&bb[4] = *(const float4*)&Xs[k][tx * 8 + 4];
#pragma unroll
            for (int i = 0; i < 8; i++)
#pragma unroll
                for (int j = 0; j < 8; j++) acc[i][j] += a[i] * bb[j];
        }
    }
#pragma unroll
    for (int i = 0; i < 8; i++) {
        const int o = o0 + ty * 8 + i;
        const float bv = bias[o];
        float* orow = out + (size_t)o * M + m0 + tx * 8;
        const float* rrow = (FLAGS & 4) ? (res + (size_t)o * M + m0 + tx * 8) : nullptr;
#pragma unroll
        for (int jj = 0; jj < 8; jj += 4) {
            float4 v;
            v.x = acc[i][jj + 0] + bv; v.y = acc[i][jj + 1] + bv;
            v.z = acc[i][jj + 2] + bv; v.w = acc[i][jj + 3] + bv;
            if (FLAGS & 1) { v.x = fmaxf(v.x, 0.f); v.y = fmaxf(v.y, 0.f);
                             v.z = fmaxf(v.z, 0.f); v.w = fmaxf(v.w, 0.f); }
            if (FLAGS & 2) { float4 old = *(float4*)&orow[jj];
                             v.x += old.x; v.y += old.y; v.z += old.z; v.w += old.w; }
            if (FLAGS & 4) { float4 r = *(const float4*)&rrow[jj];
                             v.x += r.x; v.y += r.y; v.z += r.z; v.w += r.w; }
            *(float4*)&orow[jj] = v;
        }
    }
}

// ---------------- pos_rel conv1 + BN partial stats ---------------------------
__global__ void posrel_kernel(const float* __restrict__ pos, const int* __restrict__ idx,
                              const float* __restrict__ w, const float* __restrict__ bias,
                              float* __restrict__ t1, float* __restrict__ part) {
    size_t i = (size_t)blockIdx.x * 256 + threadIdx.x;
    int k = (int)(i & 15);
    int n = (int)((i >> 4) & (N_ - 1));
    int c = (int)((i >> 16) & (PH_ - 1));
    int b = (int)(i >> 22);
    int m = idx[(((size_t)b * N_ + n) << 4) + k];
    const float* p = pos + (size_t)b * 3 * N_;
    float rx = p[n] - p[m];
    float ry = p[N_ + n] - p[N_ + m];
    float rz = p[2 * N_ + n] - p[2 * N_ + m];
    float val = w[c * 3] * rx + w[c * 3 + 1] * ry + w[c * 3 + 2] * rz + bias[c];
    t1[i] = val;
    __shared__ float ssum[256], ssq[256];
    ssum[threadIdx.x] = val; ssq[threadIdx.x] = val * val;
    __syncthreads();
    for (int st = 128; st > 0; st >>= 1) {
        if ((int)threadIdx.x < st) {
            ssum[threadIdx.x] += ssum[threadIdx.x + st];
            ssq[threadIdx.x]  += ssq[threadIdx.x + st];
        }
        __syncthreads();
    }
    if (threadIdx.x == 0) {
        int cb = (blockIdx.x >> 8) & (PH_ - 1);
        int bb = blockIdx.x >> 14;
        int sblk = blockIdx.x & 255;
        size_t o = ((size_t)cb * 512 + bb * 256 + sblk) * 2;
        part[o] = ssum[0]; part[o + 1] = ssq[0];
    }
}

// ---------------- BN finalize ------------------------------------------------
__global__ void finalize_stats(const float* __restrict__ part, int P, int ps, int cs,
                               const float* __restrict__ g, const float* __restrict__ be,
                               float* __restrict__ sc, float* __restrict__ sh, float cnt) {
    int c = blockIdx.x;
    double s = 0.0, q = 0.0;
    for (int p = threadIdx.x; p < P; p += blockDim.x) {
        size_t o = ((size_t)p * ps + (size_t)c * cs) * 2;
        s += (double)part[o]; q += (double)part[o + 1];
    }
    __shared__ double S[256], Q[256];
    S[threadIdx.x] = s; Q[threadIdx.x] = q;
    __syncthreads();
    for (int st = 128; st > 0; st >>= 1) {
        if ((int)threadIdx.x < st) {
            S[threadIdx.x] += S[threadIdx.x + st];
            Q[threadIdx.x] += Q[threadIdx.x + st];
        }
        __syncthreads();
    }
    if (threadIdx.x == 0) {
        double mean = S[0] / (double)cnt;
        double var  = Q[0] / (double)cnt - mean * mean;
        float scv = g[c] * (float)(1.0 / sqrt(var + 1e-5));
        sc[c] = scv;
        sh[c] = be[c] - (float)mean * scv;
    }
}

// ---------------- fused mid: h (c-major) + pe + BN partials ------------------
__global__ __launch_bounds__(256) void fused_mid_kernel(
    const float* __restrict__ t1, const float* __restrict__ psc,
    const float* __restrict__ psh, const float* __restrict__ A1t,
    const float* __restrict__ posw2t, const float* __restrict__ bias1,
    const float* __restrict__ pos_b2, const float* __restrict__ u,
    const float* __restrict__ v, const int* __restrict__ idx,
    float* __restrict__ h, float* __restrict__ pe, float* __restrict__ part) {
    extern __shared__ float sm[];
    float (*Xs)[128] = (float(*)[128])sm;
    float (*Ws)[128] = (float(*)[128])(sm + 64 * 128);
    float* redS = (float*)(sm + 64 * 128);
    float* redQ = redS + 128 * 17;
    __shared__ int sidx[128];
    const int tid = threadIdx.x;
    const int tx = tid & 15, ty = tid >> 4;
    const int b = blockIdx.y;
    const int m0 = blockIdx.x * 128;
    const int lr = tid >> 5, lc = (tid & 31) * 4;

#pragma unroll
    for (int it = 0; it < 8; it++) {
        int r = it * 8 + lr;
        float4 vv = *(const float4*)&t1[((size_t)(b * PH_ + r)) * M_ + m0 + lc];
        float s_ = psc[r], h_ = psh[r];
        float4 o;
        o.x = fmaxf(vv.x * s_ + h_, 0.f); o.y = fmaxf(vv.y * s_ + h_, 0.f);
        o.z = fmaxf(vv.z * s_ + h_, 0.f); o.w = fmaxf(vv.w * s_ + h_, 0.f);
        *(float4*)&Xs[r][lc] = o;
    }
    if (tid < 128) sidx[tid] = idx[(((size_t)b * N_ + (m0 >> 4)) << 4) + tid];

    const int nloc = tx >> 1;
    const int khalf = (tx & 1) * 8;
    const int n = (m0 >> 4) + nloc;

    for (int ot = 0; ot < 10; ot++) {
        const float* Wt; int wstr;
        if (ot < 8) { Wt = A1t + ot * 128; wstr = AH_; }
        else        { Wt = posw2t + (ot - 8) * 128; wstr = DIM_; }
        __syncthreads();
#pragma unroll
        for (int it = 0; it < 8; it++) {
            int r = it * 8 + lr;
            *(float4*)&Ws[r][lc] = *(const float4*)&Wt[(size_t)r * wstr + lc];
        }
        __syncthreads();
        float acc[8][8];
#pragma unroll
        for (int i = 0; i < 8; i++)
#pragma unroll
            for (int j = 0; j < 8; j++) acc[i][j] = 0.0f;
#pragma unroll 4
        for (int k = 0; k < 64; k++) {
            float a[8], bb[8];
            *(float4*)&a[0]  = *(const float4*)&Ws[k][ty * 8];
            *(float4*)&a[4]  = *(const float4*)&Ws[k][ty * 8 + 4];
            *(float4*)&bb[0] = *(const float4*)&Xs[k][tx * 8];
            *(float4*)&bb[4] = *(const float4*)&Xs[k][tx * 8 + 4];
#pragma unroll
            for (int i = 0; i < 8; i++)
#pragma unroll
                for (int j = 0; j < 8; j++) acc[i][j] += a[i] * bb[j];
        }
        __syncthreads();
        if (ot < 8) {
#pragma unroll
            for (int i = 0; i < 8; i++) {
                int cl = ty * 8 + i;
                int c = ot * 128 + cl;
                size_t crow = (size_t)b * AH_ + c;
                float uval = u[crow * N_ + n] + bias1[c];
                const float* vrow = v + crow * N_;
                float hv[8]; float s = 0.f, q = 0.f;
#pragma unroll
                for (int j = 0; j < 8; j++) {
                    float val = acc[i][j] + uval - vrow[sidx[nloc * 16 + khalf + j]];
                    hv[j] = val; s += val; q += val * val;
                }
                float* hd = h + crow * M_ + m0 + tx * 8;
                *(float4*)hd       = make_float4(hv[0], hv[1], hv[2], hv[3]);
                *(float4*)(hd + 4) = make_float4(hv[4], hv[5], hv[6], hv[7]);
                redS[cl * 17 + tx] = s; redQ[cl * 17 + tx] = q;
            }
            __syncthreads();
            if (tid < 128) {
                float s = 0.f, q = 0.f;
#pragma unroll
                for (int t = 0; t < 16; t++) { s += redS[tid * 17 + t]; q += redQ[tid * 17 + t]; }
                size_t p = (((size_t)b * (M_ / 128) + blockIdx.x) * AH_ + ot * 128 + tid) * 2;
                part[p] = s; part[p + 1] = q;
            }
        } else {
#pragma unroll
            for (int i = 0; i < 8; i++) {
                int c = (ot - 8) * 128 + ty * 8 + i;
                float bv = pos_b2[c];
                float* pd = pe + ((size_t)b * DIM_ + c) * M_ + m0 + tx * 8;
                *(float4*)pd       = make_float4(acc[i][0] + bv, acc[i][1] + bv,
                                                 acc[i][2] + bv, acc[i][3] + bv);
                *(float4*)(pd + 4) = make_float4(acc[i][4] + bv, acc[i][5] + bv,
                                                 acc[i][6] + bv, acc[i][7] + bv);
            }
        }
    }
}

// ---------------- attn GEMM2 (HMMA, cp.async pipelined) ----------------------
// D[m=128][c=256] = sum_k bnrelu(h[k][m]) * att_w2[c][k]  (K=1024, chunks of 64)
// smem: A bf16 2x32K (0,32K) | B 2x64K (64K,128K) | A fp32 staging 32K (192K)
#define A_OFF(s)  ((s) * 32768)
#define B_OFF(s)  (65536 + (s) * 65536)
#define STG_OFF   196608
#define SMEM_ATT2 229376

__device__ __forceinline__ void attn2_cpasync(uint32_t sb, int s, int cq,
                                              const float* hbase, const uint4* w2img,
                                              int tid) {
    // B: 4096 uint4, contiguous
    const uint4* src = w2img + (size_t)cq * 4096;
    uint32_t bdst = sb + B_OFF(s);
#pragma unroll
    for (int it = 0; it < 16; it++) {
        int i = it * 256 + tid;
        cp_async16(bdst + i * 16, src + i);
    }
    // A fp32: 64 rows (k) x 512B (128 m floats) into staging
#pragma unroll
    for (int it = 0; it < 8; it++) {
        int ch = it * 256 + tid;           // 2048 chunks of 16B
        int krow = ch >> 5, moff = (ch & 31) * 4;
        const float* srcr = hbase + (size_t)(cq * 64 + krow) * M_ + moff;
        cp_async16(sb + STG_OFF + krow * 512 + (ch & 31) * 16, srcr);
    }
}

__device__ __forceinline__ void attn2_convert(char* smc, uint32_t sb, int s, int cq,
                                              const float* __restrict__ scale,
                                              const float* __restrict__ shift,
                                              int wid, int lane) {
    const float* stg = (const float*)(smc + STG_OFF);
    char* dst = smc + A_OFF(s);
#pragma unroll
    for (int g2 = 0; g2 < 2; g2++) {
        int base_k = wid * 8 + g2 * 4;
        float4 v[4];
        uint32_t hiv[4], lov[4];
#pragma unroll
        for (int r = 0; r < 4; r++)
            v[r] = *(const float4*)&stg[(base_k + r) * 128 + lane * 4];
#pragma unroll
        for (int r = 0; r < 4; r++) {
            float sc = scale[cq * 64 + base_k + r];
            float sh = shift[cq * 64 + base_k + r];
            float x0 = fmaxf(v[r].x * sc + sh, 0.f);
            float x1 = fmaxf(v[r].y * sc + sh, 0.f);
            float x2 = fmaxf(v[r].z * sc + sh, 0.f);
            float x3 = fmaxf(v[r].w * sc + sh, 0.f);
            float r0 = __bfloat162float(__float2bfloat16(x0));
            float r1 = __bfloat162float(__float2bfloat16(x1));
            float r2 = __bfloat162float(__float2bfloat16(x2));
            float r3 = __bfloat162float(__float2bfloat16(x3));
            // transpose into per-m registers: element mm of hi/lo gets k-slot r
            float xs[4] = {x0, x1, x2, x3};
            float rs[4] = {x0 - r0, x1 - r1, x2 - r2, x3 - r3};
#pragma unroll
            for (int mm = 0; mm < 4; mm++) {
                uint32_t hb = (uint32_t)__bfloat16_as_ushort(__float2bfloat16(xs[mm]));
                uint32_t lb = (uint32_t)__bfloat16_as_ushort(__float2bfloat16(rs[mm]));
                if (r == 0) { hiv[mm] = hb; lov[mm] = lb; }
                else { hiv[mm] |= hb << (16 * (r & 1)); lov[mm] |= lb << (16 * (r & 1)); }
                if (r == 2) { hiv[mm] = (hiv[mm] & 0xFFFFu) | (hb << 0); }  // placeholder, fixed below
            }
            (void)rs;
        }
        // NOTE: the above per-r packing is awkward; redo cleanly:
        {
            float X[4][4], L[4][4];
#pragma unroll
            for (int r = 0; r < 4; r++) {
                float sc = scale[cq * 64 + base_k + r];
                float sh = shift[cq * 64 + base_k + r];
                float xv[4] = {v[r].x, v[r].y, v[r].z, v[r].w};
#pragma unroll
                for (int mm = 0; mm < 4; mm++) {
                    float x = fmaxf(xv[mm] * sc + sh, 0.f);
                    float hi = __bfloat162float(__float2bfloat16(x));
                    X[mm][r] = x; L[mm][r] = x - hi;
                }
            }
#pragma unroll
            for (int mm = 0; mm < 4; mm++) {
                int m = lane * 4 + mm;
                uint32_t off = (uint32_t)((m >> 3) * 1024 + (m & 7) * 128 +
                                          ((base_k * 2) ^ ((m & 7) << 4)));
                *(uint2*)(dst + off) =
                    make_uint2(pack_bf16(X[mm][0], X[mm][1]), pack_bf16(X[mm][2], X[mm][3]));
                *(uint2*)(dst + 16384 + off) =
                    make_uint2(pack_bf16(L[mm][0], L[mm][1]), pack_bf16(L[mm][2], L[mm][3]));
            }
        }
    }
}

__global__ __launch_bounds__(256, 1) void attn2_hmma_kernel(
    const uint4* __restrict__ w2img, const float* __restrict__ h,
    const float* __restrict__ scale, const float* __restrict__ shift,
    const float* __restrict__ pe, const float* __restrict__ vf,
    float* __restrict__ agg) {
    extern __shared__ char smc[];
    const uint32_t sb = smem_u32(smc);
    const int tid = threadIdx.x, lane = tid & 31, wid = tid >> 5;
    const int b = blockIdx.y, m0 = blockIdx.x * 128;
    const int warp_m = wid >> 2, warp_c = wid & 3;   // 2 x 4 warp grid, 64x64 tiles

    const float* hbase = h + (size_t)b * AH_ * M_ + m0;

    float acc[4][8][4];
#pragma unroll
    for (int mt = 0; mt < 4; mt++)
#pragma unroll
        for (int nt = 0; nt < 8; nt++)
#pragma unroll
            for (int j = 0; j < 4; j++) acc[mt][nt][j] = 0.0f;

    const int g = lane >> 3, lr = lane & 7;
    const int amr  = warp_m * 64 + (g & 1) * 8 + lr;
    const int bcr  = warp_c * 64 + (g >> 1) * 8 + lr;
    const int akb0 = (g >> 1) * 16;
    const int bkb0 = (g & 1) * 16;

    // prologue: stage 0
    attn2_cpasync(sb, 0, 0, hbase, w2img, tid);
    CP_COMMIT();
    CP_WAIT0();
    __syncthreads();
    attn2_convert(smc, sb, 0, 0, scale, shift, wid, lane);
    __syncthreads();

    for (int cq = 0; cq < 16; cq++) {
        const int s = cq & 1;
        if (cq + 1 < 16) {
            attn2_cpasync(sb, s ^ 1, cq + 1, hbase, w2img, tid);
            CP_COMMIT();
        }
        const uint32_t sA = sb + A_OFF(s);
        const uint32_t sB = sb + B_OFF(s);
#pragma unroll
        for (int ks = 0; ks < 4; ks++) {
            uint32_t Ahi[4][4], Alo[4][4], Bhi[4][4], Blo[4][4];
#pragma unroll
            for (int mt = 0; mt < 4; mt++) {
                int m = amr + mt * 16;
                uint32_t ro = (uint32_t)((m >> 3) * 1024 + (m & 7) * 128);
                uint32_t kb = (uint32_t)((ks * 32 + akb0) ^ ((m & 7) << 4));
                ldm_x4(Ahi[mt], sA + ro + kb);
                ldm_x4(Alo[mt], sA + 16384 + ro + kb);
            }
#pragma unroll
            for (int np = 0; np < 4; np++) {
                int c = bcr + np * 16;
                uint32_t ro = (uint32_t)((c >> 3) * 1024 + (c & 7) * 128);
                uint32_t kb = (uint32_t)((ks * 32 + bkb0) ^ ((c & 7) << 4));
                ldm_x4(Bhi[np], sB + ro + kb);
                ldm_x4(Blo[np], sB + 32768 + ro + kb);
            }
#pragma unroll
            for (int mt = 0; mt < 4; mt++)
#pragma unroll
                for (int np = 0; np < 4; np++) {
                    mma16816(acc[mt][np * 2],     Ahi[mt], &Bhi[np][0]);
                    mma16816(acc[mt][np * 2],     Alo[mt], &Bhi[np][0]);
                    mma16816(acc[mt][np * 2],     Ahi[mt], &Blo[np][0]);
                    mma16816(acc[mt][np * 2 + 1], Ahi[mt], &Bhi[np][2]);
                    mma16816(acc[mt][np * 2 + 1], Alo[mt], &Bhi[np][2]);
                    mma16816(acc[mt][np * 2 + 1], Ahi[mt], &Blo[np][2]);
                }
        }
        if (cq + 1 < 16) {
            CP_WAIT0();
            __syncthreads();
            attn2_convert(smc, sb, s ^ 1, cq + 1, scale, shift, wid, lane);
            __syncthreads();
        }
    }
    __syncthreads();

    // ---- epilogue: stage pe tile (c=256 rows x m=128 cols, stride 132) ----
    float* pes = (float*)smc;
    for (int i = tid; i < 256 * 32; i += 256) {
        int row = i >> 5, q = i & 31;
        float4 v = *(const float4*)(pe + ((size_t)(b * DIM_ + row)) * M_ + m0 + q * 4);
        *(float4*)&pes[row * 132 + q * 4] = v;
    }
    __syncthreads();

#pragma unroll
    for (int mt = 0; mt < 4; mt++) {
        const int mbase = warp_m * 64 + mt * 16;
        const int n = (m0 + mbase) >> 4;
        const int r = lane >> 2;
#pragma unroll
        for (int nt = 0; nt < 8; nt++) {
#pragma unroll
            for (int j = 0; j < 2; j++) {
                int c = warp_c * 64 + nt * 8 + (lane & 3) * 2 + j;
                float v0 = acc[mt][nt][j], v1 = acc[mt][nt][2 + j];
                float mx = fmaxf(v0, v1);
                mx = fmaxf(mx, __shfl_xor_sync(0xffffffffu, mx, 4));
                mx = fmaxf(mx, __shfl_xor_sync(0xffffffffu, mx, 8));
                mx = fmaxf(mx, __shfl_xor_sync(0xffffffffu, mx, 16));
                float e0 = __expf(v0 - mx), e1 = __expf(v1 - mx);
                float se = e0 + e1;
                se += __shfl_xor_sync(0xffffffffu, se, 4);
                se += __shfl_xor_sync(0xffffffffu, se, 8);
                se += __shfl_xor_sync(0xffffffffu, se, 16);
                float p0 = pes[c * 132 + mbase + r];
                float p1 = pes[c * 132 + mbase + r + 8];
                float t = e0 * p0 + e1 * p1;
                t += __shfl_xor_sync(0xffffffffu, t, 4);
                t += __shfl_xor_sync(0xffffffffu, t, 8);
                t += __shfl_xor_sync(0xffffffffu, t, 16);
                if (r == 0) {
                    size_t o = ((size_t)(b * DIM_ + c)) * N_ + n;
                    agg[o] = vf[o] + t / se;
                }
            }
        }
    }
}

// ---------------- launch ----------------------------------------------------
extern "C" void kernel_launch(void* const* d_in, const int* in_sizes, int n_in,
                              void* d_out, int out_size) {
    const float* pos     = (const float*)d_in[0];
    const float* key     = (const float*)d_in[1];
    const float* query   = (const float*)d_in[2];
    const float* mlpv_w1 = (const float*)d_in[3];
    const float* mlpv_b1 = (const float*)d_in[4];
    const float* mlpv_w2 = (const float*)d_in[5];
    const float* mlpv_b2 = (const float*)d_in[6];
    const float* mlpv_ws = (const float*)d_in[7];
    const float* mlpv_bs = (const float*)d_in[8];
    const float* wk      = (const float*)d_in[9];
    const float* bk      = (const float*)d_in[10];
    const float* wq      = (const float*)d_in[11];
    const float* bq      = (const float*)d_in[12];
    const float* wv      = (const float*)d_in[13];
    const float* bv      = (const float*)d_in[14];
    const float* pos_w1  = (const float*)d_in[15];
    const float* pos_b1  = (const float*)d_in[16];
    const float* pos_g1  = (const float*)d_in[17];
    const float* pos_be1 = (const float*)d_in[18];
    const float* pos_w2  = (const float*)d_in[19];
    const float* pos_b2  = (const float*)d_in[20];
    const float* att_w1  = (const float*)d_in[21];
    const float* att_b1  = (const float*)d_in[22];
    const float* att_g1  = (const float*)d_in[23];
    const float* att_be1 = (const float*)d_in[24];
    const float* att_w2  = (const float*)d_in[25];
    const float* we      = (const float*)d_in[27];
    const float* be      = (const float*)d_in[28];
    float* out = (float*)d_out;

    void* p;
#define GETP(sym, var) cudaGetSymbolAddress(&p, sym); float* var = (float*)p;
    GETP(g_x, x_)       GETP(g_t, t_)       GETP(g_value, val)
    GETP(g_vf, vf_)     GETP(g_u, u_)       GETP(g_v, v_)
    GETP(g_t1, t1_)     GETP(g_pe, pe_)     GETP(g_h, h_)
    GETP(g_agg, agg)    GETP(g_part, part)  GETP(g_partp, partp)
    GETP(g_Wuq, Wuq)    GETP(g_Wvk, Wvk)    GETP(g_A1t, A1t)
    GETP(g_posw2t, posw2t) GETP(g_bias1, bias1)
    GETP(g_scp, scp)    GETP(g_shp, shp)    GETP(g_sca, sca)
    GETP(g_sha, sha)    GETP(g_zero, zero)
#undef GETP
    cudaGetSymbolAddress(&p, g_idx);   int* idx = (int*)p;
    cudaGetSymbolAddress(&p, g_w2img); unsigned int* w2img = (unsigned int*)p;

    // --- precompute folded weights + w2 bf16 image ---
    smallmm_kernel<<<(AH_ * C_ + 255) / 256, 256>>>(att_w1, wq, Wuq, AH_, DIM_, C_, 0);
    smallmm_kernel<<<(AH_ * C_ + 255) / 256, 256>>>(att_w1, wk, Wvk, AH_, DIM_, C_, 0);
    smallmm_kernel<<<(AH_ * PH_ + 255) / 256, 256>>>(att_w1, pos_w2, A1t, AH_, DIM_, PH_, 1);
    transpose_kernel<<<(DIM_ * PH_ + 255) / 256, 256>>>(pos_w2, posw2t, DIM_, PH_);
    bias1_kernel<<<(AH_ + 255) / 256, 256>>>(att_w1, bq, bk, pos_b2, att_b1, bias1);
    prep_w2_kernel<<<(256 * 256) / 256, 256>>>(att_w2, w2img);

    // --- front end ---
    concat_kernel<<<(unsigned)(((size_t)B_ * 2 * C_ * N_ + 255) / 256), 256>>>(key, query, x_);
    knn_kernel<<<dim3(N_ / 256, B_), 256>>>(pos, idx);
    sgemm_kernel<1><<<dim3(N_ / 128, C_ / 128, B_), 256>>>(mlpv_w1, x_, mlpv_b1, t_, nullptr, C_, 2 * C_, N_);
    sgemm_kernel<0><<<dim3(N_ / 128, C_ / 128, B_), 256>>>(mlpv_w2, t_, mlpv_b2, val, nullptr, C_, C_, N_);
    sgemm_kernel<2><<<dim3(N_ / 128, C_ / 128, B_), 256>>>(mlpv_ws, x_, mlpv_bs, val, nullptr, C_, 2 * C_, N_);
    sgemm_kernel<0><<<dim3(N_ / 128, DIM_ / 128, B_), 256>>>(wv, val, bv, vf_, nullptr, DIM_, C_, N_);
    sgemm_kernel<0><<<dim3(N_ / 128, AH_ / 128, B_), 256>>>(Wuq, query, zero, u_, nullptr, AH_, C_, N_);
    sgemm_kernel<0><<<dim3(N_ / 128, AH_ / 128, B_), 256>>>(Wvk, key, zero, v_, nullptr, AH_, C_, N_);

    // --- pos_rel conv1 + pos BN ---
    posrel_kernel<<<(unsigned)(((size_t)B_ * PH_ * M_) / 256), 256>>>(pos, idx, pos_w1, pos_b1, t1_, partp);
    finalize_stats<<<PH_, 256>>>(partp, 512, 1, 512, pos_g1, pos_be1, scp, shp, (float)((size_t)B_ * M_));

    // --- fused mid: h + pe (+ attn BN partials) ---
    cudaFuncSetAttribute(fused_mid_kernel, cudaFuncAttributeMaxDynamicSharedMemorySize, 65536);
    fused_mid_kernel<<<dim3(M_ / 128, B_), 256, 65536>>>(
        t1_, scp, shp, A1t, posw2t, bias1, pos_b2, u_, v_, idx, h_, pe_, part);
    finalize_stats<<<AH_, 256>>>(part, B_ * (M_ / 128), AH_, 1, att_g1, att_be1, sca, sha, (float)((size_t)B_ * M_));

    // --- big GEMM2: cp.async-pipelined HMMA + softmax + aggregation ---
    cudaFuncSetAttribute(attn2_hmma_kernel, cudaFuncAttributeMaxDynamicSharedMemorySize, SMEM_ATT2);
    attn2_hmma_kernel<<<dim3(M_ / 128, B_), 256, SMEM_ATT2>>>(
        (const uint4*)w2img, h_, sca, sha, pe_, vf_, agg);

    // --- final projection + residual ---
    sgemm_kernel<4><<<dim3(N_ / 128, C_ / 128, B_), 256>>>(we, agg, be, out, val, C_, DIM_, N_);
}

// round 8
// speedup vs baseline: 1.8566x; 1.0348x over previous
#include <cuda_runtime.h>
#include <cuda_bf16.h>
#include <math.h>
#include <stdint.h>

#define B_   2
#define C_   128
#define N_   4096
#define K_   16
#define DIM_ 256
#define PH_  64
#define AH_  1024
#define M_   (N_ * K_)          // 65536 columns per batch in (n,k) space

// ---------------- scratch ---------------------------------------------------
__device__ float g_x    [(size_t)B_ * 2 * C_ * N_];
__device__ float g_t    [(size_t)B_ * C_ * N_];
__device__ float g_value[(size_t)B_ * C_ * N_];
__device__ float g_vf   [(size_t)B_ * DIM_ * N_];
__device__ float g_u    [(size_t)B_ * AH_ * N_];
__device__ float g_v    [(size_t)B_ * AH_ * N_];
__device__ int   g_idx  [(size_t)B_ * N_ * K_];
__device__ float g_t1   [(size_t)B_ * PH_ * M_];
__device__ float g_pe   [(size_t)B_ * DIM_ * M_];
__device__ float g_h    [(size_t)B_ * AH_ * M_];       // h: [B][AH][M]  (c-major)
__device__ float g_agg  [(size_t)B_ * DIM_ * N_];
__device__ float g_part [(size_t)B_ * 512 * AH_ * 2];
__device__ float g_partp[(size_t)PH_ * 512 * 2];
__device__ float g_Wuq  [AH_ * C_];
__device__ float g_Wvk  [AH_ * C_];
__device__ float g_bias1[AH_];
__device__ float g_scp  [PH_];
__device__ float g_shp  [PH_];
__device__ float g_sca  [AH_];
__device__ float g_sha  [AH_];
__device__ float g_zero [AH_];
// pre-swizzled bf16 image of att_w2: 16 K-chunks x (hi 32KB + lo 32KB) = 1MB
__device__ unsigned int g_w2img[16 * 65536 / 4];
// pre-swizzled bf16 image of Wmid = concat(att_w1@pos_w2, pos_w2): 10 chunks x 32KB
__device__ unsigned int g_wmidimg[10 * 32768 / 4];

// ---------------- helpers ---------------------------------------------------
__device__ __forceinline__ uint32_t smem_u32(const void* p) {
    uint32_t a;
    asm("{ .reg .u64 t; cvta.to.shared.u64 t, %1; cvt.u32.u64 %0, t; }" : "=r"(a) : "l"(p));
    return a;
}
#define SWZ128(b) ((b) ^ (((b) >> 3) & 0x70))
__device__ __forceinline__ uint32_t pack_bf16(float a, float b) {
    __nv_bfloat16 ha = __float2bfloat16(a), hb = __float2bfloat16(b);
    return (uint32_t)__bfloat16_as_ushort(ha) |
           ((uint32_t)__bfloat16_as_ushort(hb) << 16);
}
__device__ __forceinline__ void ldm_x4(uint32_t* r, uint32_t addr) {
    asm volatile("ldmatrix.sync.aligned.m8n8.x4.shared.b16 {%0,%1,%2,%3}, [%4];"
        : "=r"(r[0]), "=r"(r[1]), "=r"(r[2]), "=r"(r[3]) : "r"(addr));
}
__device__ __forceinline__ void mma16816(float* d, const uint32_t* a, const uint32_t* b) {
    asm volatile(
        "mma.sync.aligned.m16n8k16.row.col.f32.bf16.bf16.f32 "
        "{%0,%1,%2,%3}, {%4,%5,%6,%7}, {%8,%9}, {%0,%1,%2,%3};"
        : "+f"(d[0]), "+f"(d[1]), "+f"(d[2]), "+f"(d[3])
        : "r"(a[0]), "r"(a[1]), "r"(a[2]), "r"(a[3]), "r"(b[0]), "r"(b[1]));
}
__device__ __forceinline__ void cp_async16(uint32_t dst, const void* src) {
    asm volatile("cp.async.cg.shared.global [%0], [%1], 16;" :: "r"(dst), "l"(src));
}
#define CP_COMMIT() asm volatile("cp.async.commit_group;" ::: "memory")
#define CP_WAIT0()  asm volatile("cp.async.wait_group 0;" ::: "memory")

// ---------------- concat ----------------------------------------------------
__global__ void concat_kernel(const float* __restrict__ key,
                              const float* __restrict__ query,
                              float* __restrict__ x) {
    size_t i = (size_t)blockIdx.x * blockDim.x + threadIdx.x;
    if (i >= (size_t)B_ * 2 * C_ * N_) return;
    int n = (int)(i % N_);
    int c = (int)((i / N_) % (2 * C_));
    int b = (int)(i / ((size_t)N_ * 2 * C_));
    float v;
    if (c < C_) v = key  [((size_t)b * C_ + c) * N_ + n];
    else        v = query[((size_t)b * C_ + (c - C_)) * N_ + n];
    x[i] = v;
}

// ---------------- KNN -------------------------------------------------------
__global__ void knn_kernel(const float* __restrict__ pos, int* __restrict__ idx) {
    const int b = blockIdx.y;
    const int n = blockIdx.x * blockDim.x + threadIdx.x;
    const float* p = pos + (size_t)b * 3 * N_;
    const float qx = p[n], qy = p[N_ + n], qz = p[2 * N_ + n];
    const float qs = qx * qx + qy * qy + qz * qz;
    float bd[K_]; int bi[K_];
#pragma unroll
    for (int j = 0; j < K_; j++) { bd[j] = 3.4e38f; bi[j] = 0; }
    __shared__ float sx[512], sy[512], sz[512], ss[512];
    for (int t0 = 0; t0 < N_; t0 += 512) {
        __syncthreads();
        for (int i = threadIdx.x; i < 512; i += blockDim.x) {
            float x = p[t0 + i], y = p[N_ + t0 + i], z = p[2 * N_ + t0 + i];
            sx[i] = x; sy[i] = y; sz[i] = z; ss[i] = x * x + y * y + z * z;
        }
        __syncthreads();
        for (int i = 0; i < 512; i++) {
            float d = qs + ss[i] - 2.0f * (qx * sx[i] + qy * sy[i] + qz * sz[i]);
            if (d < bd[K_ - 1]) {
                int j = K_ - 1;
                while (j > 0 && d < bd[j - 1]) { bd[j] = bd[j - 1]; bi[j] = bi[j - 1]; j--; }
                bd[j] = d; bi[j] = t0 + i;
            }
        }
    }
    int* op = idx + ((size_t)b * N_ + n) * K_;
#pragma unroll
    for (int j = 0; j < K_; j++) op[j] = bi[j];
}

// ---------------- precompute small products ---------------------------------
__global__ void smallmm_kernel(const float* __restrict__ A, const float* __restrict__ Bm,
                               float* __restrict__ Cc, int O, int Id, int J, int tr) {
    int t = blockIdx.x * 256 + threadIdx.x;
    if (t >= O * J) return;
    int o = t / J, j = t % J;
    float s = 0.0f;
    for (int d = 0; d < Id; d++) s += A[o * Id + d] * Bm[d * J + j];
    if (tr) Cc[j * O + o] = s; else Cc[o * J + j] = s;
}
__global__ void bias1_kernel(const float* __restrict__ w1, const float* __restrict__ bq,
                             const float* __restrict__ bk, const float* __restrict__ pb2,
                             const float* __restrict__ ab1, float* __restrict__ out) {
    int o = blockIdx.x * 256 + threadIdx.x;
    if (o >= AH_) return;
    float s = ab1[o];
    for (int d = 0; d < DIM_; d++) s += w1[o * DIM_ + d] * (bq[d] - bk[d] + pb2[d]);
    out[o] = s;
}

// ---------------- att_w2 -> pre-swizzled bf16 hi/lo image --------------------
__global__ void prep_w2_kernel(const float* __restrict__ w2, unsigned int* __restrict__ img) {
    int t = blockIdx.x * 256 + threadIdx.x;   // 65536 = 256 c * 256 k4
    if (t >= 256 * 256) return;
    int c = t >> 8, k4 = t & 255;
    int k = k4 * 4;
    int q = k >> 6, kl = k & 63;
    const float* src = w2 + (size_t)c * AH_ + k;
    float f0 = src[0], f1 = src[1], f2 = src[2], f3 = src[3];
    float h0 = __bfloat162float(__float2bfloat16(f0));
    float h1 = __bfloat162float(__float2bfloat16(f1));
    float h2 = __bfloat162float(__float2bfloat16(f2));
    float h3 = __bfloat162float(__float2bfloat16(f3));
    uint32_t off = SWZ128((uint32_t)((c >> 3) * 1024 + (c & 7) * 128 + kl * 2));
    char* base = (char*)img + (size_t)q * 65536;
    *(uint2*)(base + off) = make_uint2(pack_bf16(f0, f1), pack_bf16(f2, f3));
    *(uint2*)(base + 32768 + off) =
        make_uint2(pack_bf16(f0 - h0, f1 - h1), pack_bf16(f2 - h2, f3 - h3));
}

// ---------------- Wmid -> pre-swizzled bf16 hi/lo image ----------------------
// Wmid[c][k]: c<1024: (att_w1@pos_w2)[c][k]; c>=1024: pos_w2[c-1024][k]. k=0..63.
// Image: 10 chunks of 128 c-rows; chunk = [hi 16KB][lo 16KB] contiguous.
__global__ void prep_wmid_kernel(const float* __restrict__ att_w1,
                                 const float* __restrict__ pos_w2,
                                 unsigned int* __restrict__ img) {
    int t = blockIdx.x * 256 + threadIdx.x;   // 1280 * 16
    if (t >= 1280 * 16) return;
    int c = t >> 4, k4 = t & 15;
    float f[4];
    if (c < AH_) {
#pragma unroll 4
        for (int kk = 0; kk < 4; kk++) {
            float s = 0.0f;
            for (int d = 0; d < DIM_; d++)
                s += att_w1[(size_t)c * DIM_ + d] * pos_w2[d * PH_ + k4 * 4 + kk];
            f[kk] = s;
        }
    } else {
#pragma unroll
        for (int kk = 0; kk < 4; kk++) f[kk] = pos_w2[(c - AH_) * PH_ + k4 * 4 + kk];
    }
    float r[4];
#pragma unroll
    for (int kk = 0; kk < 4; kk++)
        r[kk] = f[kk] - __bfloat162float(__float2bfloat16(f[kk]));
    int ct = c >> 7, cl = c & 127;
    uint32_t off = (uint32_t)((cl >> 3) * 1024 + (cl & 7) * 128 +
                              ((k4 * 8) ^ ((cl & 7) << 4)));
    char* base = (char*)img + (size_t)ct * 32768;
    *(uint2*)(base + off) = make_uint2(pack_bf16(f[0], f[1]), pack_bf16(f[2], f[3]));
    *(uint2*)(base + 16384 + off) = make_uint2(pack_bf16(r[0], r[1]), pack_bf16(r[2], r[3]));
}

// ---------------- generic fp32 SGEMM (small GEMMs) --------------------------
template <int FLAGS>
__global__ void sgemm_kernel(const float* __restrict__ W, const float* __restrict__ Xg,
                             const float* __restrict__ bias, float* __restrict__ outg,
                             const float* __restrict__ resg, int O, int I, int M) {
    const int b = blockIdx.z;
    const float* X = Xg + (size_t)b * I * M;
    float* out = outg + (size_t)b * O * M;
    const float* res = (FLAGS & 4) ? (resg + (size_t)b * O * M) : nullptr;
    __shared__ float Ws[8][132];
    __shared__ float Xs[8][128];
    const int tid = threadIdx.x;
    const int tx = tid & 15, ty = tid >> 4;
    const int o0 = blockIdx.y * 128, m0 = blockIdx.x * 128;
    const int wr = tid >> 1, wc = (tid & 1) * 4;
    const int xr = tid >> 5, xc = (tid & 31) * 4;
    float acc[8][8];
#pragma unroll
    for (int i = 0; i < 8; i++)
#pragma unroll
        for (int j = 0; j < 8; j++) acc[i][j] = 0.0f;
    for (int kt = 0; kt < I; kt += 8) {
        float4 wv = *(const float4*)&W[(size_t)(o0 + wr) * I + kt + wc];
        float4 xv = *(const float4*)&X[(size_t)(kt + xr) * M + m0 + xc];
        __syncthreads();
        Ws[wc + 0][wr] = wv.x; Ws[wc + 1][wr] = wv.y;
        Ws[wc + 2][wr] = wv.z; Ws[wc + 3][wr] = wv.w;
        *(float4*)&Xs[xr][xc] = xv;
        __syncthreads();
#pragma unroll
        for (int k = 0; k < 8; k++) {
            float a[8], bb[8];
            *(float4*)&a[0]  = *(const float4*)&Ws[k][ty * 8];
            *(float4*)&a[4]  = *(const float4*)&Ws[k][ty * 8 + 4];
            *(float4*)&bb[0] = *(const float4*)&Xs[k][tx * 8];
            *(float4*)&bb[4] = *(const float4*)&Xs[k][tx * 8 + 4];
#pragma unroll
            for (int i = 0; i < 8; i++)
#pragma unroll
                for (int j = 0; j < 8; j++) acc[i][j] += a[i] * bb[j];
        }
    }
#pragma unroll
    for (int i = 0; i < 8; i++) {
        const int o = o0 + ty * 8 + i;
        const float bv = bias[o];
        float* orow = out + (size_t)o * M + m0 + tx * 8;
        const float* rrow = (FLAGS & 4) ? (res + (size_t)o * M + m0 + tx * 8) : nullptr;
#pragma unroll
        for (int jj = 0; jj < 8; jj += 4) {
            float4 v;
            v.x = acc[i][jj + 0] + bv; v.y = acc[i][jj + 1] + bv;
            v.z = acc[i][jj + 2] + bv; v.w = acc[i][jj + 3] + bv;
            if (FLAGS & 1) { v.x = fmaxf(v.x, 0.f); v.y = fmaxf(v.y, 0.f);
                             v.z = fmaxf(v.z, 0.f); v.w = fmaxf(v.w, 0.f); }
            if (FLAGS & 2) { float4 old = *(float4*)&orow[jj];
                             v.x += old.x; v.y += old.y; v.z += old.z; v.w += old.w; }
            if (FLAGS & 4) { float4 r = *(const float4*)&rrow[jj];
                             v.x += r.x; v.y += r.y; v.z += r.z; v.w += r.w; }
            *(float4*)&orow[jj] = v;
        }
    }
}

// ---------------- pos_rel conv1 + BN partial stats ---------------------------
__global__ void posrel_kernel(const float* __restrict__ pos, const int* __restrict__ idx,
                              const float* __restrict__ w, const float* __restrict__ bias,
                              float* __restrict__ t1, float* __restrict__ part) {
    size_t i = (size_t)blockIdx.x * 256 + threadIdx.x;
    int k = (int)(i & 15);
    int n = (int)((i >> 4) & (N_ - 1));
    int c = (int)((i >> 16) & (PH_ - 1));
    int b = (int)(i >> 22);
    int m = idx[(((size_t)b * N_ + n) << 4) + k];
    const float* p = pos + (size_t)b * 3 * N_;
    float rx = p[n] - p[m];
    float ry = p[N_ + n] - p[N_ + m];
    float rz = p[2 * N_ + n] - p[2 * N_ + m];
    float val = w[c * 3] * rx + w[c * 3 + 1] * ry + w[c * 3 + 2] * rz + bias[c];
    t1[i] = val;
    __shared__ float ssum[256], ssq[256];
    ssum[threadIdx.x] = val; ssq[threadIdx.x] = val * val;
    __syncthreads();
    for (int st = 128; st > 0; st >>= 1) {
        if ((int)threadIdx.x < st) {
            ssum[threadIdx.x] += ssum[threadIdx.x + st];
            ssq[threadIdx.x]  += ssq[threadIdx.x + st];
        }
        __syncthreads();
    }
    if (threadIdx.x == 0) {
        int cb = (blockIdx.x >> 8) & (PH_ - 1);
        int bb = blockIdx.x >> 14;
        int sblk = blockIdx.x & 255;
        size_t o = ((size_t)cb * 512 + bb * 256 + sblk) * 2;
        part[o] = ssum[0]; part[o + 1] = ssq[0];
    }
}

// ---------------- BN finalize ------------------------------------------------
__global__ void finalize_stats(const float* __restrict__ part, int P, int ps, int cs,
                               const float* __restrict__ g, const float* __restrict__ be,
                               float* __restrict__ sc, float* __restrict__ sh, float cnt) {
    int c = blockIdx.x;
    double s = 0.0, q = 0.0;
    for (int p = threadIdx.x; p < P; p += blockDim.x) {
        size_t o = ((size_t)p * ps + (size_t)c * cs) * 2;
        s += (double)part[o]; q += (double)part[o + 1];
    }
    __shared__ double S[256], Q[256];
    S[threadIdx.x] = s; Q[threadIdx.x] = q;
    __syncthreads();
    for (int st = 128; st > 0; st >>= 1) {
        if ((int)threadIdx.x < st) {
            S[threadIdx.x] += S[threadIdx.x + st];
            Q[threadIdx.x] += Q[threadIdx.x + st];
        }
        __syncthreads();
    }
    if (threadIdx.x == 0) {
        double mean = S[0] / (double)cnt;
        double var  = Q[0] / (double)cnt - mean * mean;
        float scv = g[c] * (float)(1.0 / sqrt(var + 1e-5));
        sc[c] = scv;
        sh[c] = be[c] - (float)mean * scv;
    }
}

// ---------------- fused mid on HMMA ------------------------------------------
// D[c(1280)][m(256)] = Wmid[c][k] * relu(bn(t1))[k][m], K=64.
// c<1024: h = D + u + bias1 - gather(v); stats.  c>=1024: pe = D + pos_b2.
#define FM_XHI   0
#define FM_XLO   32768
#define FM_W(s)  (65536 + (s) * 32768)
#define FM_RED   131072
#define FM_SIDX  135168
#define FM_SMEM  136192

__global__ __launch_bounds__(256, 1) void fused_mid_hmma(
    const float* __restrict__ t1, const float* __restrict__ psc,
    const float* __restrict__ psh, const unsigned int* __restrict__ wimg,
    const float* __restrict__ bias1, const float* __restrict__ pos_b2,
    const float* __restrict__ u, const float* __restrict__ v,
    const int* __restrict__ idx, float* __restrict__ h,
    float* __restrict__ pe, float* __restrict__ part) {
    extern __shared__ char smc[];
    const uint32_t sb = smem_u32(smc);
    const int tid = threadIdx.x, lane = tid & 31, wid = tid >> 5;
    const int b = blockIdx.y, m0 = blockIdx.x * 256;
    const int warp_cg = wid >> 2, warp_mg = wid & 3;

    int* sidx = (int*)(smc + FM_SIDX);
    float* redS = (float*)(smc + FM_RED);
    float* redQ = redS + 512;

    sidx[tid] = idx[((size_t)b * N_ + (m0 >> 4)) * K_ + tid];

    // prefetch W chunk 0
    {
        const uint4* src = (const uint4*)wimg;
        uint32_t dst = sb + FM_W(0);
#pragma unroll
        for (int it = 0; it < 8; it++)
            cp_async16(dst + (it * 256 + tid) * 16, src + it * 256 + tid);
        CP_COMMIT();
    }
    // convert X: 64k x 256m -> bf16 hi/lo, m-row atoms, k-contiguous swizzled
    {
        const float* tb = t1 + (size_t)b * PH_ * M_ + m0;
        char* xhi = smc + FM_XHI;
        char* xlo = smc + FM_XLO;
        int m = tid;
#pragma unroll
        for (int k2 = 0; k2 < 32; k2++) {
            float x0 = tb[(size_t)(2 * k2) * M_ + m];
            float x1 = tb[(size_t)(2 * k2 + 1) * M_ + m];
            x0 = fmaxf(x0 * psc[2 * k2] + psh[2 * k2], 0.f);
            x1 = fmaxf(x1 * psc[2 * k2 + 1] + psh[2 * k2 + 1], 0.f);
            float l0 = x0 - __bfloat162float(__float2bfloat16(x0));
            float l1 = x1 - __bfloat162float(__float2bfloat16(x1));
            uint32_t off = (uint32_t)((m >> 3) * 1024 + (m & 7) * 128 +
                                      ((k2 * 4) ^ ((m & 7) << 4)));
            *(uint32_t*)(xhi + off) = pack_bf16(x0, x1);
            *(uint32_t*)(xlo + off) = pack_bf16(l0, l1);
        }
    }
    CP_WAIT0();
    __syncthreads();

    const int g = lane >> 3, lr = lane & 7;
    const int wrow = warp_cg * 64 + (g & 1) * 8 + lr;    // + ct2*16  (c rows)
    const int xrow = warp_mg * 64 + (g >> 1) * 8 + lr;   // + np*16   (m rows)
    const int wkb0 = (g >> 1) * 16;
    const int xkb0 = (g & 1) * 16;
    const uint32_t sX = sb + FM_XHI;

    for (int ct = 0; ct < 10; ct++) {
        const int s = ct & 1;
        if (ct + 1 < 10) {
            const uint4* src = (const uint4*)wimg + (ct + 1) * 2048;
            uint32_t dst = sb + FM_W(s ^ 1);
#pragma unroll
            for (int it = 0; it < 8; it++)
                cp_async16(dst + (it * 256 + tid) * 16, src + it * 256 + tid);
            CP_COMMIT();
        }
        const uint32_t sW = sb + FM_W(s);
        float acc[4][8][4];
#pragma unroll
        for (int a = 0; a < 4; a++)
#pragma unroll
            for (int q = 0; q < 8; q++)
#pragma unroll
                for (int j = 0; j < 4; j++) acc[a][q][j] = 0.0f;
#pragma unroll
        for (int ks = 0; ks < 4; ks++) {
            uint32_t Whi[4][4], Wlo[4][4], Xhf[4][4], Xlf[4][4];
#pragma unroll
            for (int ct2 = 0; ct2 < 4; ct2++) {
                int cr = wrow + ct2 * 16;
                uint32_t ro = (uint32_t)((cr >> 3) * 1024 + (cr & 7) * 128);
                uint32_t kb = (uint32_t)((ks * 32 + wkb0) ^ ((cr & 7) << 4));
                ldm_x4(Whi[ct2], sW + ro + kb);
                ldm_x4(Wlo[ct2], sW + 16384 + ro + kb);
            }
#pragma unroll
            for (int np = 0; np < 4; np++) {
                int mr = xrow + np * 16;
                uint32_t ro = (uint32_t)((mr >> 3) * 1024 + (mr & 7) * 128);
                uint32_t kb = (uint32_t)((ks * 32 + xkb0) ^ ((mr & 7) << 4));
                ldm_x4(Xhf[np], sX + ro + kb);
                ldm_x4(Xlf[np], sX + 32768 + ro + kb);
            }
#pragma unroll
            for (int ct2 = 0; ct2 < 4; ct2++)
#pragma unroll
                for (int np = 0; np < 4; np++) {
                    mma16816(acc[ct2][np * 2],     Whi[ct2], &Xhf[np][0]);
                    mma16816(acc[ct2][np * 2],     Wlo[ct2], &Xhf[np][0]);
                    mma16816(acc[ct2][np * 2],     Whi[ct2], &Xlf[np][0]);
                    mma16816(acc[ct2][np * 2 + 1], Whi[ct2], &Xhf[np][2]);
                    mma16816(acc[ct2][np * 2 + 1], Wlo[ct2], &Xhf[np][2]);
                    mma16816(acc[ct2][np * 2 + 1], Whi[ct2], &Xlf[np][2]);
                }
        }
        // epilogue
        if (ct < 8) {
            float sS[4][2], sQ[4][2];
#pragma unroll
            for (int a = 0; a < 4; a++) { sS[a][0] = sS[a][1] = 0.f; sQ[a][0] = sQ[a][1] = 0.f; }
#pragma unroll
            for (int ct2 = 0; ct2 < 4; ct2++) {
#pragma unroll
                for (int j = 0; j < 4; j++) {
                    int rh = j >> 1;
                    int c_g = ct * 128 + warp_cg * 64 + ct2 * 16 + (lane >> 2) + rh * 8;
                    size_t crow = (size_t)b * AH_ + c_g;
                    float bval = bias1[c_g];
                    const float* urow = u + crow * N_;
                    const float* vrow = v + crow * N_;
                    float* hrow = h + crow * M_ + m0;
#pragma unroll
                    for (int q = 0; q < 8; q++) {
                        int m_loc = warp_mg * 64 + q * 8 + (lane & 3) * 2 + (j & 1);
                        int n = (m0 + m_loc) >> 4;
                        float val = acc[ct2][q][j] + urow[n] + bval - vrow[sidx[m_loc]];
                        hrow[m_loc] = val;
                        sS[ct2][rh] += val; sQ[ct2][rh] += val * val;
                    }
                }
            }
#pragma unroll
            for (int ct2 = 0; ct2 < 4; ct2++)
#pragma unroll
                for (int rh = 0; rh < 2; rh++) {
                    float s1 = sS[ct2][rh], q1 = sQ[ct2][rh];
                    s1 += __shfl_xor_sync(0xffffffffu, s1, 1);
                    s1 += __shfl_xor_sync(0xffffffffu, s1, 2);
                    q1 += __shfl_xor_sync(0xffffffffu, q1, 1);
                    q1 += __shfl_xor_sync(0xffffffffu, q1, 2);
                    if ((lane & 3) == 0) {
                        int c_loc = warp_cg * 64 + ct2 * 16 + (lane >> 2) + rh * 8;
                        redS[c_loc * 4 + warp_mg] = s1;
                        redQ[c_loc * 4 + warp_mg] = q1;
                    }
                }
            __syncthreads();
            if (tid < 128) {
                float ss = redS[tid * 4] + redS[tid * 4 + 1] + redS[tid * 4 + 2] + redS[tid * 4 + 3];
                float qq = redQ[tid * 4] + redQ[tid * 4 + 1] + redQ[tid * 4 + 2] + redQ[tid * 4 + 3];
                size_t po = (((size_t)b * 256 + blockIdx.x) * AH_ + ct * 128 + tid) * 2;
                part[po] = ss; part[po + 1] = qq;
            }
        } else {
#pragma unroll
            for (int ct2 = 0; ct2 < 4; ct2++) {
#pragma unroll
                for (int j = 0; j < 4; j++) {
                    int c_pe = (ct - 8) * 128 + warp_cg * 64 + ct2 * 16 + (lane >> 2) + (j >> 1) * 8;
                    float bv = pos_b2[c_pe];
                    float* prow = pe + ((size_t)b * DIM_ + c_pe) * M_ + m0;
#pragma unroll
                    for (int q = 0; q < 8; q++) {
                        int m_loc = warp_mg * 64 + q * 8 + (lane & 3) * 2 + (j & 1);
                        prow[m_loc] = acc[ct2][q][j] + bv;
                    }
                }
            }
        }
        CP_WAIT0();
        __syncthreads();
    }
}

// ---------------- attn GEMM2 (HMMA, cp.async pipelined) ----------------------
#define A_OFF(s)  ((s) * 32768)
#define B_OFF(s)  (65536 + (s) * 65536)
#define STG_OFF   196608
#define SMEM_ATT2 229376

__device__ __forceinline__ void attn2_cpasync(uint32_t sb, int s, int cq,
                                              const float* hbase, const uint4* w2img,
                                              int tid) {
    const uint4* src = w2img + (size_t)cq * 4096;
    uint32_t bdst = sb + B_OFF(s);
#pragma unroll
    for (int it = 0; it < 16; it++) {
        int i = it * 256 + tid;
        cp_async16(bdst + i * 16, src + i);
    }
#pragma unroll
    for (int it = 0; it < 8; it++) {
        int ch = it * 256 + tid;
        int krow = ch >> 5;
        const float* srcr = hbase + (size_t)(cq * 64 + krow) * M_ + (ch & 31) * 4;
        cp_async16(sb + STG_OFF + krow * 512 + (ch & 31) * 16, srcr);
    }
}

__device__ __forceinline__ void attn2_convert(char* smc, int s, int cq,
                                              const float* __restrict__ scale,
                                              const float* __restrict__ shift,
                                              int wid, int lane) {
    const float* stg = (const float*)(smc + STG_OFF);
    char* dst = smc + A_OFF(s);
#pragma unroll
    for (int g2 = 0; g2 < 2; g2++) {
        int base_k = wid * 8 + g2 * 4;
        float4 v[4];
#pragma unroll
        for (int r = 0; r < 4; r++)
            v[r] = *(const float4*)&stg[(base_k + r) * 128 + lane * 4];
        float X[4][4], L[4][4];
#pragma unroll
        for (int r = 0; r < 4; r++) {
            float sc = scale[cq * 64 + base_k + r];
            float sh = shift[cq * 64 + base_k + r];
            float xv[4] = {v[r].x, v[r].y, v[r].z, v[r].w};
#pragma unroll
            for (int mm = 0; mm < 4; mm++) {
                float x = fmaxf(xv[mm] * sc + sh, 0.f);
                X[mm][r] = x;
                L[mm][r] = x - __bfloat162float(__float2bfloat16(x));
            }
        }
#pragma unroll
        for (int mm = 0; mm < 4; mm++) {
            int m = lane * 4 + mm;
            uint32_t off = (uint32_t)((m >> 3) * 1024 + (m & 7) * 128 +
                                      ((base_k * 2) ^ ((m & 7) << 4)));
            *(uint2*)(dst + off) = make_uint2(pack_bf16(X[mm][0], X[mm][1]),
                                              pack_bf16(X[mm][2], X[mm][3]));
            *(uint2*)(dst + 16384 + off) = make_uint2(pack_bf16(L[mm][0], L[mm][1]),
                                                      pack_bf16(L[mm][2], L[mm][3]));
        }
    }
}

__global__ __launch_bounds__(256, 1) void attn2_hmma_kernel(
    const uint4* __restrict__ w2img, const float* __restrict__ h,
    const float* __restrict__ scale, const float* __restrict__ shift,
    const float* __restrict__ pe, const float* __restrict__ vf,
    float* __restrict__ agg) {
    extern __shared__ char smc[];
    const uint32_t sb = smem_u32(smc);
    const int tid = threadIdx.x, lane = tid & 31, wid = tid >> 5;
    const int b = blockIdx.y, m0 = blockIdx.x * 128;
    const int warp_m = wid >> 2, warp_c = wid & 3;

    const float* hbase = h + (size_t)b * AH_ * M_ + m0;

    float acc[4][8][4];
#pragma unroll
    for (int mt = 0; mt < 4; mt++)
#pragma unroll
        for (int nt = 0; nt < 8; nt++)
#pragma unroll
            for (int j = 0; j < 4; j++) acc[mt][nt][j] = 0.0f;

    const int g = lane >> 3, lr = lane & 7;
    const int amr  = warp_m * 64 + (g & 1) * 8 + lr;
    const int bcr  = warp_c * 64 + (g >> 1) * 8 + lr;
    const int akb0 = (g >> 1) * 16;
    const int bkb0 = (g & 1) * 16;

    attn2_cpasync(sb, 0, 0, hbase, w2img, tid);
    CP_COMMIT();
    CP_WAIT0();
    __syncthreads();
    attn2_convert(smc, 0, 0, scale, shift, wid, lane);
    __syncthreads();

    for (int cq = 0; cq < 16; cq++) {
        const int s = cq & 1;
        if (cq + 1 < 16) {
            attn2_cpasync(sb, s ^ 1, cq + 1, hbase, w2img, tid);
            CP_COMMIT();
        }
        const uint32_t sA = sb + A_OFF(s);
        const uint32_t sB = sb + B_OFF(s);
#pragma unroll
        for (int ks = 0; ks < 4; ks++) {
            uint32_t Ahi[4][4], Alo[4][4], Bhi[4][4], Blo[4][4];
#pragma unroll
            for (int mt = 0; mt < 4; mt++) {
                int m = amr + mt * 16;
                uint32_t ro = (uint32_t)((m >> 3) * 1024 + (m & 7) * 128);
                uint32_t kb = (uint32_t)((ks * 32 + akb0) ^ ((m & 7) << 4));
                ldm_x4(Ahi[mt], sA + ro + kb);
                ldm_x4(Alo[mt], sA + 16384 + ro + kb);
            }
#pragma unroll
            for (int np = 0; np < 4; np++) {
                int c = bcr + np * 16;
                uint32_t ro = (uint32_t)((c >> 3) * 1024 + (c & 7) * 128);
                uint32_t kb = (uint32_t)((ks * 32 + bkb0) ^ ((c & 7) << 4));
                ldm_x4(Bhi[np], sB + ro + kb);
                ldm_x4(Blo[np], sB + 32768 + ro + kb);
            }
#pragma unroll
            for (int mt = 0; mt < 4; mt++)
#pragma unroll
                for (int np = 0; np < 4; np++) {
                    mma16816(acc[mt][np * 2],     Ahi[mt], &Bhi[np][0]);
                    mma16816(acc[mt][np * 2],     Alo[mt], &Bhi[np][0]);
                    mma16816(acc[mt][np * 2],     Ahi[mt], &Blo[np][0]);
                    mma16816(acc[mt][np * 2 + 1], Ahi[mt], &Bhi[np][2]);
                    mma16816(acc[mt][np * 2 + 1], Alo[mt], &Bhi[np][2]);
                    mma16816(acc[mt][np * 2 + 1], Ahi[mt], &Blo[np][2]);
                }
        }
        if (cq + 1 < 16) {
            CP_WAIT0();
            __syncthreads();
            attn2_convert(smc, s ^ 1, cq + 1, scale, shift, wid, lane);
            __syncthreads();
        }
    }
    __syncthreads();

    float* pes = (float*)smc;
    for (int i = tid; i < 256 * 32; i += 256) {
        int row = i >> 5, q = i & 31;
        float4 v = *(const float4*)(pe + ((size_t)(b * DIM_ + row)) * M_ + m0 + q * 4);
        *(float4*)&pes[row * 132 + q * 4] = v;
    }
    __syncthreads();

#pragma unroll
    for (int mt = 0; mt < 4; mt++) {
        const int mbase = warp_m * 64 + mt * 16;
        const int n = (m0 + mbase) >> 4;
        const int r = lane >> 2;
#pragma unroll
        for (int nt = 0; nt < 8; nt++) {
#pragma unroll
            for (int j = 0; j < 2; j++) {
                int c = warp_c * 64 + nt * 8 + (lane & 3) * 2 + j;
                float v0 = acc[mt][nt][j], v1 = acc[mt][nt][2 + j];
                float mx = fmaxf(v0, v1);
                mx = fmaxf(mx, __shfl_xor_sync(0xffffffffu, mx, 4));
                mx = fmaxf(mx, __shfl_xor_sync(0xffffffffu, mx, 8));
                mx = fmaxf(mx, __shfl_xor_sync(0xffffffffu, mx, 16));
                float e0 = __expf(v0 - mx), e1 = __expf(v1 - mx);
                float se = e0 + e1;
                se += __shfl_xor_sync(0xffffffffu, se, 4);
                se += __shfl_xor_sync(0xffffffffu, se, 8);
                se += __shfl_xor_sync(0xffffffffu, se, 16);
                float p0 = pes[c * 132 + mbase + r];
                float p1 = pes[c * 132 + mbase + r + 8];
                float t = e0 * p0 + e1 * p1;
                t += __shfl_xor_sync(0xffffffffu, t, 4);
                t += __shfl_xor_sync(0xffffffffu, t, 8);
                t += __shfl_xor_sync(0xffffffffu, t, 16);
                if (r == 0) {
                    size_t o = ((size_t)(b * DIM_ + c)) * N_ + n;
                    agg[o] = vf[o] + t / se;
                }
            }
        }
    }
}

// ---------------- launch ----------------------------------------------------
extern "C" void kernel_launch(void* const* d_in, const int* in_sizes, int n_in,
                              void* d_out, int out_size) {
    const float* pos     = (const float*)d_in[0];
    const float* key     = (const float*)d_in[1];
    const float* query   = (const float*)d_in[2];
    const float* mlpv_w1 = (const float*)d_in[3];
    const float* mlpv_b1 = (const float*)d_in[4];
    const float* mlpv_w2 = (const float*)d_in[5];
    const float* mlpv_b2 = (const float*)d_in[6];
    const float* mlpv_ws = (const float*)d_in[7];
    const float* mlpv_bs = (const float*)d_in[8];
    const float* wk      = (const float*)d_in[9];
    const float* bk      = (const float*)d_in[10];
    const float* wq      = (const float*)d_in[11];
    const float* bq      = (const float*)d_in[12];
    const float* wv      = (const float*)d_in[13];
    const float* bv      = (const float*)d_in[14];
    const float* pos_w1  = (const float*)d_in[15];
    const float* pos_b1  = (const float*)d_in[16];
    const float* pos_g1  = (const float*)d_in[17];
    const float* pos_be1 = (const float*)d_in[18];
    const float* pos_w2  = (const float*)d_in[19];
    const float* pos_b2  = (const float*)d_in[20];
    const float* att_w1  = (const float*)d_in[21];
    const float* att_b1  = (const float*)d_in[22];
    const float* att_g1  = (const float*)d_in[23];
    const float* att_be1 = (const float*)d_in[24];
    const float* att_w2  = (const float*)d_in[25];
    const float* we      = (const float*)d_in[27];
    const float* be      = (const float*)d_in[28];
    float* out = (float*)d_out;

    void* p;
#define GETP(sym, var) cudaGetSymbolAddress(&p, sym); float* var = (float*)p;
    GETP(g_x, x_)       GETP(g_t, t_)       GETP(g_value, val)
    GETP(g_vf, vf_)     GETP(g_u, u_)       GETP(g_v, v_)
    GETP(g_t1, t1_)     GETP(g_pe, pe_)     GETP(g_h, h_)
    GETP(g_agg, agg)    GETP(g_part, part)  GETP(g_partp, partp)
    GETP(g_Wuq, Wuq)    GETP(g_Wvk, Wvk)    GETP(g_bias1, bias1)
    GETP(g_scp, scp)    GETP(g_shp, shp)    GETP(g_sca, sca)
    GETP(g_sha, sha)    GETP(g_zero, zero)
#undef GETP
    cudaGetSymbolAddress(&p, g_idx);      int* idx = (int*)p;
    cudaGetSymbolAddress(&p, g_w2img);    unsigned int* w2img = (unsigned int*)p;
    cudaGetSymbolAddress(&p, g_wmidimg);  unsigned int* wmidimg = (unsigned int*)p;

    // --- precompute folded weights + weight images ---
    smallmm_kernel<<<(AH_ * C_ + 255) / 256, 256>>>(att_w1, wq, Wuq, AH_, DIM_, C_, 0);
    smallmm_kernel<<<(AH_ * C_ + 255) / 256, 256>>>(att_w1, wk, Wvk, AH_, DIM_, C_, 0);
    bias1_kernel<<<(AH_ + 255) / 256, 256>>>(att_w1, bq, bk, pos_b2, att_b1, bias1);
    prep_w2_kernel<<<(256 * 256) / 256, 256>>>(att_w2, w2img);
    prep_wmid_kernel<<<(1280 * 16 + 255) / 256, 256>>>(att_w1, pos_w2, wmidimg);

    // --- front end ---
    concat_kernel<<<(unsigned)(((size_t)B_ * 2 * C_ * N_ + 255) / 256), 256>>>(key, query, x_);
    knn_kernel<<<dim3(N_ / 256, B_), 256>>>(pos, idx);
    sgemm_kernel<1><<<dim3(N_ / 128, C_ / 128, B_), 256>>>(mlpv_w1, x_, mlpv_b1, t_, nullptr, C_, 2 * C_, N_);
    sgemm_kernel<0><<<dim3(N_ / 128, C_ / 128, B_), 256>>>(mlpv_w2, t_, mlpv_b2, val, nullptr, C_, C_, N_);
    sgemm_kernel<2><<<dim3(N_ / 128, C_ / 128, B_), 256>>>(mlpv_ws, x_, mlpv_bs, val, nullptr, C_, 2 * C_, N_);
    sgemm_kernel<0><<<dim3(N_ / 128, DIM_ / 128, B_), 256>>>(wv, val, bv, vf_, nullptr, DIM_, C_, N_);
    sgemm_kernel<0><<<dim3(N_ / 128, AH_ / 128, B_), 256>>>(Wuq, query, zero, u_, nullptr, AH_, C_, N_);
    sgemm_kernel<0><<<dim3(N_ / 128, AH_ / 128, B_), 256>>>(Wvk, key, zero, v_, nullptr, AH_, C_, N_);

    // --- pos_rel conv1 + pos BN ---
    posrel_kernel<<<(unsigned)(((size_t)B_ * PH_ * M_) / 256), 256>>>(pos, idx, pos_w1, pos_b1, t1_, partp);
    finalize_stats<<<PH_, 256>>>(partp, 512, 1, 512, pos_g1, pos_be1, scp, shp, (float)((size_t)B_ * M_));

    // --- fused mid on HMMA: h + pe (+ attn BN partials) ---
    cudaFuncSetAttribute(fused_mid_hmma, cudaFuncAttributeMaxDynamicSharedMemorySize, FM_SMEM);
    fused_mid_hmma<<<dim3(M_ / 256, B_), 256, FM_SMEM>>>(
        t1_, scp, shp, wmidimg, bias1, pos_b2, u_, v_, idx, h_, pe_, part);
    finalize_stats<<<AH_, 256>>>(part, B_ * 256, AH_, 1, att_g1, att_be1, sca, sha, (float)((size_t)B_ * M_));

    // --- big GEMM2: cp.async-pipelined HMMA + softmax + aggregation ---
    cudaFuncSetAttribute(attn2_hmma_kernel, cudaFuncAttributeMaxDynamicSharedMemorySize, SMEM_ATT2);
    attn2_hmma_kernel<<<dim3(M_ / 128, B_), 256, SMEM_ATT2>>>(
        (const uint4*)w2img, h_, sca, sha, pe_, vf_, agg);

    // --- final projection + residual ---
    sgemm_kernel<4><<<dim3(N_ / 128, C_ / 128, B_), 256>>>(we, agg, be, out, val, C_, DIM_, N_);
}

// round 9
// speedup vs baseline: 1.9754x; 1.0640x over previous
#include <cuda_runtime.h>
#include <cuda_bf16.h>
#include <math.h>
#include <stdint.h>

#define B_   2
#define C_   128
#define N_   4096
#define K_   16
#define DIM_ 256
#define PH_  64
#define AH_  1024
#define M_   (N_ * K_)          // 65536 columns per batch in (n,k) space

// ---------------- scratch ---------------------------------------------------
__device__ float g_x    [(size_t)B_ * 2 * C_ * N_];
__device__ float g_t    [(size_t)B_ * C_ * N_];
__device__ float g_value[(size_t)B_ * C_ * N_];
__device__ float g_vf   [(size_t)B_ * DIM_ * N_];
__device__ float g_u    [(size_t)B_ * AH_ * N_];
__device__ float g_v    [(size_t)B_ * AH_ * N_];
__device__ float g_vt   [(size_t)B_ * N_ * AH_];       // v transposed: [B][N][AH]
__device__ int   g_idx  [(size_t)B_ * N_ * K_];
__device__ float g_t1   [(size_t)B_ * PH_ * M_];
__device__ float g_pe   [(size_t)B_ * DIM_ * M_];
__device__ float g_h    [(size_t)B_ * AH_ * M_];       // h: [B][AH][M]  (c-major)
__device__ float g_agg  [(size_t)B_ * DIM_ * N_];
__device__ float g_part [(size_t)B_ * 512 * AH_ * 2];
__device__ float g_partp[(size_t)PH_ * 512 * 2];
__device__ float g_Wuq  [AH_ * C_];
__device__ float g_Wvk  [AH_ * C_];
__device__ float g_bias1[AH_];
__device__ float g_scp  [PH_];
__device__ float g_shp  [PH_];
__device__ float g_sca  [AH_];
__device__ float g_sha  [AH_];
__device__ float g_zero [AH_];
__device__ unsigned int g_w2img[16 * 65536 / 4];
__device__ unsigned int g_wmidimg[10 * 32768 / 4];

// ---------------- helpers ---------------------------------------------------
__device__ __forceinline__ uint32_t smem_u32(const void* p) {
    uint32_t a;
    asm("{ .reg .u64 t; cvta.to.shared.u64 t, %1; cvt.u32.u64 %0, t; }" : "=r"(a) : "l"(p));
    return a;
}
#define SWZ128(b) ((b) ^ (((b) >> 3) & 0x70))
__device__ __forceinline__ uint32_t pack_bf16(float a, float b) {
    __nv_bfloat16 ha = __float2bfloat16(a), hb = __float2bfloat16(b);
    return (uint32_t)__bfloat16_as_ushort(ha) |
           ((uint32_t)__bfloat16_as_ushort(hb) << 16);
}
__device__ __forceinline__ void ldm_x4(uint32_t* r, uint32_t addr) {
    asm volatile("ldmatrix.sync.aligned.m8n8.x4.shared.b16 {%0,%1,%2,%3}, [%4];"
        : "=r"(r[0]), "=r"(r[1]), "=r"(r[2]), "=r"(r[3]) : "r"(addr));
}
__device__ __forceinline__ void mma16816(float* d, const uint32_t* a, const uint32_t* b) {
    asm volatile(
        "mma.sync.aligned.m16n8k16.row.col.f32.bf16.bf16.f32 "
        "{%0,%1,%2,%3}, {%4,%5,%6,%7}, {%8,%9}, {%0,%1,%2,%3};"
        : "+f"(d[0]), "+f"(d[1]), "+f"(d[2]), "+f"(d[3])
        : "r"(a[0]), "r"(a[1]), "r"(a[2]), "r"(a[3]), "r"(b[0]), "r"(b[1]));
}
__device__ __forceinline__ void cp_async16(uint32_t dst, const void* src) {
    asm volatile("cp.async.cg.shared.global [%0], [%1], 16;" :: "r"(dst), "l"(src));
}
#define CP_COMMIT() asm volatile("cp.async.commit_group;" ::: "memory")
#define CP_WAIT0()  asm volatile("cp.async.wait_group 0;" ::: "memory")

// ---------------- concat ----------------------------------------------------
__global__ void concat_kernel(const float* __restrict__ key,
                              const float* __restrict__ query,
                              float* __restrict__ x) {
    size_t i = (size_t)blockIdx.x * blockDim.x + threadIdx.x;
    if (i >= (size_t)B_ * 2 * C_ * N_) return;
    int n = (int)(i % N_);
    int c = (int)((i / N_) % (2 * C_));
    int b = (int)(i / ((size_t)N_ * 2 * C_));
    float v;
    if (c < C_) v = key  [((size_t)b * C_ + c) * N_ + n];
    else        v = query[((size_t)b * C_ + (c - C_)) * N_ + n];
    x[i] = v;
}

// ---------------- KNN -------------------------------------------------------
__global__ void knn_kernel(const float* __restrict__ pos, int* __restrict__ idx) {
    const int b = blockIdx.y;
    const int n = blockIdx.x * blockDim.x + threadIdx.x;
    const float* p = pos + (size_t)b * 3 * N_;
    const float qx = p[n], qy = p[N_ + n], qz = p[2 * N_ + n];
    const float qs = qx * qx + qy * qy + qz * qz;
    float bd[K_]; int bi[K_];
#pragma unroll
    for (int j = 0; j < K_; j++) { bd[j] = 3.4e38f; bi[j] = 0; }
    __shared__ float sx[512], sy[512], sz[512], ss[512];
    for (int t0 = 0; t0 < N_; t0 += 512) {
        __syncthreads();
        for (int i = threadIdx.x; i < 512; i += blockDim.x) {
            float x = p[t0 + i], y = p[N_ + t0 + i], z = p[2 * N_ + t0 + i];
            sx[i] = x; sy[i] = y; sz[i] = z; ss[i] = x * x + y * y + z * z;
        }
        __syncthreads();
        for (int i = 0; i < 512; i++) {
            float d = qs + ss[i] - 2.0f * (qx * sx[i] + qy * sy[i] + qz * sz[i]);
            if (d < bd[K_ - 1]) {
                int j = K_ - 1;
                while (j > 0 && d < bd[j - 1]) { bd[j] = bd[j - 1]; bi[j] = bi[j - 1]; j--; }
                bd[j] = d; bi[j] = t0 + i;
            }
        }
    }
    int* op = idx + ((size_t)b * N_ + n) * K_;
#pragma unroll
    for (int j = 0; j < K_; j++) op[j] = bi[j];
}

// ---------------- precompute small products ---------------------------------
__global__ void smallmm_kernel(const float* __restrict__ A, const float* __restrict__ Bm,
                               float* __restrict__ Cc, int O, int Id, int J, int tr) {
    int t = blockIdx.x * 256 + threadIdx.x;
    if (t >= O * J) return;
    int o = t / J, j = t % J;
    float s = 0.0f;
    for (int d = 0; d < Id; d++) s += A[o * Id + d] * Bm[d * J + j];
    if (tr) Cc[j * O + o] = s; else Cc[o * J + j] = s;
}
__global__ void bias1_kernel(const float* __restrict__ w1, const float* __restrict__ bq,
                             const float* __restrict__ bk, const float* __restrict__ pb2,
                             const float* __restrict__ ab1, float* __restrict__ out) {
    int o = blockIdx.x * 256 + threadIdx.x;
    if (o >= AH_) return;
    float s = ab1[o];
    for (int d = 0; d < DIM_; d++) s += w1[o * DIM_ + d] * (bq[d] - bk[d] + pb2[d]);
    out[o] = s;
}
// v [B][AH][N] -> v_t [B][N][AH]
__global__ void transpose_bt(const float* __restrict__ src, float* __restrict__ dst) {
    __shared__ float tile[32][33];
    int b = blockIdx.z;
    int c0 = blockIdx.y * 32, n0 = blockIdx.x * 32;
    int tx = threadIdx.x, ty = threadIdx.y;
    const float* s = src + ((size_t)b * AH_ + c0) * N_ + n0;
#pragma unroll
    for (int i = 0; i < 32; i += 8) tile[ty + i][tx] = s[(size_t)(ty + i) * N_ + tx];
    __syncthreads();
    float* d = dst + ((size_t)b * N_ + n0) * AH_ + c0;
#pragma unroll
    for (int i = 0; i < 32; i += 8) d[(size_t)(ty + i) * AH_ + tx] = tile[tx][ty + i];
}

// ---------------- att_w2 -> pre-swizzled bf16 hi/lo image --------------------
__global__ void prep_w2_kernel(const float* __restrict__ w2, unsigned int* __restrict__ img) {
    int t = blockIdx.x * 256 + threadIdx.x;
    if (t >= 256 * 256) return;
    int c = t >> 8, k4 = t & 255;
    int k = k4 * 4;
    int q = k >> 6, kl = k & 63;
    const float* src = w2 + (size_t)c * AH_ + k;
    float f0 = src[0], f1 = src[1], f2 = src[2], f3 = src[3];
    float h0 = __bfloat162float(__float2bfloat16(f0));
    float h1 = __bfloat162float(__float2bfloat16(f1));
    float h2 = __bfloat162float(__float2bfloat16(f2));
    float h3 = __bfloat162float(__float2bfloat16(f3));
    uint32_t off = SWZ128((uint32_t)((c >> 3) * 1024 + (c & 7) * 128 + kl * 2));
    char* base = (char*)img + (size_t)q * 65536;
    *(uint2*)(base + off) = make_uint2(pack_bf16(f0, f1), pack_bf16(f2, f3));
    *(uint2*)(base + 32768 + off) =
        make_uint2(pack_bf16(f0 - h0, f1 - h1), pack_bf16(f2 - h2, f3 - h3));
}

// ---------------- Wmid -> pre-swizzled bf16 hi/lo image ----------------------
__global__ void prep_wmid_kernel(const float* __restrict__ att_w1,
                                 const float* __restrict__ pos_w2,
                                 unsigned int* __restrict__ img) {
    int t = blockIdx.x * 256 + threadIdx.x;
    if (t >= 1280 * 16) return;
    int c = t >> 4, k4 = t & 15;
    float f[4];
    if (c < AH_) {
#pragma unroll 4
        for (int kk = 0; kk < 4; kk++) {
            float s = 0.0f;
            for (int d = 0; d < DIM_; d++)
                s += att_w1[(size_t)c * DIM_ + d] * pos_w2[d * PH_ + k4 * 4 + kk];
            f[kk] = s;
        }
    } else {
#pragma unroll
        for (int kk = 0; kk < 4; kk++) f[kk] = pos_w2[(c - AH_) * PH_ + k4 * 4 + kk];
    }
    float r[4];
#pragma unroll
    for (int kk = 0; kk < 4; kk++)
        r[kk] = f[kk] - __bfloat162float(__float2bfloat16(f[kk]));
    int ct = c >> 7, cl = c & 127;
    uint32_t off = (uint32_t)((cl >> 3) * 1024 + (cl & 7) * 128 +
                              ((k4 * 8) ^ ((cl & 7) << 4)));
    char* base = (char*)img + (size_t)ct * 32768;
    *(uint2*)(base + off) = make_uint2(pack_bf16(f[0], f[1]), pack_bf16(f[2], f[3]));
    *(uint2*)(base + 16384 + off) = make_uint2(pack_bf16(r[0], r[1]), pack_bf16(r[2], r[3]));
}

// ---------------- generic fp32 SGEMM (small GEMMs) --------------------------
template <int FLAGS>
__global__ void sgemm_kernel(const float* __restrict__ W, const float* __restrict__ Xg,
                             const float* __restrict__ bias, float* __restrict__ outg,
                             const float* __restrict__ resg, int O, int I, int M) {
    const int b = blockIdx.z;
    const float* X = Xg + (size_t)b * I * M;
    float* out = outg + (size_t)b * O * M;
    const float* res = (FLAGS & 4) ? (resg + (size_t)b * O * M) : nullptr;
    __shared__ float Ws[8][132];
    __shared__ float Xs[8][128];
    const int tid = threadIdx.x;
    const int tx = tid & 15, ty = tid >> 4;
    const int o0 = blockIdx.y * 128, m0 = blockIdx.x * 128;
    const int wr = tid >> 1, wc = (tid & 1) * 4;
    const int xr = tid >> 5, xc = (tid & 31) * 4;
    float acc[8][8];
#pragma unroll
    for (int i = 0; i < 8; i++)
#pragma unroll
        for (int j = 0; j < 8; j++) acc[i][j] = 0.0f;
    for (int kt = 0; kt < I; kt += 8) {
        float4 wv = *(const float4*)&W[(size_t)(o0 + wr) * I + kt + wc];
        float4 xv = *(const float4*)&X[(size_t)(kt + xr) * M + m0 + xc];
        __syncthreads();
        Ws[wc + 0][wr] = wv.x; Ws[wc + 1][wr] = wv.y;
        Ws[wc + 2][wr] = wv.z; Ws[wc + 3][wr] = wv.w;
        *(float4*)&Xs[xr][xc] = xv;
        __syncthreads();
#pragma unroll
        for (int k = 0; k < 8; k++) {
            float a[8], bb[8];
            *(float4*)&a[0]  = *(const float4*)&Ws[k][ty * 8];
            *(float4*)&a[4]  = *(const float4*)&Ws[k][ty * 8 + 4];
            *(float4*)&bb[0] = *(const float4*)&Xs[k][tx * 8];
            *(float4*)&bb[4] = *(const float4*)&Xs[k][tx * 8 + 4];
#pragma unroll
            for (int i = 0; i < 8; i++)
#pragma unroll
                for (int j = 0; j < 8; j++) acc[i][j] += a[i] * bb[j];
        }
    }
#pragma unroll
    for (int i = 0; i < 8; i++) {
        const int o = o0 + ty * 8 + i;
        const float bv = bias[o];
        float* orow = out + (size_t)o * M + m0 + tx * 8;
        const float* rrow = (FLAGS & 4) ? (res + (size_t)o * M + m0 + tx * 8) : nullptr;
#pragma unroll
        for (int jj = 0; jj < 8; jj += 4) {
            float4 v;
            v.x = acc[i][jj + 0] + bv; v.y = acc[i][jj + 1] + bv;
            v.z = acc[i][jj + 2] + bv; v.w = acc[i][jj + 3] + bv;
            if (FLAGS & 1) { v.x = fmaxf(v.x, 0.f); v.y = fmaxf(v.y, 0.f);
                             v.z = fmaxf(v.z, 0.f); v.w = fmaxf(v.w, 0.f); }
            if (FLAGS & 2) { float4 old = *(float4*)&orow[jj];
                             v.x += old.x; v.y += old.y; v.z += old.z; v.w += old.w; }
            if (FLAGS & 4) { float4 r = *(const float4*)&rrow[jj];
                             v.x += r.x; v.y += r.y; v.z += r.z; v.w += r.w; }
            *(float4*)&orow[jj] = v;
        }
    }
}

// ---------------- pos_rel conv1 + BN partial stats ---------------------------
__global__ void posrel_kernel(const float* __restrict__ pos, const int* __restrict__ idx,
                              const float* __restrict__ w, const float* __restrict__ bias,
                              float* __restrict__ t1, float* __restrict__ part) {
    size_t i = (size_t)blockIdx.x * 256 + threadIdx.x;
    int k = (int)(i & 15);
    int n = (int)((i >> 4) & (N_ - 1));
    int c = (int)((i >> 16) & (PH_ - 1));
    int b = (int)(i >> 22);
    int m = idx[(((size_t)b * N_ + n) << 4) + k];
    const float* p = pos + (size_t)b * 3 * N_;
    float rx = p[n] - p[m];
    float ry = p[N_ + n] - p[N_ + m];
    float rz = p[2 * N_ + n] - p[2 * N_ + m];
    float val = w[c * 3] * rx + w[c * 3 + 1] * ry + w[c * 3 + 2] * rz + bias[c];
    t1[i] = val;
    __shared__ float ssum[256], ssq[256];
    ssum[threadIdx.x] = val; ssq[threadIdx.x] = val * val;
    __syncthreads();
    for (int st = 128; st > 0; st >>= 1) {
        if ((int)threadIdx.x < st) {
            ssum[threadIdx.x] += ssum[threadIdx.x + st];
            ssq[threadIdx.x]  += ssq[threadIdx.x + st];
        }
        __syncthreads();
    }
    if (threadIdx.x == 0) {
        int cb = (blockIdx.x >> 8) & (PH_ - 1);
        int bb = blockIdx.x >> 14;
        int sblk = blockIdx.x & 255;
        size_t o = ((size_t)cb * 512 + bb * 256 + sblk) * 2;
        part[o] = ssum[0]; part[o + 1] = ssq[0];
    }
}

// ---------------- BN finalize ------------------------------------------------
__global__ void finalize_stats(const float* __restrict__ part, int P, int ps, int cs,
                               const float* __restrict__ g, const float* __restrict__ be,
                               float* __restrict__ sc, float* __restrict__ sh, float cnt) {
    int c = blockIdx.x;
    double s = 0.0, q = 0.0;
    for (int p = threadIdx.x; p < P; p += blockDim.x) {
        size_t o = ((size_t)p * ps + (size_t)c * cs) * 2;
        s += (double)part[o]; q += (double)part[o + 1];
    }
    __shared__ double S[256], Q[256];
    S[threadIdx.x] = s; Q[threadIdx.x] = q;
    __syncthreads();
    for (int st = 128; st > 0; st >>= 1) {
        if ((int)threadIdx.x < st) {
            S[threadIdx.x] += S[threadIdx.x + st];
            Q[threadIdx.x] += Q[threadIdx.x + st];
        }
        __syncthreads();
    }
    if (threadIdx.x == 0) {
        double mean = S[0] / (double)cnt;
        double var  = Q[0] / (double)cnt - mean * mean;
        float scv = g[c] * (float)(1.0 / sqrt(var + 1e-5));
        sc[c] = scv;
        sh[c] = be[c] - (float)mean * scv;
    }
}

// ---------------- fused mid on HMMA, smem-staged gather ----------------------
#define FM_XHI   0
#define FM_XLO   16384
#define FM_W(s)  (32768 + (s) * 32768)
#define FM_VG    98304
#define FM_U     164352
#define FM_RED   168960
#define FM_SIDX  171008
#define FM_SMEM  171520

__global__ __launch_bounds__(256, 1) void fused_mid_hmma(
    const float* __restrict__ t1, const float* __restrict__ psc,
    const float* __restrict__ psh, const unsigned int* __restrict__ wimg,
    const float* __restrict__ bias1, const float* __restrict__ pos_b2,
    const float* __restrict__ u, const float* __restrict__ vt,
    const int* __restrict__ idx, float* __restrict__ h,
    float* __restrict__ pe, float* __restrict__ part) {
    extern __shared__ char smc[];
    const uint32_t sb = smem_u32(smc);
    const int tid = threadIdx.x, lane = tid & 31, wid = tid >> 5;
    const int b = blockIdx.y, m0 = blockIdx.x * 128;
    const int warp_cg = wid >> 1;    // 0..3 : 32-c groups
    const int warp_mg = wid & 1;     // 0..1 : 64-m groups

    int* sidx = (int*)(smc + FM_SIDX);
    float* vgs = (float*)(smc + FM_VG);
    float* us  = (float*)(smc + FM_U);
    float* redS = (float*)(smc + FM_RED);
    float* redQ = redS + 256;

    if (tid < 128) sidx[tid] = idx[((size_t)b * N_ + (m0 >> 4)) * K_ + tid];

    {
        const uint4* src = (const uint4*)wimg;
        uint32_t dst = sb + FM_W(0);
#pragma unroll
        for (int it = 0; it < 8; it++)
            cp_async16(dst + (it * 256 + tid) * 16, src + it * 256 + tid);
        CP_COMMIT();
    }
    {
        const float* tb = t1 + (size_t)b * PH_ * M_ + m0;
        char* xhi = smc + FM_XHI;
        char* xlo = smc + FM_XLO;
        int m = tid & 127, khalf = tid >> 7;
#pragma unroll
        for (int k2 = 0; k2 < 16; k2++) {
            int k = khalf * 32 + k2 * 2;
            float x0 = tb[(size_t)k * M_ + m];
            float x1 = tb[(size_t)(k + 1) * M_ + m];
            x0 = fmaxf(x0 * psc[k] + psh[k], 0.f);
            x1 = fmaxf(x1 * psc[k + 1] + psh[k + 1], 0.f);
            float l0 = x0 - __bfloat162float(__float2bfloat16(x0));
            float l1 = x1 - __bfloat162float(__float2bfloat16(x1));
            uint32_t off = (uint32_t)((m >> 3) * 1024 + (m & 7) * 128 +
                                      ((k * 2) ^ ((m & 7) << 4)));
            *(uint32_t*)(xhi + off) = pack_bf16(x0, x1);
            *(uint32_t*)(xlo + off) = pack_bf16(l0, l1);
        }
    }
    CP_WAIT0();
    __syncthreads();

    const int g = lane >> 3, lr = lane & 7;
    const int wrow = warp_cg * 32 + (g & 1) * 8 + lr;
    const int xrow = warp_mg * 64 + (g >> 1) * 8 + lr;
    const int wkb0 = (g >> 1) * 16;
    const int xkb0 = (g & 1) * 16;
    const uint32_t sX = sb + FM_XHI;
    const float* vtb = vt + (size_t)b * N_ * AH_;
    const int n0 = m0 >> 4;

    for (int ct = 0; ct < 10; ct++) {
        const int s = ct & 1;
        if (ct + 1 < 10) {
            const uint4* src = (const uint4*)wimg + (ct + 1) * 2048;
            uint32_t dst = sb + FM_W(s ^ 1);
#pragma unroll
            for (int it = 0; it < 8; it++)
                cp_async16(dst + (it * 256 + tid) * 16, src + it * 256 + tid);
            CP_COMMIT();
        }
        if (ct < 8) {
#pragma unroll
            for (int jj = 0; jj < 16; jj++) {
                int j = wid * 16 + jj;
                const float* row = vtb + (size_t)sidx[j] * AH_ + ct * 128;
#pragma unroll
                for (int cc = 0; cc < 4; cc++) {
                    int c = cc * 32 + lane;
                    vgs[c * 129 + j] = row[c];
                }
            }
#pragma unroll
            for (int it = 0; it < 4; it++) {
                int e = it * 256 + tid;
                int c = e >> 3, nn = e & 7;
                us[c * 9 + nn] = u[((size_t)b * AH_ + ct * 128 + c) * N_ + n0 + nn]
                               + bias1[ct * 128 + c];
            }
        }
        const uint32_t sW = sb + FM_W(s);
        float acc[2][8][4];
#pragma unroll
        for (int a = 0; a < 2; a++)
#pragma unroll
            for (int q = 0; q < 8; q++)
#pragma unroll
                for (int j = 0; j < 4; j++) acc[a][q][j] = 0.0f;
#pragma unroll
        for (int ks = 0; ks < 4; ks++) {
            uint32_t Whi[2][4], Wlo[2][4], Xhf[4][4], Xlf[4][4];
#pragma unroll
            for (int ct2 = 0; ct2 < 2; ct2++) {
                int cr = wrow + ct2 * 16;
                uint32_t ro = (uint32_t)((cr >> 3) * 1024 + (cr & 7) * 128);
                uint32_t kb = (uint32_t)((ks * 32 + wkb0) ^ ((cr & 7) << 4));
                ldm_x4(Whi[ct2], sW + ro + kb);
                ldm_x4(Wlo[ct2], sW + 16384 + ro + kb);
            }
#pragma unroll
            for (int np = 0; np < 4; np++) {
                int mr = xrow + np * 16;
                uint32_t ro = (uint32_t)((mr >> 3) * 1024 + (mr & 7) * 128);
                uint32_t kb = (uint32_t)((ks * 32 + xkb0) ^ ((mr & 7) << 4));
                ldm_x4(Xhf[np], sX + ro + kb);
                ldm_x4(Xlf[np], sX + 16384 + ro + kb);
            }
#pragma unroll
            for (int ct2 = 0; ct2 < 2; ct2++)
#pragma unroll
                for (int np = 0; np < 4; np++) {
                    mma16816(acc[ct2][np * 2],     Whi[ct2], &Xhf[np][0]);
                    mma16816(acc[ct2][np * 2],     Wlo[ct2], &Xhf[np][0]);
                    mma16816(acc[ct2][np * 2],     Whi[ct2], &Xlf[np][0]);
                    mma16816(acc[ct2][np * 2 + 1], Whi[ct2], &Xhf[np][2]);
                    mma16816(acc[ct2][np * 2 + 1], Wlo[ct2], &Xhf[np][2]);
                    mma16816(acc[ct2][np * 2 + 1], Whi[ct2], &Xlf[np][2]);
                }
        }
        if (ct < 8) {
            __syncthreads();
            float sS[2][2], sQ[2][2];
#pragma unroll
            for (int a = 0; a < 2; a++) { sS[a][0] = sS[a][1] = 0.f; sQ[a][0] = sQ[a][1] = 0.f; }
#pragma unroll
            for (int ct2 = 0; ct2 < 2; ct2++) {
#pragma unroll
                for (int j = 0; j < 4; j++) {
                    int rh = j >> 1;
                    int c_loc = warp_cg * 32 + ct2 * 16 + (lane >> 2) + rh * 8;
                    int c_g = ct * 128 + c_loc;
                    float* hrow = h + ((size_t)b * AH_ + c_g) * M_ + m0;
#pragma unroll
                    for (int q = 0; q < 8; q++) {
                        int m_loc = warp_mg * 64 + q * 8 + (lane & 3) * 2 + (j & 1);
                        float val = acc[ct2][q][j] + us[c_loc * 9 + (m_loc >> 4)]
                                  - vgs[c_loc * 129 + m_loc];
                        hrow[m_loc] = val;
                        sS[ct2][rh] += val; sQ[ct2][rh] += val * val;
                    }
                }
            }
#pragma unroll
            for (int ct2 = 0; ct2 < 2; ct2++)
#pragma unroll
                for (int rh = 0; rh < 2; rh++) {
                    float s1 = sS[ct2][rh], q1 = sQ[ct2][rh];
                    s1 += __shfl_xor_sync(0xffffffffu, s1, 1);
                    s1 += __shfl_xor_sync(0xffffffffu, s1, 2);
                    q1 += __shfl_xor_sync(0xffffffffu, q1, 1);
                    q1 += __shfl_xor_sync(0xffffffffu, q1, 2);
                    if ((lane & 3) == 0) {
                        int c_loc = warp_cg * 32 + ct2 * 16 + (lane >> 2) + rh * 8;
                        redS[c_loc * 2 + warp_mg] = s1;
                        redQ[c_loc * 2 + warp_mg] = q1;
                    }
                }
            __syncthreads();
            if (tid < 128) {
                float ss = redS[tid * 2] + redS[tid * 2 + 1];
                float qq = redQ[tid * 2] + redQ[tid * 2 + 1];
                size_t po = (((size_t)b * 512 + blockIdx.x) * AH_ + ct * 128 + tid) * 2;
                part[po] = ss; part[po + 1] = qq;
            }
        } else {
#pragma unroll
            for (int ct2 = 0; ct2 < 2; ct2++) {
#pragma unroll
                for (int j = 0; j < 4; j++) {
                    int c_pe = (ct - 8) * 128 + warp_cg * 32 + ct2 * 16 + (lane >> 2) + (j >> 1) * 8;
                    float bv = pos_b2[c_pe];
                    float* prow = pe + ((size_t)b * DIM_ + c_pe) * M_ + m0;
#pragma unroll
                    for (int q = 0; q < 8; q++) {
                        int m_loc = warp_mg * 64 + q * 8 + (lane & 3) * 2 + (j & 1);
                        prow[m_loc] = acc[ct2][q][j] + bv;
                    }
                }
            }
        }
        CP_WAIT0();
        __syncthreads();
    }
}

// ---------------- attn GEMM2 (HMMA, cp.async pipelined) ----------------------
#define A_OFF(s)  ((s) * 32768)
#define B_OFF(s)  (65536 + (s) * 65536)
#define STG_OFF   196608
#define SMEM_ATT2 229376

__device__ __forceinline__ void attn2_cpasync(uint32_t sb, int s, int cq,
                                              const float* hbase, const uint4* w2img,
                                              int tid) {
    const uint4* src = w2img + (size_t)cq * 4096;
    uint32_t bdst = sb + B_OFF(s);
#pragma unroll
    for (int it = 0; it < 16; it++) {
        int i = it * 256 + tid;
        cp_async16(bdst + i * 16, src + i);
    }
#pragma unroll
    for (int it = 0; it < 8; it++) {
        int ch = it * 256 + tid;
        int krow = ch >> 5;
        const float* srcr = hbase + (size_t)(cq * 64 + krow) * M_ + (ch & 31) * 4;
        cp_async16(sb + STG_OFF + krow * 512 + (ch & 31) * 16, srcr);
    }
}

__device__ __forceinline__ void attn2_convert(char* smc, int s, int cq,
                                              const float* __restrict__ scale,
                                              const float* __restrict__ shift,
                                              int wid, int lane) {
    const float* stg = (const float*)(smc + STG_OFF);
    char* dst = smc + A_OFF(s);
#pragma unroll
    for (int g2 = 0; g2 < 2; g2++) {
        int base_k = wid * 8 + g2 * 4;
        float4 v[4];
#pragma unroll
        for (int r = 0; r < 4; r++)
            v[r] = *(const float4*)&stg[(base_k + r) * 128 + lane * 4];
        float X[4][4], L[4][4];
#pragma unroll
        for (int r = 0; r < 4; r++) {
            float sc = scale[cq * 64 + base_k + r];
            float sh = shift[cq * 64 + base_k + r];
            float xv[4] = {v[r].x, v[r].y, v[r].z, v[r].w};
#pragma unroll
            for (int mm = 0; mm < 4; mm++) {
                float x = fmaxf(xv[mm] * sc + sh, 0.f);
                X[mm][r] = x;
                L[mm][r] = x - __bfloat162float(__float2bfloat16(x));
            }
        }
#pragma unroll
        for (int mm = 0; mm < 4; mm++) {
            int m = lane * 4 + mm;
            uint32_t off = (uint32_t)((m >> 3) * 1024 + (m & 7) * 128 +
                                      ((base_k * 2) ^ ((m & 7) << 4)));
            *(uint2*)(dst + off) = make_uint2(pack_bf16(X[mm][0], X[mm][1]),
                                              pack_bf16(X[mm][2], X[mm][3]));
            *(uint2*)(dst + 16384 + off) = make_uint2(pack_bf16(L[mm][0], L[mm][1]),
                                                      pack_bf16(L[mm][2], L[mm][3]));
        }
    }
}

__global__ __launch_bounds__(256, 1) void attn2_hmma_kernel(
    const uint4* __restrict__ w2img, const float* __restrict__ h,
    const float* __restrict__ scale, const float* __restrict__ shift,
    const float* __restrict__ pe, const float* __restrict__ vf,
    float* __restrict__ agg) {
    extern __shared__ char smc[];
    const uint32_t sb = smem_u32(smc);
    const int tid = threadIdx.x, lane = tid & 31, wid = tid >> 5;
    const int b = blockIdx.y, m0 = blockIdx.x * 128;
    const int warp_m = wid >> 2, warp_c = wid & 3;

    const float* hbase = h + (size_t)b * AH_ * M_ + m0;

    float acc[4][8][4];
#pragma unroll
    for (int mt = 0; mt < 4; mt++)
#pragma unroll
        for (int nt = 0; nt < 8; nt++)
#pragma unroll
            for (int j = 0; j < 4; j++) acc[mt][nt][j] = 0.0f;

    const int g = lane >> 3, lr = lane & 7;
    const int amr  = warp_m * 64 + (g & 1) * 8 + lr;
    const int bcr  = warp_c * 64 + (g >> 1) * 8 + lr;
    const int akb0 = (g >> 1) * 16;
    const int bkb0 = (g & 1) * 16;

    attn2_cpasync(sb, 0, 0, hbase, w2img, tid);
    CP_COMMIT();
    CP_WAIT0();
    __syncthreads();
    attn2_convert(smc, 0, 0, scale, shift, wid, lane);
    __syncthreads();

    for (int cq = 0; cq < 16; cq++) {
        const int s = cq & 1;
        if (cq + 1 < 16) {
            attn2_cpasync(sb, s ^ 1, cq + 1, hbase, w2img, tid);
            CP_COMMIT();
        }
        const uint32_t sA = sb + A_OFF(s);
        const uint32_t sB = sb + B_OFF(s);
#pragma unroll
        for (int ks = 0; ks < 4; ks++) {
            uint32_t Ahi[4][4], Alo[4][4], Bhi[4][4], Blo[4][4];
#pragma unroll
            for (int mt = 0; mt < 4; mt++) {
                int m = amr + mt * 16;
                uint32_t ro = (uint32_t)((m >> 3) * 1024 + (m & 7) * 128);
                uint32_t kb = (uint32_t)((ks * 32 + akb0) ^ ((m & 7) << 4));
                ldm_x4(Ahi[mt], sA + ro + kb);
                ldm_x4(Alo[mt], sA + 16384 + ro + kb);
            }
#pragma unroll
            for (int np = 0; np < 4; np++) {
                int c = bcr + np * 16;
                uint32_t ro = (uint32_t)((c >> 3) * 1024 + (c & 7) * 128);
                uint32_t kb = (uint32_t)((ks * 32 + bkb0) ^ ((c & 7) << 4));
                ldm_x4(Bhi[np], sB + ro + kb);
                ldm_x4(Blo[np], sB + 32768 + ro + kb);
            }
#pragma unroll
            for (int mt = 0; mt < 4; mt++)
#pragma unroll
                for (int np = 0; np < 4; np++) {
                    mma16816(acc[mt][np * 2],     Ahi[mt], &Bhi[np][0]);
                    mma16816(acc[mt][np * 2],     Alo[mt], &Bhi[np][0]);
                    mma16816(acc[mt][np * 2],     Ahi[mt], &Blo[np][0]);
                    mma16816(acc[mt][np * 2 + 1], Ahi[mt], &Bhi[np][2]);
                    mma16816(acc[mt][np * 2 + 1], Alo[mt], &Bhi[np][2]);
                    mma16816(acc[mt][np * 2 + 1], Ahi[mt], &Blo[np][2]);
                }
        }
        if (cq + 1 < 16) {
            CP_WAIT0();
            __syncthreads();
            attn2_convert(smc, s ^ 1, cq + 1, scale, shift, wid, lane);
            __syncthreads();
        }
    }
    __syncthreads();

    float* pes = (float*)smc;
    for (int i = tid; i < 256 * 32; i += 256) {
        int row = i >> 5, q = i & 31;
        float4 v = *(const float4*)(pe + ((size_t)(b * DIM_ + row)) * M_ + m0 + q * 4);
        *(float4*)&pes[row * 132 + q * 4] = v;
    }
    __syncthreads();

#pragma unroll
    for (int mt = 0; mt < 4; mt++) {
        const int mbase = warp_m * 64 + mt * 16;
        const int n = (m0 + mbase) >> 4;
        const int r = lane >> 2;
#pragma unroll
        for (int nt = 0; nt < 8; nt++) {
#pragma unroll
            for (int j = 0; j < 2; j++) {
                int c = warp_c * 64 + nt * 8 + (lane & 3) * 2 + j;
                float v0 = acc[mt][nt][j], v1 = acc[mt][nt][2 + j];
                float mx = fmaxf(v0, v1);
                mx = fmaxf(mx, __shfl_xor_sync(0xffffffffu, mx, 4));
                mx = fmaxf(mx, __shfl_xor_sync(0xffffffffu, mx, 8));
                mx = fmaxf(mx, __shfl_xor_sync(0xffffffffu, mx, 16));
                float e0 = __expf(v0 - mx), e1 = __expf(v1 - mx);
                float se = e0 + e1;
                se += __shfl_xor_sync(0xffffffffu, se, 4);
                se += __shfl_xor_sync(0xffffffffu, se, 8);
                se += __shfl_xor_sync(0xffffffffu, se, 16);
                float p0 = pes[c * 132 + mbase + r];
                float p1 = pes[c * 132 + mbase + r + 8];
                float t = e0 * p0 + e1 * p1;
                t += __shfl_xor_sync(0xffffffffu, t, 4);
                t += __shfl_xor_sync(0xffffffffu, t, 8);
                t += __shfl_xor_sync(0xffffffffu, t, 16);
                if (r == 0) {
                    size_t o = ((size_t)(b * DIM_ + c)) * N_ + n;
                    agg[o] = vf[o] + t / se;
                }
            }
        }
    }
}

// ---------------- launch ----------------------------------------------------
extern "C" void kernel_launch(void* const* d_in, const int* in_sizes, int n_in,
                              void* d_out, int out_size) {
    const float* pos     = (const float*)d_in[0];
    const float* key     = (const float*)d_in[1];
    const float* query   = (const float*)d_in[2];
    const float* mlpv_w1 = (const float*)d_in[3];
    const float* mlpv_b1 = (const float*)d_in[4];
    const float* mlpv_w2 = (const float*)d_in[5];
    const float* mlpv_b2 = (const float*)d_in[6];
    const float* mlpv_ws = (const float*)d_in[7];
    const float* mlpv_bs = (const float*)d_in[8];
    const float* wk      = (const float*)d_in[9];
    const float* bk      = (const float*)d_in[10];
    const float* wq      = (const float*)d_in[11];
    const float* bq      = (const float*)d_in[12];
    const float* wv      = (const float*)d_in[13];
    const float* bv      = (const float*)d_in[14];
    const float* pos_w1  = (const float*)d_in[15];
    const float* pos_b1  = (const float*)d_in[16];
    const float* pos_g1  = (const float*)d_in[17];
    const float* pos_be1 = (const float*)d_in[18];
    const float* pos_w2  = (const float*)d_in[19];
    const float* pos_b2  = (const float*)d_in[20];
    const float* att_w1  = (const float*)d_in[21];
    const float* att_b1  = (const float*)d_in[22];
    const float* att_g1  = (const float*)d_in[23];
    const float* att_be1 = (const float*)d_in[24];
    const float* att_w2  = (const float*)d_in[25];
    const float* we      = (const float*)d_in[27];
    const float* be      = (const float*)d_in[28];
    float* out = (float*)d_out;

    void* p;
#define GETP(sym, var) cudaGetSymbolAddress(&p, sym); float* var = (float*)p;
    GETP(g_x, x_)       GETP(g_t, t_)       GETP(g_value, val)
    GETP(g_vf, vf_)     GETP(g_u, u_)       GETP(g_v, v_)
    GETP(g_vt, vt_)
    GETP(g_t1, t1_)     GETP(g_pe, pe_)     GETP(g_h, h_)
    GETP(g_agg, agg)    GETP(g_part, part)  GETP(g_partp, partp)
    GETP(g_Wuq, Wuq)    GETP(g_Wvk, Wvk)    GETP(g_bias1, bias1)
    GETP(g_scp, scp)    GETP(g_shp, shp)    GETP(g_sca, sca)
    GETP(g_sha, sha)    GETP(g_zero, zero)
#undef GETP
    cudaGetSymbolAddress(&p, g_idx);      int* idx = (int*)p;
    cudaGetSymbolAddress(&p, g_w2img);    unsigned int* w2img = (unsigned int*)p;
    cudaGetSymbolAddress(&p, g_wmidimg);  unsigned int* wmidimg = (unsigned int*)p;

    smallmm_kernel<<<(AH_ * C_ + 255) / 256, 256>>>(att_w1, wq, Wuq, AH_, DIM_, C_, 0);
    smallmm_kernel<<<(AH_ * C_ + 255) / 256, 256>>>(att_w1, wk, Wvk, AH_, DIM_, C_, 0);
    bias1_kernel<<<(AH_ + 255) / 256, 256>>>(att_w1, bq, bk, pos_b2, att_b1, bias1);
    prep_w2_kernel<<<(256 * 256) / 256, 256>>>(att_w2, w2img);
    prep_wmid_kernel<<<(1280 * 16 + 255) / 256, 256>>>(att_w1, pos_w2, wmidimg);

    concat_kernel<<<(unsigned)(((size_t)B_ * 2 * C_ * N_ + 255) / 256), 256>>>(key, query, x_);
    knn_kernel<<<dim3(N_ / 256, B_), 256>>>(pos, idx);
    sgemm_kernel<1><<<dim3(N_ / 128, C_ / 128, B_), 256>>>(mlpv_w1, x_, mlpv_b1, t_, nullptr, C_, 2 * C_, N_);
    sgemm_kernel<0><<<dim3(N_ / 128, C_ / 128, B_), 256>>>(mlpv_w2, t_, mlpv_b2, val, nullptr, C_, C_, N_);
    sgemm_kernel<2><<<dim3(N_ / 128, C_ / 128, B_), 256>>>(mlpv_ws, x_, mlpv_bs, val, nullptr, C_, 2 * C_, N_);
    sgemm_kernel<0><<<dim3(N_ / 128, DIM_ / 128, B_), 256>>>(wv, val, bv, vf_, nullptr, DIM_, C_, N_);
    sgemm_kernel<0><<<dim3(N_ / 128, AH_ / 128, B_), 256>>>(Wuq, query, zero, u_, nullptr, AH_, C_, N_);
    sgemm_kernel<0><<<dim3(N_ / 128, AH_ / 128, B_), 256>>>(Wvk, key, zero, v_, nullptr, AH_, C_, N_);
    transpose_bt<<<dim3(N_ / 32, AH_ / 32, B_), dim3(32, 8)>>>(v_, vt_);

    posrel_kernel<<<(unsigned)(((size_t)B_ * PH_ * M_) / 256), 256>>>(pos, idx, pos_w1, pos_b1, t1_, partp);
    finalize_stats<<<PH_, 256>>>(partp, 512, 1, 512, pos_g1, pos_be1, scp, shp, (float)((size_t)B_ * M_));

    cudaFuncSetAttribute(fused_mid_hmma, cudaFuncAttributeMaxDynamicSharedMemorySize, FM_SMEM);
    fused_mid_hmma<<<dim3(M_ / 128, B_), 256, FM_SMEM>>>(
        t1_, scp, shp, wmidimg, bias1, pos_b2, u_, vt_, idx, h_, pe_, part);
    finalize_stats<<<AH_, 256>>>(part, B_ * 512, AH_, 1, att_g1, att_be1, sca, sha, (float)((size_t)B_ * M_));

    cudaFuncSetAttribute(attn2_hmma_kernel, cudaFuncAttributeMaxDynamicSharedMemorySize, SMEM_ATT2);
    attn2_hmma_kernel<<<dim3(M_ / 128, B_), 256, SMEM_ATT2>>>(
        (const uint4*)w2img, h_, sca, sha, pe_, vf_, agg);

    sgemm_kernel<4><<<dim3(N_ / 128, C_ / 128, B_), 256>>>(we, agg, be, out, val, C_, DIM_, N_);
}